// round 8
// baseline (speedup 1.0000x reference)
#include <cuda_runtime.h>
#include <cstdint>

// Problem constants (shapes fixed by the dataset)
#define NNODES 100000
#define NEDGES 1600000
#define NGRAPH 128
#define HDIM   128
#define FDIM   64
#define LN_EPS 1e-5f

#define SCANW   1024
#define NSCANBLK ((NNODES + SCANW) / SCANW + 1)
#define NPARTIAL (NSCANBLK * SCANW)

// ---------------- scratch (device globals; no allocations allowed) ----------
__device__ int   g_ibuf[NPARTIAL + NNODES];         // deg + fill cursors (one memset)
__device__ int   g_partial[NPARTIAL];               // per-block exclusive scan
__device__ int   g_blocksum[256];
__device__ int   g_blockpref[128];                  // written by k_fill block 0
__device__ int2  g_csr[NEDGES];                     // (src, bits(dinv[src]))
__device__ float g_bufa[(size_t)NNODES * HDIM];
__device__ float g_bufb[(size_t)NNODES * HDIM];
__device__ float g_pool[NGRAPH * HDIM + NGRAPH];    // gsum + gcnt (one memset)

// ---------------- degree count ----------------
__global__ void k_count_deg(const int* __restrict__ dst, int* __restrict__ deg, int e) {
    int i = blockIdx.x * blockDim.x + threadIdx.x;
    if (i < e) atomicAdd(&deg[dst[i]], 1);
}

// ---------------- per-block exclusive scan (level 1) ----------------
__global__ void k_scan_block(const int* __restrict__ deg, int* __restrict__ partial,
                             int* __restrict__ blocksum, int n) {
    __shared__ int sm[2][SCANW];
    int t = threadIdx.x;
    int g = blockIdx.x * SCANW + t;
    int v = (g < n) ? deg[g] : 0;
    sm[0][t] = v;
    __syncthreads();
    int cur = 0;
#pragma unroll
    for (int off = 1; off < SCANW; off <<= 1) {
        int x = sm[cur][t];
        if (t >= off) x += sm[cur][t - off];
        sm[cur ^ 1][t] = x;
        __syncthreads();
        cur ^= 1;
    }
    int inc = sm[cur][t];
    partial[g] = inc - v;
    if (t == SCANW - 1) blocksum[blockIdx.x] = inc;
}

// Level-2 prefix computed in-block (<=128 scan blocks). All threads call it.
__device__ __forceinline__ void block_prefix(const int* __restrict__ bsum, int B,
                                             int* __restrict__ sbp) {
    __shared__ int tmp[128];
    int t = threadIdx.x;
    int v = 0;
    if (t < 128) { v = (t < B) ? bsum[t] : 0; tmp[t] = v; }
    __syncthreads();
#pragma unroll
    for (int off = 1; off < 128; off <<= 1) {
        int x = 0;
        if (t < 128) { x = tmp[t]; if (t >= off) x += tmp[t - off]; }
        __syncthreads();
        if (t < 128) tmp[t] = x;
        __syncthreads();
    }
    if (t < 128) sbp[t] = tmp[t] - v;   // exclusive
    __syncthreads();
}

// ---------------- CSR fill (also publishes the level-2 prefix) --------------
__global__ void __launch_bounds__(256)
k_fill(const int* __restrict__ src, const int* __restrict__ dst,
       const int* __restrict__ deg, const int* __restrict__ partial,
       const int* __restrict__ bsum, int B, int* __restrict__ bpref_g,
       int* __restrict__ cnt2, int2* __restrict__ csr, int e) {
    __shared__ int sbp[128];
    block_prefix(bsum, B, sbp);
    if (blockIdx.x == 0 && threadIdx.x < 128) bpref_g[threadIdx.x] = sbp[threadIdx.x];
    int i = blockIdx.x * blockDim.x + threadIdx.x;
    if (i >= e) return;
    int s = src[i];
    int d = dst[i];
    float dvs = rsqrtf((float)(deg[s] + 1));
    int pos = partial[d] + sbp[d >> 10] + atomicAdd(&cnt2[d], 1);
    csr[pos] = make_int2(s, __float_as_int(dvs));
}

// ---------------- FUSED gather-aggregate + GEMM + bias + LN (+ReLU) ---------
// Phase 1: 8 warps aggregate 4 nodes each (warp-per-node gather over CSR),
//          writing the aggregated tile TRANSPOSED into sXT[k][row].
// Phase 2: X @ W; per k-iter each thread does 1 broadcast LDS.128 (4 rows of x)
//          + 1 LDS.128 (W) + 16 FFMA -> minimal L1 pressure alongside gathers.
// out[v,:] = LN( [dinv_v*(sum dinv_s*feat_s + dinv_v*feat_v)] @ W + b )
template <int K, bool RELU>
__global__ void __launch_bounds__(256)
k_agg_gemm_ln(const float* __restrict__ feat, const int* __restrict__ deg,
              const int2* __restrict__ csr, const int* __restrict__ partial,
              const int* __restrict__ bpref,
              const float* __restrict__ W, const float* __restrict__ bias,
              const float* __restrict__ gamma, const float* __restrict__ beta,
              float* __restrict__ out, int n) {
    __shared__ __align__(16) float sW[32][128];
    __shared__ __align__(16) float sXT[K][36];   // [k][row], 144B row stride (16B mult)

    const int tid  = threadIdx.x;
    const int warp = tid >> 5;
    const int lane = tid & 31;
    const int row0 = blockIdx.x * 32;   // n divisible by 32

    // ---------------- phase 1: aggregation into sXT (transposed) ------------
#pragma unroll
    for (int i = 0; i < 4; i++) {
        const int rl = warp * 4 + i;            // local row
        const int w = row0 + rl;
        const int r0 = partial[w] + bpref[w >> 10];
        const int r1 = partial[w + 1] + bpref[(w + 1) >> 10];
        const float dv = rsqrtf((float)(deg[w] + 1));

        if (K == 64) {
            float2 acc = reinterpret_cast<const float2*>(feat)[(size_t)w * 32 + lane];
            acc.x *= dv; acc.y *= dv;
            int r = r0;
            for (; r + 4 <= r1; r += 4) {
                int2 e0 = csr[r], e1 = csr[r + 1], e2 = csr[r + 2], e3 = csr[r + 3];
                float2 v0 = reinterpret_cast<const float2*>(feat)[(size_t)e0.x * 32 + lane];
                float2 v1 = reinterpret_cast<const float2*>(feat)[(size_t)e1.x * 32 + lane];
                float2 v2 = reinterpret_cast<const float2*>(feat)[(size_t)e2.x * 32 + lane];
                float2 v3 = reinterpret_cast<const float2*>(feat)[(size_t)e3.x * 32 + lane];
                float w0 = __int_as_float(e0.y), w1 = __int_as_float(e1.y);
                float w2 = __int_as_float(e2.y), w3 = __int_as_float(e3.y);
                acc.x = fmaf(w0, v0.x, acc.x); acc.y = fmaf(w0, v0.y, acc.y);
                acc.x = fmaf(w1, v1.x, acc.x); acc.y = fmaf(w1, v1.y, acc.y);
                acc.x = fmaf(w2, v2.x, acc.x); acc.y = fmaf(w2, v2.y, acc.y);
                acc.x = fmaf(w3, v3.x, acc.x); acc.y = fmaf(w3, v3.y, acc.y);
            }
            for (; r < r1; r++) {
                int2 e0 = csr[r];
                float2 v0 = reinterpret_cast<const float2*>(feat)[(size_t)e0.x * 32 + lane];
                float w0 = __int_as_float(e0.y);
                acc.x = fmaf(w0, v0.x, acc.x); acc.y = fmaf(w0, v0.y, acc.y);
            }
            acc.x *= dv; acc.y *= dv;
            sXT[lane * 2 + 0][rl] = acc.x;
            sXT[lane * 2 + 1][rl] = acc.y;
        } else {
            float4 acc = reinterpret_cast<const float4*>(feat)[(size_t)w * 32 + lane];
            acc.x *= dv; acc.y *= dv; acc.z *= dv; acc.w *= dv;
            int r = r0;
            for (; r + 4 <= r1; r += 4) {
                int2 e0 = csr[r], e1 = csr[r + 1], e2 = csr[r + 2], e3 = csr[r + 3];
                float4 v0 = reinterpret_cast<const float4*>(feat)[(size_t)e0.x * 32 + lane];
                float4 v1 = reinterpret_cast<const float4*>(feat)[(size_t)e1.x * 32 + lane];
                float4 v2 = reinterpret_cast<const float4*>(feat)[(size_t)e2.x * 32 + lane];
                float4 v3 = reinterpret_cast<const float4*>(feat)[(size_t)e3.x * 32 + lane];
                float w0 = __int_as_float(e0.y), w1 = __int_as_float(e1.y);
                float w2 = __int_as_float(e2.y), w3 = __int_as_float(e3.y);
                acc.x = fmaf(w0, v0.x, acc.x); acc.y = fmaf(w0, v0.y, acc.y);
                acc.z = fmaf(w0, v0.z, acc.z); acc.w = fmaf(w0, v0.w, acc.w);
                acc.x = fmaf(w1, v1.x, acc.x); acc.y = fmaf(w1, v1.y, acc.y);
                acc.z = fmaf(w1, v1.z, acc.z); acc.w = fmaf(w1, v1.w, acc.w);
                acc.x = fmaf(w2, v2.x, acc.x); acc.y = fmaf(w2, v2.y, acc.y);
                acc.z = fmaf(w2, v2.z, acc.z); acc.w = fmaf(w2, v2.w, acc.w);
                acc.x = fmaf(w3, v3.x, acc.x); acc.y = fmaf(w3, v3.y, acc.y);
                acc.z = fmaf(w3, v3.z, acc.z); acc.w = fmaf(w3, v3.w, acc.w);
            }
            for (; r < r1; r++) {
                int2 e0 = csr[r];
                float4 v0 = reinterpret_cast<const float4*>(feat)[(size_t)e0.x * 32 + lane];
                float w0 = __int_as_float(e0.y);
                acc.x = fmaf(w0, v0.x, acc.x); acc.y = fmaf(w0, v0.y, acc.y);
                acc.z = fmaf(w0, v0.z, acc.z); acc.w = fmaf(w0, v0.w, acc.w);
            }
            acc.x *= dv; acc.y *= dv; acc.z *= dv; acc.w *= dv;
            sXT[lane * 4 + 0][rl] = acc.x;
            sXT[lane * 4 + 1][rl] = acc.y;
            sXT[lane * 4 + 2][rl] = acc.z;
            sXT[lane * 4 + 3][rl] = acc.w;
        }
    }
    __syncthreads();

    // ---------------- phase 2: GEMM + LN ----------------
    float acc[4][4];
#pragma unroll
    for (int r = 0; r < 4; r++)
#pragma unroll
        for (int c = 0; c < 4; c++) acc[r][c] = 0.0f;

#pragma unroll
    for (int kt = 0; kt < K; kt += 32) {
        // stage W chunk: 32x128 floats = 1024 float4, 256 threads -> 4 each
#pragma unroll
        for (int i = tid; i < 1024; i += 256) {
            int kk = i >> 5;
            int c4 = i & 31;
            reinterpret_cast<float4*>(sW[kk])[c4] =
                reinterpret_cast<const float4*>(W + (size_t)(kt + kk) * 128)[c4];
        }
        __syncthreads();

#pragma unroll
        for (int kk = 0; kk < 32; kk++) {
            float4 wv = reinterpret_cast<float4*>(sW[kk])[lane];
            float4 xv = *reinterpret_cast<float4*>(&sXT[kt + kk][warp * 4]);  // broadcast
            acc[0][0] = fmaf(xv.x, wv.x, acc[0][0]);
            acc[0][1] = fmaf(xv.x, wv.y, acc[0][1]);
            acc[0][2] = fmaf(xv.x, wv.z, acc[0][2]);
            acc[0][3] = fmaf(xv.x, wv.w, acc[0][3]);
            acc[1][0] = fmaf(xv.y, wv.x, acc[1][0]);
            acc[1][1] = fmaf(xv.y, wv.y, acc[1][1]);
            acc[1][2] = fmaf(xv.y, wv.z, acc[1][2]);
            acc[1][3] = fmaf(xv.y, wv.w, acc[1][3]);
            acc[2][0] = fmaf(xv.z, wv.x, acc[2][0]);
            acc[2][1] = fmaf(xv.z, wv.y, acc[2][1]);
            acc[2][2] = fmaf(xv.z, wv.z, acc[2][2]);
            acc[2][3] = fmaf(xv.z, wv.w, acc[2][3]);
            acc[3][0] = fmaf(xv.w, wv.x, acc[3][0]);
            acc[3][1] = fmaf(xv.w, wv.y, acc[3][1]);
            acc[3][2] = fmaf(xv.w, wv.z, acc[3][2]);
            acc[3][3] = fmaf(xv.w, wv.w, acc[3][3]);
        }
        __syncthreads();
    }

    const float4 bv = reinterpret_cast<const float4*>(bias)[lane];
    const float4 gv = reinterpret_cast<const float4*>(gamma)[lane];
    const float4 be = reinterpret_cast<const float4*>(beta)[lane];

#pragma unroll
    for (int r = 0; r < 4; r++) {
        float hx = acc[r][0] + bv.x;
        float hy = acc[r][1] + bv.y;
        float hz = acc[r][2] + bv.z;
        float hw = acc[r][3] + bv.w;
        float s = hx + hy + hz + hw;
#pragma unroll
        for (int o = 16; o > 0; o >>= 1) s += __shfl_xor_sync(0xffffffffu, s, o);
        float mu = s * (1.0f / 128.0f);
        float dx = hx - mu, dy = hy - mu, dz = hz - mu, dw = hw - mu;
        float q = dx * dx + dy * dy + dz * dz + dw * dw;
#pragma unroll
        for (int o = 16; o > 0; o >>= 1) q += __shfl_xor_sync(0xffffffffu, q, o);
        float rstd = rsqrtf(q * (1.0f / 128.0f) + LN_EPS);

        float4 o4;
        o4.x = dx * rstd * gv.x + be.x;
        o4.y = dy * rstd * gv.y + be.y;
        o4.z = dz * rstd * gv.z + be.z;
        o4.w = dw * rstd * gv.w + be.w;
        if (RELU) {
            o4.x = fmaxf(o4.x, 0.0f);
            o4.y = fmaxf(o4.y, 0.0f);
            o4.z = fmaxf(o4.z, 0.0f);
            o4.w = fmaxf(o4.w, 0.0f);
        }
        int row = row0 + warp * 4 + r;
        reinterpret_cast<float4*>(out + (size_t)row * 128)[lane] = o4;
    }
}

// ---------------- pooling (batch is sorted; count fused) ----------------
__global__ void k_pool_sum(const float* __restrict__ h, const int* __restrict__ batch,
                           float* __restrict__ gsum, int* __restrict__ gcnt, int n, int rpb) {
    int c  = threadIdx.x;
    int r0 = blockIdx.x * rpb;
    int r1 = min(r0 + rpb, n);
    if (r0 >= r1) return;
    float acc = 0.0f;
    int cnt = 0;
    int cur = batch[r0];
    for (int r = r0; r < r1; r++) {
        int g = batch[r];
        if (g != cur) {
            atomicAdd(&gsum[cur * HDIM + c], acc);
            if (c == 0) atomicAdd(&gcnt[cur], cnt);
            acc = 0.0f; cnt = 0; cur = g;
        }
        acc += h[(size_t)r * HDIM + c];
        cnt++;
    }
    atomicAdd(&gsum[cur * HDIM + c], acc);
    if (c == 0) atomicAdd(&gcnt[cur], cnt);
}

__global__ void k_finalize(const float* __restrict__ gsum, const int* __restrict__ gcnt,
                           float* __restrict__ out) {
    int i = blockIdx.x * blockDim.x + threadIdx.x;
    if (i >= NGRAPH * HDIM) return;
    float cnt = fmaxf((float)gcnt[i >> 7], 1.0f);
    out[i] = gsum[i] / cnt;
}

// ---------------- launch ----------------
extern "C" void kernel_launch(void* const* d_in, const int* in_sizes, int n_in,
                              void* d_out, int out_size) {
    const float* x     = (const float*)d_in[0];
    const int*   eidx  = (const int*)d_in[1];
    const int*   batch = (const int*)d_in[2];
    const float* W1 = (const float*)d_in[3];
    const float* b1 = (const float*)d_in[4];
    const float* g1 = (const float*)d_in[5];
    const float* be1 = (const float*)d_in[6];
    const float* W2 = (const float*)d_in[7];
    const float* b2 = (const float*)d_in[8];
    const float* g2 = (const float*)d_in[9];
    const float* be2 = (const float*)d_in[10];

    const int n = in_sizes[0] / FDIM;   // 100000
    const int e = in_sizes[1] / 2;      // 1600000
    const int* src = eidx;
    const int* dst = eidx + e;

    int*   ibuf;  cudaGetSymbolAddress((void**)&ibuf,  g_ibuf);
    int*   part;  cudaGetSymbolAddress((void**)&part,  g_partial);
    int*   bsum;  cudaGetSymbolAddress((void**)&bsum,  g_blocksum);
    int*   bpref; cudaGetSymbolAddress((void**)&bpref, g_blockpref);
    int2*  csr;   cudaGetSymbolAddress((void**)&csr,   g_csr);
    float* bufa;  cudaGetSymbolAddress((void**)&bufa,  g_bufa);
    float* bufb;  cudaGetSymbolAddress((void**)&bufb,  g_bufb);
    float* pool;  cudaGetSymbolAddress((void**)&pool,  g_pool);

    int* deg  = ibuf;
    int* cnt2 = ibuf + NPARTIAL;
    float* gsum = pool;
    int*   gcnt = (int*)(pool + NGRAPH * HDIM);

    const int T = 256;
    auto cdiv = [](int a, int b) { return (a + b - 1) / b; };
    const int B = cdiv(n + 1, SCANW);   // scan blocks (covers index n)

    cudaMemsetAsync(ibuf, 0, sizeof(int) * (NPARTIAL + NNODES));
    cudaMemsetAsync(pool, 0, sizeof(float) * (NGRAPH * HDIM) + sizeof(int) * NGRAPH);

    // CSR build
    k_count_deg<<<cdiv(e, T), T>>>(dst, deg, e);                                   // 1
    k_scan_block<<<B, SCANW>>>(deg, part, bsum, n);                                // 2
    k_fill<<<cdiv(e, T), T>>>(src, dst, deg, part, bsum, B, bpref, cnt2, csr, e);  // 3

    // conv1 fused: agg64(x) -> GEMM(W1) -> LN -> ReLU -> bufb
    k_agg_gemm_ln<FDIM, true><<<n / 32, T>>>(x, deg, csr, part, bpref,
                                             W1, b1, g1, be1, bufb, n);            // 4 <- profiled
    // conv2 fused: agg128(bufb) -> GEMM(W2) -> LN -> bufa
    k_agg_gemm_ln<HDIM, false><<<n / 32, T>>>(bufb, deg, csr, part, bpref,
                                              W2, b2, g2, be2, bufa, n);           // 5

    // mean pool per graph (batch is sorted)
    const int rpb = 128;
    k_pool_sum<<<cdiv(n, rpb), HDIM>>>(bufa, batch, gsum, gcnt, n, rpb);           // 6
    k_finalize<<<cdiv(NGRAPH * HDIM, HDIM), HDIM>>>(gsum, gcnt, (float*)d_out);    // 7
}

// round 9
// speedup vs baseline: 1.0469x; 1.0469x over previous
#include <cuda_runtime.h>
#include <cstdint>

// Problem constants (shapes fixed by the dataset)
#define NNODES 100000
#define NEDGES 1600000
#define NGRAPH 128
#define HDIM   128
#define FDIM   64
#define LN_EPS 1e-5f

#define SCANW   1024
#define NSCANBLK ((NNODES + SCANW) / SCANW + 1)
#define NPARTIAL (NSCANBLK * SCANW)

// packed fp32x2 FMA (Blackwell): d = a*b + d elementwise on 2xf32
#define FMA2(d, a, b)    asm("fma.rn.f32x2 %0, %1, %2, %0;" : "+l"(d) : "l"(a), "l"(b))
#define SPLAT2(o, f)     asm("mov.b64 %0, {%1, %1};" : "=l"(o) : "f"(f))
#define UNPK2(lo, hi, v) asm("mov.b64 {%0, %1}, %2;" : "=f"(lo), "=f"(hi) : "l"(v))

// ---------------- scratch (device globals; no allocations allowed) ----------
__device__ int   g_ibuf[NPARTIAL + NNODES];         // deg + fill cursors (one memset)
__device__ int   g_partial[NPARTIAL];               // per-block exclusive scan
__device__ int   g_blocksum[256];
__device__ int   g_blockpref[128];                  // written by k_fill block 0
__device__ int2  g_csr[NEDGES];                     // (src, bits(dinv[src]))
__device__ float g_bufa[(size_t)NNODES * HDIM];
__device__ float g_bufb[(size_t)NNODES * HDIM];
__device__ float g_pool[NGRAPH * HDIM + NGRAPH];    // gsum + gcnt (one memset)

// ---------------- degree count ----------------
__global__ void k_count_deg(const int* __restrict__ dst, int* __restrict__ deg, int e) {
    int i = blockIdx.x * blockDim.x + threadIdx.x;
    if (i < e) atomicAdd(&deg[dst[i]], 1);
}

// ---------------- per-block exclusive scan (level 1) ----------------
__global__ void k_scan_block(const int* __restrict__ deg, int* __restrict__ partial,
                             int* __restrict__ blocksum, int n) {
    __shared__ int sm[2][SCANW];
    int t = threadIdx.x;
    int g = blockIdx.x * SCANW + t;
    int v = (g < n) ? deg[g] : 0;
    sm[0][t] = v;
    __syncthreads();
    int cur = 0;
#pragma unroll
    for (int off = 1; off < SCANW; off <<= 1) {
        int x = sm[cur][t];
        if (t >= off) x += sm[cur][t - off];
        sm[cur ^ 1][t] = x;
        __syncthreads();
        cur ^= 1;
    }
    int inc = sm[cur][t];
    partial[g] = inc - v;
    if (t == SCANW - 1) blocksum[blockIdx.x] = inc;
}

// Level-2 prefix computed in-block (<=128 scan blocks). All threads call it.
__device__ __forceinline__ void block_prefix(const int* __restrict__ bsum, int B,
                                             int* __restrict__ sbp) {
    __shared__ int tmp[128];
    int t = threadIdx.x;
    int v = 0;
    if (t < 128) { v = (t < B) ? bsum[t] : 0; tmp[t] = v; }
    __syncthreads();
#pragma unroll
    for (int off = 1; off < 128; off <<= 1) {
        int x = 0;
        if (t < 128) { x = tmp[t]; if (t >= off) x += tmp[t - off]; }
        __syncthreads();
        if (t < 128) tmp[t] = x;
        __syncthreads();
    }
    if (t < 128) sbp[t] = tmp[t] - v;   // exclusive
    __syncthreads();
}

// ---------------- CSR fill (also publishes the level-2 prefix) --------------
__global__ void __launch_bounds__(256)
k_fill(const int* __restrict__ src, const int* __restrict__ dst,
       const int* __restrict__ deg, const int* __restrict__ partial,
       const int* __restrict__ bsum, int B, int* __restrict__ bpref_g,
       int* __restrict__ cnt2, int2* __restrict__ csr, int e) {
    __shared__ int sbp[128];
    block_prefix(bsum, B, sbp);
    if (blockIdx.x == 0 && threadIdx.x < 128) bpref_g[threadIdx.x] = sbp[threadIdx.x];
    int i = blockIdx.x * blockDim.x + threadIdx.x;
    if (i >= e) return;
    int s = src[i];
    int d = dst[i];
    float dvs = rsqrtf((float)(deg[s] + 1));
    int pos = partial[d] + sbp[d >> 10] + atomicAdd(&cnt2[d], 1);
    csr[pos] = make_int2(s, __float_as_int(dvs));
}

// ---------------- FUSED gather-aggregate + GEMM + bias + LN (+ReLU) ---------
// Phase 1 (R7-proven): 8 warps aggregate 4 nodes each into row-major sX.
// Phase 2: X @ W with packed fma.rn.f32x2 — W col-pairs come free as aligned
//          64-bit halves of the LDS.128; x is splatted. 8 FMA2 + 4 MOV per kk
//          replaces 16 FFMA -> half the fma-pipe issue slots.
template <int K, bool RELU>
__global__ void __launch_bounds__(256)
k_agg_gemm_ln(const float* __restrict__ feat, const int* __restrict__ deg,
              const int2* __restrict__ csr, const int* __restrict__ partial,
              const int* __restrict__ bpref,
              const float* __restrict__ W, const float* __restrict__ bias,
              const float* __restrict__ gamma, const float* __restrict__ beta,
              float* __restrict__ out, int n) {
    __shared__ __align__(16) float sW[32][128];
    __shared__ __align__(16) float sX[32][K + 4];   // row-major, +4 pad

    const int tid  = threadIdx.x;
    const int warp = tid >> 5;
    const int lane = tid & 31;
    const int row0 = blockIdx.x * 32;   // n divisible by 32

    // ---------------- phase 1: aggregation into sX (row-major, as R7) -------
#pragma unroll
    for (int i = 0; i < 4; i++) {
        const int rl = warp * 4 + i;
        const int w = row0 + rl;
        const int r0 = partial[w] + bpref[w >> 10];
        const int r1 = partial[w + 1] + bpref[(w + 1) >> 10];
        const float dv = rsqrtf((float)(deg[w] + 1));

        if (K == 64) {
            float2 acc = reinterpret_cast<const float2*>(feat)[(size_t)w * 32 + lane];
            acc.x *= dv; acc.y *= dv;
            int r = r0;
            for (; r + 4 <= r1; r += 4) {
                int2 e0 = csr[r], e1 = csr[r + 1], e2 = csr[r + 2], e3 = csr[r + 3];
                float2 v0 = reinterpret_cast<const float2*>(feat)[(size_t)e0.x * 32 + lane];
                float2 v1 = reinterpret_cast<const float2*>(feat)[(size_t)e1.x * 32 + lane];
                float2 v2 = reinterpret_cast<const float2*>(feat)[(size_t)e2.x * 32 + lane];
                float2 v3 = reinterpret_cast<const float2*>(feat)[(size_t)e3.x * 32 + lane];
                float w0 = __int_as_float(e0.y), w1 = __int_as_float(e1.y);
                float w2 = __int_as_float(e2.y), w3 = __int_as_float(e3.y);
                acc.x = fmaf(w0, v0.x, acc.x); acc.y = fmaf(w0, v0.y, acc.y);
                acc.x = fmaf(w1, v1.x, acc.x); acc.y = fmaf(w1, v1.y, acc.y);
                acc.x = fmaf(w2, v2.x, acc.x); acc.y = fmaf(w2, v2.y, acc.y);
                acc.x = fmaf(w3, v3.x, acc.x); acc.y = fmaf(w3, v3.y, acc.y);
            }
            for (; r < r1; r++) {
                int2 e0 = csr[r];
                float2 v0 = reinterpret_cast<const float2*>(feat)[(size_t)e0.x * 32 + lane];
                float w0 = __int_as_float(e0.y);
                acc.x = fmaf(w0, v0.x, acc.x); acc.y = fmaf(w0, v0.y, acc.y);
            }
            acc.x *= dv; acc.y *= dv;
            *reinterpret_cast<float2*>(&sX[rl][lane * 2]) = acc;
        } else {
            float4 acc = reinterpret_cast<const float4*>(feat)[(size_t)w * 32 + lane];
            acc.x *= dv; acc.y *= dv; acc.z *= dv; acc.w *= dv;
            int r = r0;
            for (; r + 4 <= r1; r += 4) {
                int2 e0 = csr[r], e1 = csr[r + 1], e2 = csr[r + 2], e3 = csr[r + 3];
                float4 v0 = reinterpret_cast<const float4*>(feat)[(size_t)e0.x * 32 + lane];
                float4 v1 = reinterpret_cast<const float4*>(feat)[(size_t)e1.x * 32 + lane];
                float4 v2 = reinterpret_cast<const float4*>(feat)[(size_t)e2.x * 32 + lane];
                float4 v3 = reinterpret_cast<const float4*>(feat)[(size_t)e3.x * 32 + lane];
                float w0 = __int_as_float(e0.y), w1 = __int_as_float(e1.y);
                float w2 = __int_as_float(e2.y), w3 = __int_as_float(e3.y);
                acc.x = fmaf(w0, v0.x, acc.x); acc.y = fmaf(w0, v0.y, acc.y);
                acc.z = fmaf(w0, v0.z, acc.z); acc.w = fmaf(w0, v0.w, acc.w);
                acc.x = fmaf(w1, v1.x, acc.x); acc.y = fmaf(w1, v1.y, acc.y);
                acc.z = fmaf(w1, v1.z, acc.z); acc.w = fmaf(w1, v1.w, acc.w);
                acc.x = fmaf(w2, v2.x, acc.x); acc.y = fmaf(w2, v2.y, acc.y);
                acc.z = fmaf(w2, v2.z, acc.z); acc.w = fmaf(w2, v2.w, acc.w);
                acc.x = fmaf(w3, v3.x, acc.x); acc.y = fmaf(w3, v3.y, acc.y);
                acc.z = fmaf(w3, v3.z, acc.z); acc.w = fmaf(w3, v3.w, acc.w);
            }
            for (; r < r1; r++) {
                int2 e0 = csr[r];
                float4 v0 = reinterpret_cast<const float4*>(feat)[(size_t)e0.x * 32 + lane];
                float w0 = __int_as_float(e0.y);
                acc.x = fmaf(w0, v0.x, acc.x); acc.y = fmaf(w0, v0.y, acc.y);
                acc.z = fmaf(w0, v0.z, acc.z); acc.w = fmaf(w0, v0.w, acc.w);
            }
            acc.x *= dv; acc.y *= dv; acc.z *= dv; acc.w *= dv;
            *reinterpret_cast<float4*>(&sX[rl][lane * 4]) = acc;
        }
    }
    __syncthreads();

    // ---------------- phase 2: GEMM (fma.rn.f32x2) + LN ----------------
    // acc2[r][cp]: packed pair (col 4*lane+2cp, 4*lane+2cp+1) for local row r.
    uint64_t acc2[4][2];
#pragma unroll
    for (int r = 0; r < 4; r++) { acc2[r][0] = 0ull; acc2[r][1] = 0ull; }

#pragma unroll
    for (int kt = 0; kt < K; kt += 32) {
        // stage W chunk: 32x128 floats = 1024 float4, 256 threads -> 4 each
#pragma unroll
        for (int i = tid; i < 1024; i += 256) {
            int kk = i >> 5;
            int c4 = i & 31;
            reinterpret_cast<float4*>(sW[kk])[c4] =
                reinterpret_cast<const float4*>(W + (size_t)(kt + kk) * 128)[c4];
        }
        __syncthreads();

#pragma unroll
        for (int kk = 0; kk < 32; kk++) {
            // W col-pairs: free aligned u64 halves of the 16B shared load
            ulonglong2 wp = *reinterpret_cast<const ulonglong2*>(&sW[kk][lane * 4]);
#pragma unroll
            for (int r = 0; r < 4; r++) {
                float xv = sX[warp * 4 + r][kt + kk];
                uint64_t xs;
                SPLAT2(xs, xv);
                FMA2(acc2[r][0], xs, wp.x);
                FMA2(acc2[r][1], xs, wp.y);
            }
        }
        __syncthreads();
    }

    const float4 bv = reinterpret_cast<const float4*>(bias)[lane];
    const float4 gv = reinterpret_cast<const float4*>(gamma)[lane];
    const float4 be = reinterpret_cast<const float4*>(beta)[lane];

#pragma unroll
    for (int r = 0; r < 4; r++) {
        float ax, ay, az, aw;
        UNPK2(ax, ay, acc2[r][0]);
        UNPK2(az, aw, acc2[r][1]);
        float hx = ax + bv.x;
        float hy = ay + bv.y;
        float hz = az + bv.z;
        float hw = aw + bv.w;
        float s = hx + hy + hz + hw;
#pragma unroll
        for (int o = 16; o > 0; o >>= 1) s += __shfl_xor_sync(0xffffffffu, s, o);
        float mu = s * (1.0f / 128.0f);
        float dx = hx - mu, dy = hy - mu, dz = hz - mu, dw = hw - mu;
        float q = dx * dx + dy * dy + dz * dz + dw * dw;
#pragma unroll
        for (int o = 16; o > 0; o >>= 1) q += __shfl_xor_sync(0xffffffffu, q, o);
        float rstd = rsqrtf(q * (1.0f / 128.0f) + LN_EPS);

        float4 o4;
        o4.x = dx * rstd * gv.x + be.x;
        o4.y = dy * rstd * gv.y + be.y;
        o4.z = dz * rstd * gv.z + be.z;
        o4.w = dw * rstd * gv.w + be.w;
        if (RELU) {
            o4.x = fmaxf(o4.x, 0.0f);
            o4.y = fmaxf(o4.y, 0.0f);
            o4.z = fmaxf(o4.z, 0.0f);
            o4.w = fmaxf(o4.w, 0.0f);
        }
        int row = row0 + warp * 4 + r;
        reinterpret_cast<float4*>(out + (size_t)row * 128)[lane] = o4;
    }
}

// ---------------- pooling (batch is sorted; count fused) ----------------
__global__ void k_pool_sum(const float* __restrict__ h, const int* __restrict__ batch,
                           float* __restrict__ gsum, int* __restrict__ gcnt, int n, int rpb) {
    int c  = threadIdx.x;
    int r0 = blockIdx.x * rpb;
    int r1 = min(r0 + rpb, n);
    if (r0 >= r1) return;
    float acc = 0.0f;
    int cnt = 0;
    int cur = batch[r0];
    for (int r = r0; r < r1; r++) {
        int g = batch[r];
        if (g != cur) {
            atomicAdd(&gsum[cur * HDIM + c], acc);
            if (c == 0) atomicAdd(&gcnt[cur], cnt);
            acc = 0.0f; cnt = 0; cur = g;
        }
        acc += h[(size_t)r * HDIM + c];
        cnt++;
    }
    atomicAdd(&gsum[cur * HDIM + c], acc);
    if (c == 0) atomicAdd(&gcnt[cur], cnt);
}

__global__ void k_finalize(const float* __restrict__ gsum, const int* __restrict__ gcnt,
                           float* __restrict__ out) {
    int i = blockIdx.x * blockDim.x + threadIdx.x;
    if (i >= NGRAPH * HDIM) return;
    float cnt = fmaxf((float)gcnt[i >> 7], 1.0f);
    out[i] = gsum[i] / cnt;
}

// ---------------- launch ----------------
extern "C" void kernel_launch(void* const* d_in, const int* in_sizes, int n_in,
                              void* d_out, int out_size) {
    const float* x     = (const float*)d_in[0];
    const int*   eidx  = (const int*)d_in[1];
    const int*   batch = (const int*)d_in[2];
    const float* W1 = (const float*)d_in[3];
    const float* b1 = (const float*)d_in[4];
    const float* g1 = (const float*)d_in[5];
    const float* be1 = (const float*)d_in[6];
    const float* W2 = (const float*)d_in[7];
    const float* b2 = (const float*)d_in[8];
    const float* g2 = (const float*)d_in[9];
    const float* be2 = (const float*)d_in[10];

    const int n = in_sizes[0] / FDIM;   // 100000
    const int e = in_sizes[1] / 2;      // 1600000
    const int* src = eidx;
    const int* dst = eidx + e;

    int*   ibuf;  cudaGetSymbolAddress((void**)&ibuf,  g_ibuf);
    int*   part;  cudaGetSymbolAddress((void**)&part,  g_partial);
    int*   bsum;  cudaGetSymbolAddress((void**)&bsum,  g_blocksum);
    int*   bpref; cudaGetSymbolAddress((void**)&bpref, g_blockpref);
    int2*  csr;   cudaGetSymbolAddress((void**)&csr,   g_csr);
    float* bufa;  cudaGetSymbolAddress((void**)&bufa,  g_bufa);
    float* bufb;  cudaGetSymbolAddress((void**)&bufb,  g_bufb);
    float* pool;  cudaGetSymbolAddress((void**)&pool,  g_pool);

    int* deg  = ibuf;
    int* cnt2 = ibuf + NPARTIAL;
    float* gsum = pool;
    int*   gcnt = (int*)(pool + NGRAPH * HDIM);

    const int T = 256;
    auto cdiv = [](int a, int b) { return (a + b - 1) / b; };
    const int B = cdiv(n + 1, SCANW);   // scan blocks (covers index n)

    cudaMemsetAsync(ibuf, 0, sizeof(int) * (NPARTIAL + NNODES));
    cudaMemsetAsync(pool, 0, sizeof(float) * (NGRAPH * HDIM) + sizeof(int) * NGRAPH);

    // CSR build
    k_count_deg<<<cdiv(e, T), T>>>(dst, deg, e);                                   // 1
    k_scan_block<<<B, SCANW>>>(deg, part, bsum, n);                                // 2
    k_fill<<<cdiv(e, T), T>>>(src, dst, deg, part, bsum, B, bpref, cnt2, csr, e);  // 3

    // conv1 fused: agg64(x) -> GEMM(W1) -> LN -> ReLU -> bufb
    k_agg_gemm_ln<FDIM, true><<<n / 32, T>>>(x, deg, csr, part, bpref,
                                             W1, b1, g1, be1, bufb, n);            // 4 <- profiled
    // conv2 fused: agg128(bufb) -> GEMM(W2) -> LN -> bufa
    k_agg_gemm_ln<HDIM, false><<<n / 32, T>>>(bufb, deg, csr, part, bpref,
                                              W2, b2, g2, be2, bufa, n);           // 5

    // mean pool per graph (batch is sorted)
    const int rpb = 128;
    k_pool_sum<<<cdiv(n, rpb), HDIM>>>(bufa, batch, gsum, gcnt, n, rpb);           // 6
    k_finalize<<<cdiv(NGRAPH * HDIM, HDIM), HDIM>>>(gsum, gcnt, (float*)d_out);    // 7
}

// round 10
// speedup vs baseline: 1.1270x; 1.0765x over previous
#include <cuda_runtime.h>
#include <cuda_bf16.h>
#include <cstdint>

// Problem constants (shapes fixed by the dataset)
#define NNODES 100000
#define NEDGES 1600000
#define NGRAPH 128
#define HDIM   128
#define FDIM   64
#define LN_EPS 1e-5f

#define SCANW   1024
#define NSCANBLK ((NNODES + SCANW) / SCANW + 1)
#define NPARTIAL (NSCANBLK * SCANW)

typedef unsigned short ushort_t;

// ---------------- mma / ldmatrix (Ampere-path HMMA, legal on plain sm_100) --
#define LDSM4(r0, r1, r2, r3, addr) \
    asm volatile("ldmatrix.sync.aligned.m8n8.x4.shared.b16 {%0,%1,%2,%3}, [%4];" \
                 : "=r"(r0), "=r"(r1), "=r"(r2), "=r"(r3) : "r"(addr))

#define MMA_BF16(d, a0, a1, a2, a3, b0, b1) \
    asm volatile("mma.sync.aligned.m16n8k16.row.col.f32.bf16.bf16.f32 " \
                 "{%0,%1,%2,%3}, {%4,%5,%6,%7}, {%8,%9}, {%0,%1,%2,%3};" \
                 : "+f"(d[0]), "+f"(d[1]), "+f"(d[2]), "+f"(d[3]) \
                 : "r"(a0), "r"(a1), "r"(a2), "r"(a3), "r"(b0), "r"(b1))

__device__ __forceinline__ uint32_t smem_u32(const void* p) {
    uint32_t a;
    asm("{ .reg .u64 t; cvta.to.shared.u64 t, %1; cvt.u32.u64 %0, t; }" : "=r"(a) : "l"(p));
    return a;
}

// ---------------- scratch (device globals; no allocations allowed) ----------
__device__ int      g_ibuf[NPARTIAL + NNODES];      // deg + fill cursors (one memset)
__device__ int      g_partial[NPARTIAL];
__device__ int      g_blocksum[256];
__device__ int      g_blockpref[128];
__device__ int2     g_csr[NEDGES];                  // (src, bits(dinv[src]))
__device__ float    g_bufa[(size_t)NNODES * HDIM];
__device__ float    g_bufb[(size_t)NNODES * HDIM];
__device__ float    g_pool[NGRAPH * HDIM + NGRAPH];
// W split images, chunk-major [chunk][n=128][40 k-slots] (k pad 32..39 zeroed)
__device__ ushort_t g_w1h[2 * 128 * 40], g_w1l[2 * 128 * 40];
__device__ ushort_t g_w2h[4 * 128 * 40], g_w2l[4 * 128 * 40];

// ---------------- degree count + W split prep (fused, tail blocks) ----------
__device__ __forceinline__ void prep_w(const float* __restrict__ W, int K,
                                       ushort_t* __restrict__ wh, ushort_t* __restrict__ wl) {
    for (int idx = threadIdx.x; idx < K * 128; idx += 256) {
        int k = idx >> 7, nn = idx & 127;
        float v = W[idx];
        __nv_bfloat16 h = __float2bfloat16(v);
        __nv_bfloat16 l = __float2bfloat16(v - __bfloat162float(h));
        int off = (((k >> 5) * 128 + nn) * 40) + (k & 31);
        wh[off] = __bfloat16_as_ushort(h);
        wl[off] = __bfloat16_as_ushort(l);
    }
    // zero the k-pad slots (never read by ldmatrix, but keep deterministic)
    for (int idx = threadIdx.x; idx < (K / 32) * 128 * 8; idx += 256) {
        int cn = idx >> 3;
        int off = cn * 40 + 32 + (idx & 7);
        wh[off] = 0; wl[off] = 0;
    }
}

__global__ void __launch_bounds__(256)
k_count_prep(const int* __restrict__ dst, int* __restrict__ deg, int e, int nb,
             const float* __restrict__ W1, const float* __restrict__ W2,
             ushort_t* w1h, ushort_t* w1l, ushort_t* w2h, ushort_t* w2l) {
    if ((int)blockIdx.x < nb) {
        int i = blockIdx.x * 256 + threadIdx.x;
        if (i < e) atomicAdd(&deg[dst[i]], 1);
        return;
    }
    if (blockIdx.x == (unsigned)nb) prep_w(W1, FDIM, w1h, w1l);
    else                            prep_w(W2, HDIM, w2h, w2l);
}

// ---------------- per-block exclusive scan (level 1) ----------------
__global__ void k_scan_block(const int* __restrict__ deg, int* __restrict__ partial,
                             int* __restrict__ blocksum, int n) {
    __shared__ int sm[2][SCANW];
    int t = threadIdx.x;
    int g = blockIdx.x * SCANW + t;
    int v = (g < n) ? deg[g] : 0;
    sm[0][t] = v;
    __syncthreads();
    int cur = 0;
#pragma unroll
    for (int off = 1; off < SCANW; off <<= 1) {
        int x = sm[cur][t];
        if (t >= off) x += sm[cur][t - off];
        sm[cur ^ 1][t] = x;
        __syncthreads();
        cur ^= 1;
    }
    int inc = sm[cur][t];
    partial[g] = inc - v;
    if (t == SCANW - 1) blocksum[blockIdx.x] = inc;
}

// Level-2 prefix computed in-block (<=128 scan blocks). All threads call it.
__device__ __forceinline__ void block_prefix(const int* __restrict__ bsum, int B,
                                             int* __restrict__ sbp) {
    __shared__ int tmp[128];
    int t = threadIdx.x;
    int v = 0;
    if (t < 128) { v = (t < B) ? bsum[t] : 0; tmp[t] = v; }
    __syncthreads();
#pragma unroll
    for (int off = 1; off < 128; off <<= 1) {
        int x = 0;
        if (t < 128) { x = tmp[t]; if (t >= off) x += tmp[t - off]; }
        __syncthreads();
        if (t < 128) tmp[t] = x;
        __syncthreads();
    }
    if (t < 128) sbp[t] = tmp[t] - v;   // exclusive
    __syncthreads();
}

// ---------------- CSR fill (also publishes the level-2 prefix) --------------
__global__ void __launch_bounds__(256)
k_fill(const int* __restrict__ src, const int* __restrict__ dst,
       const int* __restrict__ deg, const int* __restrict__ partial,
       const int* __restrict__ bsum, int B, int* __restrict__ bpref_g,
       int* __restrict__ cnt2, int2* __restrict__ csr, int e) {
    __shared__ int sbp[128];
    block_prefix(bsum, B, sbp);
    if (blockIdx.x == 0 && threadIdx.x < 128) bpref_g[threadIdx.x] = sbp[threadIdx.x];
    int i = blockIdx.x * blockDim.x + threadIdx.x;
    if (i >= e) return;
    int s = src[i];
    int d = dst[i];
    float dvs = rsqrtf((float)(deg[s] + 1));
    int pos = partial[d] + sbp[d >> 10] + atomicAdd(&cnt2[d], 1);
    csr[pos] = make_int2(s, __float_as_int(dvs));
}

// ---------------- FUSED gather-aggregate + tensor GEMM + bias + LN (+ReLU) --
// Phase 1 (R7-proven gather): 8 warps aggregate 4 nodes each; result converted
//   to bf16 hi/lo and stored to padded smem tiles (stride K+8 -> conflict-free
//   ldmatrix).
// Phase 2: bf16 3-split mma.sync.m16n8k16 (D = AhWh + AhWl + AlWh, fp32 acc),
//   W staged in 32-k chunks from pre-split global images. Fragments written to
//   smem (aliasing the X tiles), then the proven LN epilogue runs on rows.
template <int K, bool RELU>
__global__ void __launch_bounds__(256)
k_agg_gemm_ln(const float* __restrict__ feat, const int* __restrict__ deg,
              const int2* __restrict__ csr, const int* __restrict__ partial,
              const int* __restrict__ bpref,
              const ushort_t* __restrict__ gWh, const ushort_t* __restrict__ gWl,
              const float* __restrict__ bias, const float* __restrict__ gamma,
              const float* __restrict__ beta, float* __restrict__ out, int n) {
    constexpr int XSTR   = K + 8;                 // ushorts per X row (pad)
    constexpr int NCH    = K / 32;                // W chunks
    constexpr int XBYTES = 32 * XSTR * 2;         // one X split
    constexpr int WBYTES = 128 * 40 * 2;          // one W chunk split

    __shared__ __align__(16) unsigned char sbuf[2 * XBYTES + 2 * WBYTES];
    ushort_t* sXh = (ushort_t*)sbuf;
    ushort_t* sXl = (ushort_t*)(sbuf + XBYTES);
    ushort_t* sWh = (ushort_t*)(sbuf + 2 * XBYTES);
    ushort_t* sWl = (ushort_t*)(sbuf + 2 * XBYTES + WBYTES);
    float (*sOut)[132] = (float (*)[132])sbuf;    // aliases X tiles after mma

    const int tid  = threadIdx.x;
    const int warp = tid >> 5;
    const int lane = tid & 31;
    const int row0 = blockIdx.x * 32;             // n divisible by 32

    // ---------------- phase 1: gather-aggregate -> bf16 hi/lo tiles ---------
#pragma unroll
    for (int i = 0; i < 4; i++) {
        const int rl = warp * 4 + i;
        const int w = row0 + rl;
        const int r0 = partial[w] + bpref[w >> 10];
        const int r1 = partial[w + 1] + bpref[(w + 1) >> 10];
        const float dv = rsqrtf((float)(deg[w] + 1));

        if (K == 64) {
            float2 acc = reinterpret_cast<const float2*>(feat)[(size_t)w * 32 + lane];
            acc.x *= dv; acc.y *= dv;
            int r = r0;
            for (; r + 4 <= r1; r += 4) {
                int2 e0 = csr[r], e1 = csr[r + 1], e2 = csr[r + 2], e3 = csr[r + 3];
                float2 v0 = reinterpret_cast<const float2*>(feat)[(size_t)e0.x * 32 + lane];
                float2 v1 = reinterpret_cast<const float2*>(feat)[(size_t)e1.x * 32 + lane];
                float2 v2 = reinterpret_cast<const float2*>(feat)[(size_t)e2.x * 32 + lane];
                float2 v3 = reinterpret_cast<const float2*>(feat)[(size_t)e3.x * 32 + lane];
                float w0 = __int_as_float(e0.y), w1 = __int_as_float(e1.y);
                float w2 = __int_as_float(e2.y), w3 = __int_as_float(e3.y);
                acc.x = fmaf(w0, v0.x, acc.x); acc.y = fmaf(w0, v0.y, acc.y);
                acc.x = fmaf(w1, v1.x, acc.x); acc.y = fmaf(w1, v1.y, acc.y);
                acc.x = fmaf(w2, v2.x, acc.x); acc.y = fmaf(w2, v2.y, acc.y);
                acc.x = fmaf(w3, v3.x, acc.x); acc.y = fmaf(w3, v3.y, acc.y);
            }
            for (; r < r1; r++) {
                int2 e0 = csr[r];
                float2 v0 = reinterpret_cast<const float2*>(feat)[(size_t)e0.x * 32 + lane];
                float w0 = __int_as_float(e0.y);
                acc.x = fmaf(w0, v0.x, acc.x); acc.y = fmaf(w0, v0.y, acc.y);
            }
            acc.x *= dv; acc.y *= dv;
            __nv_bfloat162 hp = __floats2bfloat162_rn(acc.x, acc.y);
            float2 hf = __bfloat1622float2(hp);
            __nv_bfloat162 lp = __floats2bfloat162_rn(acc.x - hf.x, acc.y - hf.y);
            ((uint32_t*)sXh)[rl * (XSTR / 2) + lane] = *reinterpret_cast<uint32_t*>(&hp);
            ((uint32_t*)sXl)[rl * (XSTR / 2) + lane] = *reinterpret_cast<uint32_t*>(&lp);
        } else {
            float4 acc = reinterpret_cast<const float4*>(feat)[(size_t)w * 32 + lane];
            acc.x *= dv; acc.y *= dv; acc.z *= dv; acc.w *= dv;
            int r = r0;
            for (; r + 4 <= r1; r += 4) {
                int2 e0 = csr[r], e1 = csr[r + 1], e2 = csr[r + 2], e3 = csr[r + 3];
                float4 v0 = reinterpret_cast<const float4*>(feat)[(size_t)e0.x * 32 + lane];
                float4 v1 = reinterpret_cast<const float4*>(feat)[(size_t)e1.x * 32 + lane];
                float4 v2 = reinterpret_cast<const float4*>(feat)[(size_t)e2.x * 32 + lane];
                float4 v3 = reinterpret_cast<const float4*>(feat)[(size_t)e3.x * 32 + lane];
                float w0 = __int_as_float(e0.y), w1 = __int_as_float(e1.y);
                float w2 = __int_as_float(e2.y), w3 = __int_as_float(e3.y);
                acc.x = fmaf(w0, v0.x, acc.x); acc.y = fmaf(w0, v0.y, acc.y);
                acc.z = fmaf(w0, v0.z, acc.z); acc.w = fmaf(w0, v0.w, acc.w);
                acc.x = fmaf(w1, v1.x, acc.x); acc.y = fmaf(w1, v1.y, acc.y);
                acc.z = fmaf(w1, v1.z, acc.z); acc.w = fmaf(w1, v1.w, acc.w);
                acc.x = fmaf(w2, v2.x, acc.x); acc.y = fmaf(w2, v2.y, acc.y);
                acc.z = fmaf(w2, v2.z, acc.z); acc.w = fmaf(w2, v2.w, acc.w);
                acc.x = fmaf(w3, v3.x, acc.x); acc.y = fmaf(w3, v3.y, acc.y);
                acc.z = fmaf(w3, v3.z, acc.z); acc.w = fmaf(w3, v3.w, acc.w);
            }
            for (; r < r1; r++) {
                int2 e0 = csr[r];
                float4 v0 = reinterpret_cast<const float4*>(feat)[(size_t)e0.x * 32 + lane];
                float w0 = __int_as_float(e0.y);
                acc.x = fmaf(w0, v0.x, acc.x); acc.y = fmaf(w0, v0.y, acc.y);
                acc.z = fmaf(w0, v0.z, acc.z); acc.w = fmaf(w0, v0.w, acc.w);
            }
            acc.x *= dv; acc.y *= dv; acc.z *= dv; acc.w *= dv;
            __nv_bfloat162 hp0 = __floats2bfloat162_rn(acc.x, acc.y);
            __nv_bfloat162 hp1 = __floats2bfloat162_rn(acc.z, acc.w);
            float2 hf0 = __bfloat1622float2(hp0);
            float2 hf1 = __bfloat1622float2(hp1);
            __nv_bfloat162 lp0 = __floats2bfloat162_rn(acc.x - hf0.x, acc.y - hf0.y);
            __nv_bfloat162 lp1 = __floats2bfloat162_rn(acc.z - hf1.x, acc.w - hf1.y);
            uint2 hu = make_uint2(*reinterpret_cast<uint32_t*>(&hp0),
                                  *reinterpret_cast<uint32_t*>(&hp1));
            uint2 lu = make_uint2(*reinterpret_cast<uint32_t*>(&lp0),
                                  *reinterpret_cast<uint32_t*>(&lp1));
            *reinterpret_cast<uint2*>(sXh + rl * XSTR + lane * 4) = hu;
            *reinterpret_cast<uint2*>(sXl + rl * XSTR + lane * 4) = lu;
        }
    }

    // ---------------- phase 2: bf16 3-split mma ----------------
    const int rt = warp & 1;                       // row-tile (16 rows)
    const int nb = (warp >> 1) << 5;               // n base (32 cols)
    const int a_row = rt * 16 + (lane & 7) + ((lane >> 3) & 1) * 8;
    const int a_k   = (lane >> 4) * 8;
    const uint32_t aH = smem_u32(sXh) + (uint32_t)(a_row * XSTR + a_k) * 2;
    const uint32_t aL = smem_u32(sXl) + (uint32_t)(a_row * XSTR + a_k) * 2;
    const int b_n = (lane & 7) + ((lane >> 4) & 1) * 8;
    const int b_k = ((lane >> 3) & 1) * 8;
    const uint32_t bH0 = smem_u32(sWh) + (uint32_t)((nb + b_n) * 40 + b_k) * 2;
    const uint32_t bL0 = smem_u32(sWl) + (uint32_t)((nb + b_n) * 40 + b_k) * 2;
    const uint32_t bH1 = bH0 + 16 * 40 * 2;
    const uint32_t bL1 = bL0 + 16 * 40 * 2;

    float acc[4][4];
#pragma unroll
    for (int t = 0; t < 4; t++)
#pragma unroll
        for (int c = 0; c < 4; c++) acc[t][c] = 0.0f;

#pragma unroll
    for (int c = 0; c < NCH; c++) {
        // stage W chunk c (hi+lo = 1280 uint4)
        {
            const uint4* srcH = reinterpret_cast<const uint4*>(gWh + c * 5120);
            const uint4* srcL = reinterpret_cast<const uint4*>(gWl + c * 5120);
            uint4* dH = reinterpret_cast<uint4*>(sWh);
            uint4* dL = reinterpret_cast<uint4*>(sWl);
#pragma unroll
            for (int i = tid; i < 640; i += 256) { dH[i] = srcH[i]; dL[i] = srcL[i]; }
        }
        __syncthreads();   // covers X stores (iter 0) + W chunk visibility

#pragma unroll
        for (int ks = 0; ks < 2; ks++) {
            const uint32_t ko = (uint32_t)(c * 32 + ks * 16) * 2;  // bytes into X row
            const uint32_t kc = (uint32_t)(ks * 16) * 2;           // bytes into W chunk row
            uint32_t ah0, ah1, ah2, ah3, al0, al1, al2, al3;
            uint32_t bh0, bh1, bh2, bh3, bh4, bh5, bh6, bh7;
            uint32_t bl0, bl1, bl2, bl3, bl4, bl5, bl6, bl7;
            LDSM4(ah0, ah1, ah2, ah3, aH + ko);
            LDSM4(al0, al1, al2, al3, aL + ko);
            LDSM4(bh0, bh1, bh2, bh3, bH0 + kc);
            LDSM4(bh4, bh5, bh6, bh7, bH1 + kc);
            LDSM4(bl0, bl1, bl2, bl3, bL0 + kc);
            LDSM4(bl4, bl5, bl6, bl7, bL1 + kc);
            // tile 0: cols nb..nb+7
            MMA_BF16(acc[0], ah0, ah1, ah2, ah3, bh0, bh1);
            MMA_BF16(acc[0], ah0, ah1, ah2, ah3, bl0, bl1);
            MMA_BF16(acc[0], al0, al1, al2, al3, bh0, bh1);
            // tile 1: nb+8
            MMA_BF16(acc[1], ah0, ah1, ah2, ah3, bh2, bh3);
            MMA_BF16(acc[1], ah0, ah1, ah2, ah3, bl2, bl3);
            MMA_BF16(acc[1], al0, al1, al2, al3, bh2, bh3);
            // tile 2: nb+16
            MMA_BF16(acc[2], ah0, ah1, ah2, ah3, bh4, bh5);
            MMA_BF16(acc[2], ah0, ah1, ah2, ah3, bl4, bl5);
            MMA_BF16(acc[2], al0, al1, al2, al3, bh4, bh5);
            // tile 3: nb+24
            MMA_BF16(acc[3], ah0, ah1, ah2, ah3, bh6, bh7);
            MMA_BF16(acc[3], ah0, ah1, ah2, ah3, bl6, bl7);
            MMA_BF16(acc[3], al0, al1, al2, al3, bh6, bh7);
        }
        __syncthreads();   // W chunk reuse / final: X tiles free for sOut
    }

    // scatter fragments to sOut (aliases X tiles; safe after final sync)
    {
        const int g  = lane >> 2;
        const int cx = 2 * (lane & 3);
#pragma unroll
        for (int t = 0; t < 4; t++) {
            const int col = nb + 8 * t + cx;
            *reinterpret_cast<float2*>(&sOut[rt * 16 + g][col]) =
                make_float2(acc[t][0], acc[t][1]);
            *reinterpret_cast<float2*>(&sOut[rt * 16 + g + 8][col]) =
                make_float2(acc[t][2], acc[t][3]);
        }
    }
    __syncthreads();

    // ---------------- LN epilogue (proven) ----------------
    const float4 bv = reinterpret_cast<const float4*>(bias)[lane];
    const float4 gv = reinterpret_cast<const float4*>(gamma)[lane];
    const float4 be = reinterpret_cast<const float4*>(beta)[lane];

#pragma unroll
    for (int r = 0; r < 4; r++) {
        float4 v = *reinterpret_cast<float4*>(&sOut[warp * 4 + r][lane * 4]);
        float hx = v.x + bv.x;
        float hy = v.y + bv.y;
        float hz = v.z + bv.z;
        float hw = v.w + bv.w;
        float s = hx + hy + hz + hw;
#pragma unroll
        for (int o = 16; o > 0; o >>= 1) s += __shfl_xor_sync(0xffffffffu, s, o);
        float mu = s * (1.0f / 128.0f);
        float dx = hx - mu, dy = hy - mu, dz = hz - mu, dw = hw - mu;
        float q = dx * dx + dy * dy + dz * dz + dw * dw;
#pragma unroll
        for (int o = 16; o > 0; o >>= 1) q += __shfl_xor_sync(0xffffffffu, q, o);
        float rstd = rsqrtf(q * (1.0f / 128.0f) + LN_EPS);

        float4 o4;
        o4.x = dx * rstd * gv.x + be.x;
        o4.y = dy * rstd * gv.y + be.y;
        o4.z = dz * rstd * gv.z + be.z;
        o4.w = dw * rstd * gv.w + be.w;
        if (RELU) {
            o4.x = fmaxf(o4.x, 0.0f);
            o4.y = fmaxf(o4.y, 0.0f);
            o4.z = fmaxf(o4.z, 0.0f);
            o4.w = fmaxf(o4.w, 0.0f);
        }
        int row = row0 + warp * 4 + r;
        reinterpret_cast<float4*>(out + (size_t)row * 128)[lane] = o4;
    }
}

// ---------------- pooling (batch is sorted; count fused) ----------------
__global__ void k_pool_sum(const float* __restrict__ h, const int* __restrict__ batch,
                           float* __restrict__ gsum, int* __restrict__ gcnt, int n, int rpb) {
    int c  = threadIdx.x;
    int r0 = blockIdx.x * rpb;
    int r1 = min(r0 + rpb, n);
    if (r0 >= r1) return;
    float acc = 0.0f;
    int cnt = 0;
    int cur = batch[r0];
    for (int r = r0; r < r1; r++) {
        int g = batch[r];
        if (g != cur) {
            atomicAdd(&gsum[cur * HDIM + c], acc);
            if (c == 0) atomicAdd(&gcnt[cur], cnt);
            acc = 0.0f; cnt = 0; cur = g;
        }
        acc += h[(size_t)r * HDIM + c];
        cnt++;
    }
    atomicAdd(&gsum[cur * HDIM + c], acc);
    if (c == 0) atomicAdd(&gcnt[cur], cnt);
}

__global__ void k_finalize(const float* __restrict__ gsum, const int* __restrict__ gcnt,
                           float* __restrict__ out) {
    int i = blockIdx.x * blockDim.x + threadIdx.x;
    if (i >= NGRAPH * HDIM) return;
    float cnt = fmaxf((float)gcnt[i >> 7], 1.0f);
    out[i] = gsum[i] / cnt;
}

// ---------------- launch ----------------
extern "C" void kernel_launch(void* const* d_in, const int* in_sizes, int n_in,
                              void* d_out, int out_size) {
    const float* x     = (const float*)d_in[0];
    const int*   eidx  = (const int*)d_in[1];
    const int*   batch = (const int*)d_in[2];
    const float* W1 = (const float*)d_in[3];
    const float* b1 = (const float*)d_in[4];
    const float* g1 = (const float*)d_in[5];
    const float* be1 = (const float*)d_in[6];
    const float* W2 = (const float*)d_in[7];
    const float* b2 = (const float*)d_in[8];
    const float* g2 = (const float*)d_in[9];
    const float* be2 = (const float*)d_in[10];

    const int n = in_sizes[0] / FDIM;   // 100000
    const int e = in_sizes[1] / 2;      // 1600000
    const int* src = eidx;
    const int* dst = eidx + e;

    int*      ibuf;  cudaGetSymbolAddress((void**)&ibuf,  g_ibuf);
    int*      part;  cudaGetSymbolAddress((void**)&part,  g_partial);
    int*      bsum;  cudaGetSymbolAddress((void**)&bsum,  g_blocksum);
    int*      bpref; cudaGetSymbolAddress((void**)&bpref, g_blockpref);
    int2*     csr;   cudaGetSymbolAddress((void**)&csr,   g_csr);
    float*    bufa;  cudaGetSymbolAddress((void**)&bufa,  g_bufa);
    float*    bufb;  cudaGetSymbolAddress((void**)&bufb,  g_bufb);
    float*    pool;  cudaGetSymbolAddress((void**)&pool,  g_pool);
    ushort_t *w1h, *w1l, *w2h, *w2l;
    cudaGetSymbolAddress((void**)&w1h, g_w1h);
    cudaGetSymbolAddress((void**)&w1l, g_w1l);
    cudaGetSymbolAddress((void**)&w2h, g_w2h);
    cudaGetSymbolAddress((void**)&w2l, g_w2l);

    int* deg  = ibuf;
    int* cnt2 = ibuf + NPARTIAL;
    float* gsum = pool;
    int*   gcnt = (int*)(pool + NGRAPH * HDIM);

    const int T = 256;
    auto cdiv = [](int a, int b) { return (a + b - 1) / b; };
    const int B  = cdiv(n + 1, SCANW);
    const int nb = cdiv(e, T);

    cudaMemsetAsync(ibuf, 0, sizeof(int) * (NPARTIAL + NNODES));
    cudaMemsetAsync(pool, 0, sizeof(float) * (NGRAPH * HDIM) + sizeof(int) * NGRAPH);

    // CSR build (+W split prep in tail blocks of launch 1)
    k_count_prep<<<nb + 2, T>>>(dst, deg, e, nb, W1, W2, w1h, w1l, w2h, w2l);      // 1
    k_scan_block<<<B, SCANW>>>(deg, part, bsum, n);                                // 2
    k_fill<<<cdiv(e, T), T>>>(src, dst, deg, part, bsum, B, bpref, cnt2, csr, e);  // 3

    // conv1 fused: agg64(x) -> mma(W1) -> LN -> ReLU -> bufb
    k_agg_gemm_ln<FDIM, true><<<n / 32, T>>>(x, deg, csr, part, bpref,
                                             w1h, w1l, b1, g1, be1, bufb, n);      // 4 <- profiled
    // conv2 fused: agg128(bufb) -> mma(W2) -> LN -> bufa
    k_agg_gemm_ln<HDIM, false><<<n / 32, T>>>(bufb, deg, csr, part, bpref,
                                              w2h, w2l, b2, g2, be2, bufa, n);     // 5

    // mean pool per graph (batch is sorted)
    const int rpb = 128;
    k_pool_sum<<<cdiv(n, rpb), HDIM>>>(bufa, batch, gsum, gcnt, n, rpb);           // 6
    k_finalize<<<cdiv(NGRAPH * HDIM, HDIM), HDIM>>>(gsum, gcnt, (float*)d_out);    // 7
}

// round 11
// speedup vs baseline: 1.1486x; 1.0192x over previous
#include <cuda_runtime.h>
#include <cuda_bf16.h>
#include <cstdint>

// Problem constants (shapes fixed by the dataset)
#define NNODES 100000
#define NEDGES 1600000
#define NGRAPH 128
#define HDIM   128
#define FDIM   64
#define LN_EPS 1e-5f

#define SCANW   1024
#define NSCANBLK ((NNODES + SCANW) / SCANW + 1)
#define NPARTIAL (NSCANBLK * SCANW)

typedef unsigned short ushort_t;

// ---------------- mma / ldmatrix (Ampere-path HMMA, legal on plain sm_100) --
#define LDSM4(r0, r1, r2, r3, addr) \
    asm volatile("ldmatrix.sync.aligned.m8n8.x4.shared.b16 {%0,%1,%2,%3}, [%4];" \
                 : "=r"(r0), "=r"(r1), "=r"(r2), "=r"(r3) : "r"(addr))

#define MMA_BF16(d, a0, a1, a2, a3, b0, b1) \
    asm volatile("mma.sync.aligned.m16n8k16.row.col.f32.bf16.bf16.f32 " \
                 "{%0,%1,%2,%3}, {%4,%5,%6,%7}, {%8,%9}, {%0,%1,%2,%3};" \
                 : "+f"(d[0]), "+f"(d[1]), "+f"(d[2]), "+f"(d[3]) \
                 : "r"(a0), "r"(a1), "r"(a2), "r"(a3), "r"(b0), "r"(b1))

__device__ __forceinline__ uint32_t smem_u32(const void* p) {
    uint32_t a;
    asm("{ .reg .u64 t; cvta.to.shared.u64 t, %1; cvt.u32.u64 %0, t; }" : "=r"(a) : "l"(p));
    return a;
}

// ---------------- scratch (device globals; no allocations allowed) ----------
__device__ int      g_ibuf[NPARTIAL + NNODES];      // deg + fill cursors (one memset)
__device__ int      g_partial[NPARTIAL];
__device__ int      g_blocksum[256];
__device__ int      g_blockpref[128];
__device__ int2     g_csr[NEDGES];                  // (src, bits(dinv[src]))
__device__ float    g_bufa[(size_t)NNODES * HDIM];
__device__ float    g_bufb[(size_t)NNODES * HDIM];
__device__ float    g_pool[NGRAPH * HDIM + NGRAPH];
// W split images, chunk-major [chunk][n=128][40 k-slots] (k pad 32..39 zeroed)
__device__ ushort_t g_w1h[2 * 128 * 40], g_w1l[2 * 128 * 40];
__device__ ushort_t g_w2h[4 * 128 * 40], g_w2l[4 * 128 * 40];

// ---------------- degree count + W split prep (fused, tail blocks) ----------
__device__ __forceinline__ void prep_w(const float* __restrict__ W, int K,
                                       ushort_t* __restrict__ wh, ushort_t* __restrict__ wl) {
    for (int idx = threadIdx.x; idx < K * 128; idx += 256) {
        int k = idx >> 7, nn = idx & 127;
        float v = W[idx];
        __nv_bfloat16 h = __float2bfloat16(v);
        __nv_bfloat16 l = __float2bfloat16(v - __bfloat162float(h));
        int off = (((k >> 5) * 128 + nn) * 40) + (k & 31);
        wh[off] = __bfloat16_as_ushort(h);
        wl[off] = __bfloat16_as_ushort(l);
    }
    for (int idx = threadIdx.x; idx < (K / 32) * 128 * 8; idx += 256) {
        int cn = idx >> 3;
        int off = cn * 40 + 32 + (idx & 7);
        wh[off] = 0; wl[off] = 0;
    }
}

__global__ void __launch_bounds__(256)
k_count_prep(const int* __restrict__ dst, int* __restrict__ deg, int e, int nb,
             const float* __restrict__ W1, const float* __restrict__ W2,
             ushort_t* w1h, ushort_t* w1l, ushort_t* w2h, ushort_t* w2l) {
    if ((int)blockIdx.x < nb) {
        int i = blockIdx.x * 256 + threadIdx.x;
        if (i < e) atomicAdd(&deg[dst[i]], 1);
        return;
    }
    if (blockIdx.x == (unsigned)nb) prep_w(W1, FDIM, w1h, w1l);
    else                            prep_w(W2, HDIM, w2h, w2l);
}

// ---------------- per-block exclusive scan (level 1) ----------------
__global__ void k_scan_block(const int* __restrict__ deg, int* __restrict__ partial,
                             int* __restrict__ blocksum, int n) {
    __shared__ int sm[2][SCANW];
    int t = threadIdx.x;
    int g = blockIdx.x * SCANW + t;
    int v = (g < n) ? deg[g] : 0;
    sm[0][t] = v;
    __syncthreads();
    int cur = 0;
#pragma unroll
    for (int off = 1; off < SCANW; off <<= 1) {
        int x = sm[cur][t];
        if (t >= off) x += sm[cur][t - off];
        sm[cur ^ 1][t] = x;
        __syncthreads();
        cur ^= 1;
    }
    int inc = sm[cur][t];
    partial[g] = inc - v;
    if (t == SCANW - 1) blocksum[blockIdx.x] = inc;
}

// Level-2 prefix computed in-block (<=128 scan blocks). All threads call it.
__device__ __forceinline__ void block_prefix(const int* __restrict__ bsum, int B,
                                             int* __restrict__ sbp) {
    __shared__ int tmp[128];
    int t = threadIdx.x;
    int v = 0;
    if (t < 128) { v = (t < B) ? bsum[t] : 0; tmp[t] = v; }
    __syncthreads();
#pragma unroll
    for (int off = 1; off < 128; off <<= 1) {
        int x = 0;
        if (t < 128) { x = tmp[t]; if (t >= off) x += tmp[t - off]; }
        __syncthreads();
        if (t < 128) tmp[t] = x;
        __syncthreads();
    }
    if (t < 128) sbp[t] = tmp[t] - v;   // exclusive
    __syncthreads();
}

// ---------------- CSR fill (also publishes the level-2 prefix) --------------
__global__ void __launch_bounds__(256)
k_fill(const int* __restrict__ src, const int* __restrict__ dst,
       const int* __restrict__ deg, const int* __restrict__ partial,
       const int* __restrict__ bsum, int B, int* __restrict__ bpref_g,
       int* __restrict__ cnt2, int2* __restrict__ csr, int e) {
    __shared__ int sbp[128];
    block_prefix(bsum, B, sbp);
    if (blockIdx.x == 0 && threadIdx.x < 128) bpref_g[threadIdx.x] = sbp[threadIdx.x];
    int i = blockIdx.x * blockDim.x + threadIdx.x;
    if (i >= e) return;
    int s = src[i];
    int d = dst[i];
    float dvs = rsqrtf((float)(deg[s] + 1));
    int pos = partial[d] + sbp[d >> 10] + atomicAdd(&cnt2[d], 1);
    csr[pos] = make_int2(s, __float_as_int(dvs));
}

// ---------------- gather aggregation: warp per dst node (R3-proven) ---------
// out[v] = dinv[v] * ( sum_{s in N(v)} dinv[s]*feat[s] + dinv[v]*feat[v] )
__global__ void __launch_bounds__(256)
k_agg64(const float* __restrict__ feat, const int* __restrict__ deg,
        const int2* __restrict__ csr, const int* __restrict__ partial,
        const int* __restrict__ bpref, float* __restrict__ out, int n) {
    int w = (blockIdx.x * blockDim.x + threadIdx.x) >> 5;
    if (w >= n) return;
    int lane = threadIdx.x & 31;
    int r0 = partial[w] + bpref[w >> 10];
    int r1 = partial[w + 1] + bpref[(w + 1) >> 10];
    float dv = rsqrtf((float)(deg[w] + 1));

    float2 acc = reinterpret_cast<const float2*>(feat)[(size_t)w * 32 + lane];
    acc.x *= dv; acc.y *= dv;

    int r = r0;
    for (; r + 4 <= r1; r += 4) {
        int2 e0 = csr[r], e1 = csr[r + 1], e2 = csr[r + 2], e3 = csr[r + 3];
        float2 v0 = reinterpret_cast<const float2*>(feat)[(size_t)e0.x * 32 + lane];
        float2 v1 = reinterpret_cast<const float2*>(feat)[(size_t)e1.x * 32 + lane];
        float2 v2 = reinterpret_cast<const float2*>(feat)[(size_t)e2.x * 32 + lane];
        float2 v3 = reinterpret_cast<const float2*>(feat)[(size_t)e3.x * 32 + lane];
        float w0 = __int_as_float(e0.y), w1 = __int_as_float(e1.y);
        float w2 = __int_as_float(e2.y), w3 = __int_as_float(e3.y);
        acc.x = fmaf(w0, v0.x, acc.x); acc.y = fmaf(w0, v0.y, acc.y);
        acc.x = fmaf(w1, v1.x, acc.x); acc.y = fmaf(w1, v1.y, acc.y);
        acc.x = fmaf(w2, v2.x, acc.x); acc.y = fmaf(w2, v2.y, acc.y);
        acc.x = fmaf(w3, v3.x, acc.x); acc.y = fmaf(w3, v3.y, acc.y);
    }
    for (; r < r1; r++) {
        int2 e0 = csr[r];
        float2 v0 = reinterpret_cast<const float2*>(feat)[(size_t)e0.x * 32 + lane];
        float w0 = __int_as_float(e0.y);
        acc.x = fmaf(w0, v0.x, acc.x); acc.y = fmaf(w0, v0.y, acc.y);
    }
    acc.x *= dv; acc.y *= dv;
    reinterpret_cast<float2*>(out)[(size_t)w * 32 + lane] = acc;
}

__global__ void __launch_bounds__(256)
k_agg128(const float* __restrict__ feat, const int* __restrict__ deg,
         const int2* __restrict__ csr, const int* __restrict__ partial,
         const int* __restrict__ bpref, float* __restrict__ out, int n) {
    int w = (blockIdx.x * blockDim.x + threadIdx.x) >> 5;
    if (w >= n) return;
    int lane = threadIdx.x & 31;
    int r0 = partial[w] + bpref[w >> 10];
    int r1 = partial[w + 1] + bpref[(w + 1) >> 10];
    float dv = rsqrtf((float)(deg[w] + 1));

    float4 acc = reinterpret_cast<const float4*>(feat)[(size_t)w * 32 + lane];
    acc.x *= dv; acc.y *= dv; acc.z *= dv; acc.w *= dv;

    int r = r0;
    for (; r + 4 <= r1; r += 4) {
        int2 e0 = csr[r], e1 = csr[r + 1], e2 = csr[r + 2], e3 = csr[r + 3];
        float4 v0 = reinterpret_cast<const float4*>(feat)[(size_t)e0.x * 32 + lane];
        float4 v1 = reinterpret_cast<const float4*>(feat)[(size_t)e1.x * 32 + lane];
        float4 v2 = reinterpret_cast<const float4*>(feat)[(size_t)e2.x * 32 + lane];
        float4 v3 = reinterpret_cast<const float4*>(feat)[(size_t)e3.x * 32 + lane];
        float w0 = __int_as_float(e0.y), w1 = __int_as_float(e1.y);
        float w2 = __int_as_float(e2.y), w3 = __int_as_float(e3.y);
        acc.x = fmaf(w0, v0.x, acc.x); acc.y = fmaf(w0, v0.y, acc.y);
        acc.z = fmaf(w0, v0.z, acc.z); acc.w = fmaf(w0, v0.w, acc.w);
        acc.x = fmaf(w1, v1.x, acc.x); acc.y = fmaf(w1, v1.y, acc.y);
        acc.z = fmaf(w1, v1.z, acc.z); acc.w = fmaf(w1, v1.w, acc.w);
        acc.x = fmaf(w2, v2.x, acc.x); acc.y = fmaf(w2, v2.y, acc.y);
        acc.z = fmaf(w2, v2.z, acc.z); acc.w = fmaf(w2, v2.w, acc.w);
        acc.x = fmaf(w3, v3.x, acc.x); acc.y = fmaf(w3, v3.y, acc.y);
        acc.z = fmaf(w3, v3.z, acc.z); acc.w = fmaf(w3, v3.w, acc.w);
    }
    for (; r < r1; r++) {
        int2 e0 = csr[r];
        float4 v0 = reinterpret_cast<const float4*>(feat)[(size_t)e0.x * 32 + lane];
        float w0 = __int_as_float(e0.y);
        acc.x = fmaf(w0, v0.x, acc.x); acc.y = fmaf(w0, v0.y, acc.y);
        acc.z = fmaf(w0, v0.z, acc.z); acc.w = fmaf(w0, v0.w, acc.w);
    }
    acc.x *= dv; acc.y *= dv; acc.z *= dv; acc.w *= dv;
    reinterpret_cast<float4*>(out)[(size_t)w * 32 + lane] = acc;
}

// ---------------- standalone tensor GEMM + bias + LN (+ReLU) ----------------
// X loaded fp32 from global, split to bf16 hi/lo smem tiles; bf16 3-split
// mma.sync (D = AhWh + AhWl + AlWh, fp32 acc); LN epilogue (R10-proven).
template <int K, bool RELU>
__global__ void __launch_bounds__(256)
k_mma_ln(const float* __restrict__ in,
         const ushort_t* __restrict__ gWh, const ushort_t* __restrict__ gWl,
         const float* __restrict__ bias, const float* __restrict__ gamma,
         const float* __restrict__ beta, float* __restrict__ out, int n) {
    constexpr int XSTR   = K + 8;                 // ushorts per X row (pad)
    constexpr int NCH    = K / 32;                // W chunks
    constexpr int XBYTES = 32 * XSTR * 2;         // one X split
    constexpr int WBYTES = 128 * 40 * 2;          // one W chunk split

    __shared__ __align__(16) unsigned char sbuf[2 * XBYTES + 2 * WBYTES];
    ushort_t* sXh = (ushort_t*)sbuf;
    ushort_t* sXl = (ushort_t*)(sbuf + XBYTES);
    ushort_t* sWh = (ushort_t*)(sbuf + 2 * XBYTES);
    ushort_t* sWl = (ushort_t*)(sbuf + 2 * XBYTES + WBYTES);
    float (*sOut)[132] = (float (*)[132])sbuf;    // aliases tiles after mma

    const int tid  = threadIdx.x;
    const int warp = tid >> 5;
    const int lane = tid & 31;
    const int row0 = blockIdx.x * 32;             // n divisible by 32

    // ---------------- load X fp32, split to bf16 hi/lo tiles ----------------
    constexpr int NF4 = 32 * K / 4;
#pragma unroll
    for (int idx = tid; idx < NF4; idx += 256) {
        int row = idx / (K / 4);
        int c4  = idx % (K / 4);
        float4 v = reinterpret_cast<const float4*>(in + (size_t)(row0 + row) * K)[c4];
        __nv_bfloat162 hp0 = __floats2bfloat162_rn(v.x, v.y);
        __nv_bfloat162 hp1 = __floats2bfloat162_rn(v.z, v.w);
        float2 hf0 = __bfloat1622float2(hp0);
        float2 hf1 = __bfloat1622float2(hp1);
        __nv_bfloat162 lp0 = __floats2bfloat162_rn(v.x - hf0.x, v.y - hf0.y);
        __nv_bfloat162 lp1 = __floats2bfloat162_rn(v.z - hf1.x, v.w - hf1.y);
        uint2 hu = make_uint2(*reinterpret_cast<uint32_t*>(&hp0),
                              *reinterpret_cast<uint32_t*>(&hp1));
        uint2 lu = make_uint2(*reinterpret_cast<uint32_t*>(&lp0),
                              *reinterpret_cast<uint32_t*>(&lp1));
        *reinterpret_cast<uint2*>(sXh + row * XSTR + c4 * 4) = hu;
        *reinterpret_cast<uint2*>(sXl + row * XSTR + c4 * 4) = lu;
    }

    // ---------------- bf16 3-split mma ----------------
    const int rt = warp & 1;                       // row-tile (16 rows)
    const int nb = (warp >> 1) << 5;               // n base (32 cols)
    const int a_row = rt * 16 + (lane & 7) + ((lane >> 3) & 1) * 8;
    const int a_k   = (lane >> 4) * 8;
    const uint32_t aH = smem_u32(sXh) + (uint32_t)(a_row * XSTR + a_k) * 2;
    const uint32_t aL = smem_u32(sXl) + (uint32_t)(a_row * XSTR + a_k) * 2;
    const int b_n = (lane & 7) + ((lane >> 4) & 1) * 8;
    const int b_k = ((lane >> 3) & 1) * 8;
    const uint32_t bH0 = smem_u32(sWh) + (uint32_t)((nb + b_n) * 40 + b_k) * 2;
    const uint32_t bL0 = smem_u32(sWl) + (uint32_t)((nb + b_n) * 40 + b_k) * 2;
    const uint32_t bH1 = bH0 + 16 * 40 * 2;
    const uint32_t bL1 = bL0 + 16 * 40 * 2;

    float acc[4][4];
#pragma unroll
    for (int t = 0; t < 4; t++)
#pragma unroll
        for (int c = 0; c < 4; c++) acc[t][c] = 0.0f;

#pragma unroll
    for (int c = 0; c < NCH; c++) {
        // stage W chunk c (hi+lo = 1280 uint4)
        {
            const uint4* srcH = reinterpret_cast<const uint4*>(gWh + c * 5120);
            const uint4* srcL = reinterpret_cast<const uint4*>(gWl + c * 5120);
            uint4* dH = reinterpret_cast<uint4*>(sWh);
            uint4* dL = reinterpret_cast<uint4*>(sWl);
#pragma unroll
            for (int i = tid; i < 640; i += 256) { dH[i] = srcH[i]; dL[i] = srcL[i]; }
        }
        __syncthreads();   // covers X stores (iter 0) + W chunk visibility

#pragma unroll
        for (int ks = 0; ks < 2; ks++) {
            const uint32_t ko = (uint32_t)(c * 32 + ks * 16) * 2;
            const uint32_t kc = (uint32_t)(ks * 16) * 2;
            uint32_t ah0, ah1, ah2, ah3, al0, al1, al2, al3;
            uint32_t bh0, bh1, bh2, bh3, bh4, bh5, bh6, bh7;
            uint32_t bl0, bl1, bl2, bl3, bl4, bl5, bl6, bl7;
            LDSM4(ah0, ah1, ah2, ah3, aH + ko);
            LDSM4(al0, al1, al2, al3, aL + ko);
            LDSM4(bh0, bh1, bh2, bh3, bH0 + kc);
            LDSM4(bh4, bh5, bh6, bh7, bH1 + kc);
            LDSM4(bl0, bl1, bl2, bl3, bL0 + kc);
            LDSM4(bl4, bl5, bl6, bl7, bL1 + kc);
            MMA_BF16(acc[0], ah0, ah1, ah2, ah3, bh0, bh1);
            MMA_BF16(acc[0], ah0, ah1, ah2, ah3, bl0, bl1);
            MMA_BF16(acc[0], al0, al1, al2, al3, bh0, bh1);
            MMA_BF16(acc[1], ah0, ah1, ah2, ah3, bh2, bh3);
            MMA_BF16(acc[1], ah0, ah1, ah2, ah3, bl2, bl3);
            MMA_BF16(acc[1], al0, al1, al2, al3, bh2, bh3);
            MMA_BF16(acc[2], ah0, ah1, ah2, ah3, bh4, bh5);
            MMA_BF16(acc[2], ah0, ah1, ah2, ah3, bl4, bl5);
            MMA_BF16(acc[2], al0, al1, al2, al3, bh4, bh5);
            MMA_BF16(acc[3], ah0, ah1, ah2, ah3, bh6, bh7);
            MMA_BF16(acc[3], ah0, ah1, ah2, ah3, bl6, bl7);
            MMA_BF16(acc[3], al0, al1, al2, al3, bh6, bh7);
        }
        __syncthreads();   // W chunk reuse / final: tiles free for sOut
    }

    // scatter fragments to sOut (aliases tiles; safe after final sync)
    {
        const int g  = lane >> 2;
        const int cx = 2 * (lane & 3);
#pragma unroll
        for (int t = 0; t < 4; t++) {
            const int col = nb + 8 * t + cx;
            *reinterpret_cast<float2*>(&sOut[rt * 16 + g][col]) =
                make_float2(acc[t][0], acc[t][1]);
            *reinterpret_cast<float2*>(&sOut[rt * 16 + g + 8][col]) =
                make_float2(acc[t][2], acc[t][3]);
        }
    }
    __syncthreads();

    // ---------------- LN epilogue (proven) ----------------
    const float4 bv = reinterpret_cast<const float4*>(bias)[lane];
    const float4 gv = reinterpret_cast<const float4*>(gamma)[lane];
    const float4 be = reinterpret_cast<const float4*>(beta)[lane];

#pragma unroll
    for (int r = 0; r < 4; r++) {
        float4 v = *reinterpret_cast<float4*>(&sOut[warp * 4 + r][lane * 4]);
        float hx = v.x + bv.x;
        float hy = v.y + bv.y;
        float hz = v.z + bv.z;
        float hw = v.w + bv.w;
        float s = hx + hy + hz + hw;
#pragma unroll
        for (int o = 16; o > 0; o >>= 1) s += __shfl_xor_sync(0xffffffffu, s, o);
        float mu = s * (1.0f / 128.0f);
        float dx = hx - mu, dy = hy - mu, dz = hz - mu, dw = hw - mu;
        float q = dx * dx + dy * dy + dz * dz + dw * dw;
#pragma unroll
        for (int o = 16; o > 0; o >>= 1) q += __shfl_xor_sync(0xffffffffu, q, o);
        float rstd = rsqrtf(q * (1.0f / 128.0f) + LN_EPS);

        float4 o4;
        o4.x = dx * rstd * gv.x + be.x;
        o4.y = dy * rstd * gv.y + be.y;
        o4.z = dz * rstd * gv.z + be.z;
        o4.w = dw * rstd * gv.w + be.w;
        if (RELU) {
            o4.x = fmaxf(o4.x, 0.0f);
            o4.y = fmaxf(o4.y, 0.0f);
            o4.z = fmaxf(o4.z, 0.0f);
            o4.w = fmaxf(o4.w, 0.0f);
        }
        int row = row0 + warp * 4 + r;
        reinterpret_cast<float4*>(out + (size_t)row * 128)[lane] = o4;
    }
}

// ---------------- pooling (batch is sorted; count fused) ----------------
__global__ void k_pool_sum(const float* __restrict__ h, const int* __restrict__ batch,
                           float* __restrict__ gsum, int* __restrict__ gcnt, int n, int rpb) {
    int c  = threadIdx.x;
    int r0 = blockIdx.x * rpb;
    int r1 = min(r0 + rpb, n);
    if (r0 >= r1) return;
    float acc = 0.0f;
    int cnt = 0;
    int cur = batch[r0];
    for (int r = r0; r < r1; r++) {
        int g = batch[r];
        if (g != cur) {
            atomicAdd(&gsum[cur * HDIM + c], acc);
            if (c == 0) atomicAdd(&gcnt[cur], cnt);
            acc = 0.0f; cnt = 0; cur = g;
        }
        acc += h[(size_t)r * HDIM + c];
        cnt++;
    }
    atomicAdd(&gsum[cur * HDIM + c], acc);
    if (c == 0) atomicAdd(&gcnt[cur], cnt);
}

__global__ void k_finalize(const float* __restrict__ gsum, const int* __restrict__ gcnt,
                           float* __restrict__ out) {
    int i = blockIdx.x * blockDim.x + threadIdx.x;
    if (i >= NGRAPH * HDIM) return;
    float cnt = fmaxf((float)gcnt[i >> 7], 1.0f);
    out[i] = gsum[i] / cnt;
}

// ---------------- launch ----------------
extern "C" void kernel_launch(void* const* d_in, const int* in_sizes, int n_in,
                              void* d_out, int out_size) {
    const float* x     = (const float*)d_in[0];
    const int*   eidx  = (const int*)d_in[1];
    const int*   batch = (const int*)d_in[2];
    const float* W1 = (const float*)d_in[3];
    const float* b1 = (const float*)d_in[4];
    const float* g1 = (const float*)d_in[5];
    const float* be1 = (const float*)d_in[6];
    const float* W2 = (const float*)d_in[7];
    const float* b2 = (const float*)d_in[8];
    const float* g2 = (const float*)d_in[9];
    const float* be2 = (const float*)d_in[10];

    const int n = in_sizes[0] / FDIM;   // 100000
    const int e = in_sizes[1] / 2;      // 1600000
    const int* src = eidx;
    const int* dst = eidx + e;

    int*      ibuf;  cudaGetSymbolAddress((void**)&ibuf,  g_ibuf);
    int*      part;  cudaGetSymbolAddress((void**)&part,  g_partial);
    int*      bsum;  cudaGetSymbolAddress((void**)&bsum,  g_blocksum);
    int*      bpref; cudaGetSymbolAddress((void**)&bpref, g_blockpref);
    int2*     csr;   cudaGetSymbolAddress((void**)&csr,   g_csr);
    float*    bufa;  cudaGetSymbolAddress((void**)&bufa,  g_bufa);
    float*    bufb;  cudaGetSymbolAddress((void**)&bufb,  g_bufb);
    float*    pool;  cudaGetSymbolAddress((void**)&pool,  g_pool);
    ushort_t *w1h, *w1l, *w2h, *w2l;
    cudaGetSymbolAddress((void**)&w1h, g_w1h);
    cudaGetSymbolAddress((void**)&w1l, g_w1l);
    cudaGetSymbolAddress((void**)&w2h, g_w2h);
    cudaGetSymbolAddress((void**)&w2l, g_w2l);

    int* deg  = ibuf;
    int* cnt2 = ibuf + NPARTIAL;
    float* gsum = pool;
    int*   gcnt = (int*)(pool + NGRAPH * HDIM);

    const int T = 256;
    auto cdiv = [](int a, int b) { return (a + b - 1) / b; };
    const int B  = cdiv(n + 1, SCANW);
    const int nb = cdiv(e, T);

    cudaMemsetAsync(ibuf, 0, sizeof(int) * (NPARTIAL + NNODES));
    cudaMemsetAsync(pool, 0, sizeof(float) * (NGRAPH * HDIM) + sizeof(int) * NGRAPH);

    // CSR build (+W split prep in tail blocks of launch 1)
    k_count_prep<<<nb + 2, T>>>(dst, deg, e, nb, W1, W2, w1h, w1l, w2h, w2l);      // 1
    k_scan_block<<<B, SCANW>>>(deg, part, bsum, n);                                // 2
    k_fill<<<cdiv(e, T), T>>>(src, dst, deg, part, bsum, B, bpref, cnt2, csr, e);  // 3

    // conv1: gather (high occupancy) then tensor GEMM+LN+ReLU
    k_agg64<<<cdiv(n * 32, T), T>>>(x, deg, csr, part, bpref, bufa, n);            // 4 <- profiled
    k_mma_ln<FDIM, true><<<n / 32, T>>>(bufa, w1h, w1l, b1, g1, be1, bufb, n);     // 5

    // conv2: gather then tensor GEMM+LN
    k_agg128<<<cdiv(n * 32, T), T>>>(bufb, deg, csr, part, bpref, bufa, n);        // 6
    k_mma_ln<HDIM, false><<<n / 32, T>>>(bufa, w2h, w2l, b2, g2, be2, bufb, n);    // 7

    // mean pool per graph (batch is sorted)
    const int rpb = 128;
    k_pool_sum<<<cdiv(n, rpb), HDIM>>>(bufb, batch, gsum, gcnt, n, rpb);           // 8
    k_finalize<<<cdiv(NGRAPH * HDIM, HDIM), HDIM>>>(gsum, gcnt, (float*)d_out);    // 9
}

// round 12
// speedup vs baseline: 1.2240x; 1.0657x over previous
#include <cuda_runtime.h>
#include <cuda_bf16.h>
#include <cstdint>

// Problem constants (shapes fixed by the dataset)
#define NNODES 100000
#define NEDGES 1600000
#define NGRAPH 128
#define HDIM   128
#define FDIM   64
#define LN_EPS 1e-5f

#define SCANW   1024
#define NSCANBLK ((NNODES + SCANW) / SCANW + 1)
#define NPARTIAL (NSCANBLK * SCANW)

typedef unsigned short ushort_t;

// ---------------- mma / ldmatrix (Ampere-path HMMA, legal on plain sm_100) --
#define LDSM4(r0, r1, r2, r3, addr) \
    asm volatile("ldmatrix.sync.aligned.m8n8.x4.shared.b16 {%0,%1,%2,%3}, [%4];" \
                 : "=r"(r0), "=r"(r1), "=r"(r2), "=r"(r3) : "r"(addr))

#define MMA_BF16(d, a0, a1, a2, a3, b0, b1) \
    asm volatile("mma.sync.aligned.m16n8k16.row.col.f32.bf16.bf16.f32 " \
                 "{%0,%1,%2,%3}, {%4,%5,%6,%7}, {%8,%9}, {%0,%1,%2,%3};" \
                 : "+f"(d[0]), "+f"(d[1]), "+f"(d[2]), "+f"(d[3]) \
                 : "r"(a0), "r"(a1), "r"(a2), "r"(a3), "r"(b0), "r"(b1))

__device__ __forceinline__ uint32_t smem_u32(const void* p) {
    uint32_t a;
    asm("{ .reg .u64 t; cvta.to.shared.u64 t, %1; cvt.u32.u64 %0, t; }" : "=r"(a) : "l"(p));
    return a;
}

// ---------------- scratch (device globals; no allocations allowed) ----------
__device__ int      g_ibuf[NPARTIAL + NNODES];      // deg + fill cursors (one memset)
__device__ int      g_partial[NPARTIAL];
__device__ int      g_blocksum[256];
__device__ int      g_blockpref[128];
__device__ int2     g_csr[NEDGES];                  // (src, bits(dinv[src]))
__device__ ushort_t g_xbf[(size_t)NNODES * FDIM];   // x in bf16 (gather operand)
__device__ float    g_bufa[(size_t)NNODES * HDIM];
__device__ float    g_bufb[(size_t)NNODES * HDIM];  // h1 as bf16 / h2 as fp32
__device__ float    g_pool[NGRAPH * HDIM + NGRAPH];
// W split images, chunk-major [chunk][n=128][40 k-slots] (k pad 32..39 zeroed)
__device__ ushort_t g_w1h[2 * 128 * 40], g_w1l[2 * 128 * 40];
__device__ ushort_t g_w2h[4 * 128 * 40], g_w2l[4 * 128 * 40];

// ---------------- degree count + W split + x->bf16 (fused) ----------------
__device__ __forceinline__ void prep_w(const float* __restrict__ W, int K,
                                       ushort_t* __restrict__ wh, ushort_t* __restrict__ wl) {
    for (int idx = threadIdx.x; idx < K * 128; idx += 256) {
        int k = idx >> 7, nn = idx & 127;
        float v = W[idx];
        __nv_bfloat16 h = __float2bfloat16(v);
        __nv_bfloat16 l = __float2bfloat16(v - __bfloat162float(h));
        int off = (((k >> 5) * 128 + nn) * 40) + (k & 31);
        wh[off] = __bfloat16_as_ushort(h);
        wl[off] = __bfloat16_as_ushort(l);
    }
    for (int idx = threadIdx.x; idx < (K / 32) * 128 * 8; idx += 256) {
        int cn = idx >> 3;
        int off = cn * 40 + 32 + (idx & 7);
        wh[off] = 0; wl[off] = 0;
    }
}

__global__ void __launch_bounds__(256)
k_count_prep(const int* __restrict__ dst, int* __restrict__ deg, int e, int nb,
             const float* __restrict__ W1, const float* __restrict__ W2,
             ushort_t* w1h, ushort_t* w1l, ushort_t* w2h, ushort_t* w2l,
             const float* __restrict__ x, ushort_t* __restrict__ xbf, int nx4) {
    if ((int)blockIdx.x < nb) {
        int i = blockIdx.x * 256 + threadIdx.x;
        if (i < e) atomicAdd(&deg[dst[i]], 1);
        return;
    }
    if (blockIdx.x == (unsigned)nb)     { prep_w(W1, FDIM, w1h, w1l); return; }
    if (blockIdx.x == (unsigned)(nb + 1)) { prep_w(W2, HDIM, w2h, w2l); return; }
    // x -> bf16 (one float4 per thread)
    int idx = (blockIdx.x - nb - 2) * 256 + threadIdx.x;
    if (idx < nx4) {
        float4 v = reinterpret_cast<const float4*>(x)[idx];
        __nv_bfloat162 p0 = __floats2bfloat162_rn(v.x, v.y);
        __nv_bfloat162 p1 = __floats2bfloat162_rn(v.z, v.w);
        uint2 u = make_uint2(*reinterpret_cast<uint32_t*>(&p0),
                             *reinterpret_cast<uint32_t*>(&p1));
        reinterpret_cast<uint2*>(xbf)[idx] = u;
    }
}

// ---------------- per-block exclusive scan (level 1) ----------------
__global__ void k_scan_block(const int* __restrict__ deg, int* __restrict__ partial,
                             int* __restrict__ blocksum, int n) {
    __shared__ int sm[2][SCANW];
    int t = threadIdx.x;
    int g = blockIdx.x * SCANW + t;
    int v = (g < n) ? deg[g] : 0;
    sm[0][t] = v;
    __syncthreads();
    int cur = 0;
#pragma unroll
    for (int off = 1; off < SCANW; off <<= 1) {
        int x = sm[cur][t];
        if (t >= off) x += sm[cur][t - off];
        sm[cur ^ 1][t] = x;
        __syncthreads();
        cur ^= 1;
    }
    int inc = sm[cur][t];
    partial[g] = inc - v;
    if (t == SCANW - 1) blocksum[blockIdx.x] = inc;
}

// Level-2 prefix computed in-block (<=128 scan blocks). All threads call it.
__device__ __forceinline__ void block_prefix(const int* __restrict__ bsum, int B,
                                             int* __restrict__ sbp) {
    __shared__ int tmp[128];
    int t = threadIdx.x;
    int v = 0;
    if (t < 128) { v = (t < B) ? bsum[t] : 0; tmp[t] = v; }
    __syncthreads();
#pragma unroll
    for (int off = 1; off < 128; off <<= 1) {
        int x = 0;
        if (t < 128) { x = tmp[t]; if (t >= off) x += tmp[t - off]; }
        __syncthreads();
        if (t < 128) tmp[t] = x;
        __syncthreads();
    }
    if (t < 128) sbp[t] = tmp[t] - v;   // exclusive
    __syncthreads();
}

// ---------------- CSR fill (also publishes the level-2 prefix) --------------
__global__ void __launch_bounds__(256)
k_fill(const int* __restrict__ src, const int* __restrict__ dst,
       const int* __restrict__ deg, const int* __restrict__ partial,
       const int* __restrict__ bsum, int B, int* __restrict__ bpref_g,
       int* __restrict__ cnt2, int2* __restrict__ csr, int e) {
    __shared__ int sbp[128];
    block_prefix(bsum, B, sbp);
    if (blockIdx.x == 0 && threadIdx.x < 128) bpref_g[threadIdx.x] = sbp[threadIdx.x];
    int i = blockIdx.x * blockDim.x + threadIdx.x;
    if (i >= e) return;
    int s = src[i];
    int d = dst[i];
    float dvs = rsqrtf((float)(deg[s] + 1));
    int pos = partial[d] + sbp[d >> 10] + atomicAdd(&cnt2[d], 1);
    csr[pos] = make_int2(s, __float_as_int(dvs));
}

// ---------------- gather aggregation: warp per dst node, bf16 operands ------
// out[v] = dinv[v] * ( sum_{s in N(v)} dinv[s]*feat[s] + dinv[v]*feat[v] )
__global__ void __launch_bounds__(256)
k_agg64(const ushort_t* __restrict__ featbf, const int* __restrict__ deg,
        const int2* __restrict__ csr, const int* __restrict__ partial,
        const int* __restrict__ bpref, float* __restrict__ out, int n) {
    int w = (blockIdx.x * blockDim.x + threadIdx.x) >> 5;
    if (w >= n) return;
    int lane = threadIdx.x & 31;
    int r0 = partial[w] + bpref[w >> 10];
    int r1 = partial[w + 1] + bpref[(w + 1) >> 10];
    float dv = rsqrtf((float)(deg[w] + 1));

    const uint32_t* f32v = reinterpret_cast<const uint32_t*>(featbf);
    uint32_t su = f32v[(size_t)w * 32 + lane];
    float2 acc = __bfloat1622float2(*reinterpret_cast<__nv_bfloat162*>(&su));
    acc.x *= dv; acc.y *= dv;

    int r = r0;
    for (; r + 4 <= r1; r += 4) {
        int2 e0 = csr[r], e1 = csr[r + 1], e2 = csr[r + 2], e3 = csr[r + 3];
        uint32_t u0 = f32v[(size_t)e0.x * 32 + lane];
        uint32_t u1 = f32v[(size_t)e1.x * 32 + lane];
        uint32_t u2 = f32v[(size_t)e2.x * 32 + lane];
        uint32_t u3 = f32v[(size_t)e3.x * 32 + lane];
        float2 v0 = __bfloat1622float2(*reinterpret_cast<__nv_bfloat162*>(&u0));
        float2 v1 = __bfloat1622float2(*reinterpret_cast<__nv_bfloat162*>(&u1));
        float2 v2 = __bfloat1622float2(*reinterpret_cast<__nv_bfloat162*>(&u2));
        float2 v3 = __bfloat1622float2(*reinterpret_cast<__nv_bfloat162*>(&u3));
        float w0 = __int_as_float(e0.y), w1 = __int_as_float(e1.y);
        float w2 = __int_as_float(e2.y), w3 = __int_as_float(e3.y);
        acc.x = fmaf(w0, v0.x, acc.x); acc.y = fmaf(w0, v0.y, acc.y);
        acc.x = fmaf(w1, v1.x, acc.x); acc.y = fmaf(w1, v1.y, acc.y);
        acc.x = fmaf(w2, v2.x, acc.x); acc.y = fmaf(w2, v2.y, acc.y);
        acc.x = fmaf(w3, v3.x, acc.x); acc.y = fmaf(w3, v3.y, acc.y);
    }
    for (; r < r1; r++) {
        int2 e0 = csr[r];
        uint32_t u0 = f32v[(size_t)e0.x * 32 + lane];
        float2 v0 = __bfloat1622float2(*reinterpret_cast<__nv_bfloat162*>(&u0));
        float w0 = __int_as_float(e0.y);
        acc.x = fmaf(w0, v0.x, acc.x); acc.y = fmaf(w0, v0.y, acc.y);
    }
    acc.x *= dv; acc.y *= dv;
    reinterpret_cast<float2*>(out)[(size_t)w * 32 + lane] = acc;
}

__device__ __forceinline__ void bf4_unpack(uint2 u, float4& o) {
    float2 a = __bfloat1622float2(*reinterpret_cast<__nv_bfloat162*>(&u.x));
    float2 b = __bfloat1622float2(*reinterpret_cast<__nv_bfloat162*>(&u.y));
    o.x = a.x; o.y = a.y; o.z = b.x; o.w = b.y;
}

__global__ void __launch_bounds__(256)
k_agg128(const ushort_t* __restrict__ featbf, const int* __restrict__ deg,
         const int2* __restrict__ csr, const int* __restrict__ partial,
         const int* __restrict__ bpref, float* __restrict__ out, int n) {
    int w = (blockIdx.x * blockDim.x + threadIdx.x) >> 5;
    if (w >= n) return;
    int lane = threadIdx.x & 31;
    int r0 = partial[w] + bpref[w >> 10];
    int r1 = partial[w + 1] + bpref[(w + 1) >> 10];
    float dv = rsqrtf((float)(deg[w] + 1));

    const uint2* f64v = reinterpret_cast<const uint2*>(featbf);
    float4 acc;
    bf4_unpack(f64v[(size_t)w * 32 + lane], acc);
    acc.x *= dv; acc.y *= dv; acc.z *= dv; acc.w *= dv;

    int r = r0;
    for (; r + 4 <= r1; r += 4) {
        int2 e0 = csr[r], e1 = csr[r + 1], e2 = csr[r + 2], e3 = csr[r + 3];
        uint2 u0 = f64v[(size_t)e0.x * 32 + lane];
        uint2 u1 = f64v[(size_t)e1.x * 32 + lane];
        uint2 u2 = f64v[(size_t)e2.x * 32 + lane];
        uint2 u3 = f64v[(size_t)e3.x * 32 + lane];
        float4 v0, v1, v2, v3;
        bf4_unpack(u0, v0); bf4_unpack(u1, v1); bf4_unpack(u2, v2); bf4_unpack(u3, v3);
        float w0 = __int_as_float(e0.y), w1 = __int_as_float(e1.y);
        float w2 = __int_as_float(e2.y), w3 = __int_as_float(e3.y);
        acc.x = fmaf(w0, v0.x, acc.x); acc.y = fmaf(w0, v0.y, acc.y);
        acc.z = fmaf(w0, v0.z, acc.z); acc.w = fmaf(w0, v0.w, acc.w);
        acc.x = fmaf(w1, v1.x, acc.x); acc.y = fmaf(w1, v1.y, acc.y);
        acc.z = fmaf(w1, v1.z, acc.z); acc.w = fmaf(w1, v1.w, acc.w);
        acc.x = fmaf(w2, v2.x, acc.x); acc.y = fmaf(w2, v2.y, acc.y);
        acc.z = fmaf(w2, v2.z, acc.z); acc.w = fmaf(w2, v2.w, acc.w);
        acc.x = fmaf(w3, v3.x, acc.x); acc.y = fmaf(w3, v3.y, acc.y);
        acc.z = fmaf(w3, v3.z, acc.z); acc.w = fmaf(w3, v3.w, acc.w);
    }
    for (; r < r1; r++) {
        int2 e0 = csr[r];
        float4 v0;
        bf4_unpack(f64v[(size_t)e0.x * 32 + lane], v0);
        float w0 = __int_as_float(e0.y);
        acc.x = fmaf(w0, v0.x, acc.x); acc.y = fmaf(w0, v0.y, acc.y);
        acc.z = fmaf(w0, v0.z, acc.z); acc.w = fmaf(w0, v0.w, acc.w);
    }
    acc.x *= dv; acc.y *= dv; acc.z *= dv; acc.w *= dv;
    reinterpret_cast<float4*>(out)[(size_t)w * 32 + lane] = acc;
}

// ---------------- standalone tensor GEMM + bias + LN (+ReLU) ----------------
// X loaded fp32 from global, split to bf16 hi/lo smem tiles; bf16 3-split
// mma.sync (D = AhWh + AhWl + AlWh, fp32 acc); LN epilogue.
// OUT_BF16: emit bf16 rows (gather operand for the next conv).
template <int K, bool RELU, bool OUT_BF16>
__global__ void __launch_bounds__(256)
k_mma_ln(const float* __restrict__ in,
         const ushort_t* __restrict__ gWh, const ushort_t* __restrict__ gWl,
         const float* __restrict__ bias, const float* __restrict__ gamma,
         const float* __restrict__ beta, void* __restrict__ outv, int n) {
    constexpr int XSTR   = K + 8;                 // ushorts per X row (pad)
    constexpr int NCH    = K / 32;                // W chunks
    constexpr int XBYTES = 32 * XSTR * 2;         // one X split
    constexpr int WBYTES = 128 * 40 * 2;          // one W chunk split

    __shared__ __align__(16) unsigned char sbuf[2 * XBYTES + 2 * WBYTES];
    ushort_t* sXh = (ushort_t*)sbuf;
    ushort_t* sXl = (ushort_t*)(sbuf + XBYTES);
    ushort_t* sWh = (ushort_t*)(sbuf + 2 * XBYTES);
    ushort_t* sWl = (ushort_t*)(sbuf + 2 * XBYTES + WBYTES);
    float (*sOut)[132] = (float (*)[132])sbuf;    // aliases tiles after mma

    const int tid  = threadIdx.x;
    const int warp = tid >> 5;
    const int lane = tid & 31;
    const int row0 = blockIdx.x * 32;             // n divisible by 32

    // ---------------- load X fp32, split to bf16 hi/lo tiles ----------------
    constexpr int NF4 = 32 * K / 4;
#pragma unroll
    for (int idx = tid; idx < NF4; idx += 256) {
        int row = idx / (K / 4);
        int c4  = idx % (K / 4);
        float4 v = reinterpret_cast<const float4*>(in + (size_t)(row0 + row) * K)[c4];
        __nv_bfloat162 hp0 = __floats2bfloat162_rn(v.x, v.y);
        __nv_bfloat162 hp1 = __floats2bfloat162_rn(v.z, v.w);
        float2 hf0 = __bfloat1622float2(hp0);
        float2 hf1 = __bfloat1622float2(hp1);
        __nv_bfloat162 lp0 = __floats2bfloat162_rn(v.x - hf0.x, v.y - hf0.y);
        __nv_bfloat162 lp1 = __floats2bfloat162_rn(v.z - hf1.x, v.w - hf1.y);
        uint2 hu = make_uint2(*reinterpret_cast<uint32_t*>(&hp0),
                              *reinterpret_cast<uint32_t*>(&hp1));
        uint2 lu = make_uint2(*reinterpret_cast<uint32_t*>(&lp0),
                              *reinterpret_cast<uint32_t*>(&lp1));
        *reinterpret_cast<uint2*>(sXh + row * XSTR + c4 * 4) = hu;
        *reinterpret_cast<uint2*>(sXl + row * XSTR + c4 * 4) = lu;
    }

    // ---------------- bf16 3-split mma ----------------
    const int rt = warp & 1;                       // row-tile (16 rows)
    const int nb = (warp >> 1) << 5;               // n base (32 cols)
    const int a_row = rt * 16 + (lane & 7) + ((lane >> 3) & 1) * 8;
    const int a_k   = (lane >> 4) * 8;
    const uint32_t aH = smem_u32(sXh) + (uint32_t)(a_row * XSTR + a_k) * 2;
    const uint32_t aL = smem_u32(sXl) + (uint32_t)(a_row * XSTR + a_k) * 2;
    const int b_n = (lane & 7) + ((lane >> 4) & 1) * 8;
    const int b_k = ((lane >> 3) & 1) * 8;
    const uint32_t bH0 = smem_u32(sWh) + (uint32_t)((nb + b_n) * 40 + b_k) * 2;
    const uint32_t bL0 = smem_u32(sWl) + (uint32_t)((nb + b_n) * 40 + b_k) * 2;
    const uint32_t bH1 = bH0 + 16 * 40 * 2;
    const uint32_t bL1 = bL0 + 16 * 40 * 2;

    float acc[4][4];
#pragma unroll
    for (int t = 0; t < 4; t++)
#pragma unroll
        for (int c = 0; c < 4; c++) acc[t][c] = 0.0f;

#pragma unroll
    for (int c = 0; c < NCH; c++) {
        {
            const uint4* srcH = reinterpret_cast<const uint4*>(gWh + c * 5120);
            const uint4* srcL = reinterpret_cast<const uint4*>(gWl + c * 5120);
            uint4* dH = reinterpret_cast<uint4*>(sWh);
            uint4* dL = reinterpret_cast<uint4*>(sWl);
#pragma unroll
            for (int i = tid; i < 640; i += 256) { dH[i] = srcH[i]; dL[i] = srcL[i]; }
        }
        __syncthreads();

#pragma unroll
        for (int ks = 0; ks < 2; ks++) {
            const uint32_t ko = (uint32_t)(c * 32 + ks * 16) * 2;
            const uint32_t kc = (uint32_t)(ks * 16) * 2;
            uint32_t ah0, ah1, ah2, ah3, al0, al1, al2, al3;
            uint32_t bh0, bh1, bh2, bh3, bh4, bh5, bh6, bh7;
            uint32_t bl0, bl1, bl2, bl3, bl4, bl5, bl6, bl7;
            LDSM4(ah0, ah1, ah2, ah3, aH + ko);
            LDSM4(al0, al1, al2, al3, aL + ko);
            LDSM4(bh0, bh1, bh2, bh3, bH0 + kc);
            LDSM4(bh4, bh5, bh6, bh7, bH1 + kc);
            LDSM4(bl0, bl1, bl2, bl3, bL0 + kc);
            LDSM4(bl4, bl5, bl6, bl7, bL1 + kc);
            MMA_BF16(acc[0], ah0, ah1, ah2, ah3, bh0, bh1);
            MMA_BF16(acc[0], ah0, ah1, ah2, ah3, bl0, bl1);
            MMA_BF16(acc[0], al0, al1, al2, al3, bh0, bh1);
            MMA_BF16(acc[1], ah0, ah1, ah2, ah3, bh2, bh3);
            MMA_BF16(acc[1], ah0, ah1, ah2, ah3, bl2, bl3);
            MMA_BF16(acc[1], al0, al1, al2, al3, bh2, bh3);
            MMA_BF16(acc[2], ah0, ah1, ah2, ah3, bh4, bh5);
            MMA_BF16(acc[2], ah0, ah1, ah2, ah3, bl4, bl5);
            MMA_BF16(acc[2], al0, al1, al2, al3, bh4, bh5);
            MMA_BF16(acc[3], ah0, ah1, ah2, ah3, bh6, bh7);
            MMA_BF16(acc[3], ah0, ah1, ah2, ah3, bl6, bl7);
            MMA_BF16(acc[3], al0, al1, al2, al3, bh6, bh7);
        }
        __syncthreads();
    }

    // scatter fragments to sOut (aliases tiles; safe after final sync)
    {
        const int g  = lane >> 2;
        const int cx = 2 * (lane & 3);
#pragma unroll
        for (int t = 0; t < 4; t++) {
            const int col = nb + 8 * t + cx;
            *reinterpret_cast<float2*>(&sOut[rt * 16 + g][col]) =
                make_float2(acc[t][0], acc[t][1]);
            *reinterpret_cast<float2*>(&sOut[rt * 16 + g + 8][col]) =
                make_float2(acc[t][2], acc[t][3]);
        }
    }
    __syncthreads();

    // ---------------- LN epilogue ----------------
    const float4 bv = reinterpret_cast<const float4*>(bias)[lane];
    const float4 gv = reinterpret_cast<const float4*>(gamma)[lane];
    const float4 be = reinterpret_cast<const float4*>(beta)[lane];

#pragma unroll
    for (int r = 0; r < 4; r++) {
        float4 v = *reinterpret_cast<float4*>(&sOut[warp * 4 + r][lane * 4]);
        float hx = v.x + bv.x;
        float hy = v.y + bv.y;
        float hz = v.z + bv.z;
        float hw = v.w + bv.w;
        float s = hx + hy + hz + hw;
#pragma unroll
        for (int o = 16; o > 0; o >>= 1) s += __shfl_xor_sync(0xffffffffu, s, o);
        float mu = s * (1.0f / 128.0f);
        float dx = hx - mu, dy = hy - mu, dz = hz - mu, dw = hw - mu;
        float q = dx * dx + dy * dy + dz * dz + dw * dw;
#pragma unroll
        for (int o = 16; o > 0; o >>= 1) q += __shfl_xor_sync(0xffffffffu, q, o);
        float rstd = rsqrtf(q * (1.0f / 128.0f) + LN_EPS);

        float4 o4;
        o4.x = dx * rstd * gv.x + be.x;
        o4.y = dy * rstd * gv.y + be.y;
        o4.z = dz * rstd * gv.z + be.z;
        o4.w = dw * rstd * gv.w + be.w;
        if (RELU) {
            o4.x = fmaxf(o4.x, 0.0f);
            o4.y = fmaxf(o4.y, 0.0f);
            o4.z = fmaxf(o4.z, 0.0f);
            o4.w = fmaxf(o4.w, 0.0f);
        }
        int row = row0 + warp * 4 + r;
        if (OUT_BF16) {
            __nv_bfloat162 p0 = __floats2bfloat162_rn(o4.x, o4.y);
            __nv_bfloat162 p1 = __floats2bfloat162_rn(o4.z, o4.w);
            uint2 u = make_uint2(*reinterpret_cast<uint32_t*>(&p0),
                                 *reinterpret_cast<uint32_t*>(&p1));
            reinterpret_cast<uint2*>((ushort_t*)outv + (size_t)row * 128)[lane] = u;
        } else {
            reinterpret_cast<float4*>((float*)outv + (size_t)row * 128)[lane] = o4;
        }
    }
}

// ---------------- pooling (batch is sorted; count fused) ----------------
__global__ void k_pool_sum(const float* __restrict__ h, const int* __restrict__ batch,
                           float* __restrict__ gsum, int* __restrict__ gcnt, int n, int rpb) {
    int c  = threadIdx.x;
    int r0 = blockIdx.x * rpb;
    int r1 = min(r0 + rpb, n);
    if (r0 >= r1) return;
    float acc = 0.0f;
    int cnt = 0;
    int cur = batch[r0];
    for (int r = r0; r < r1; r++) {
        int g = batch[r];
        if (g != cur) {
            atomicAdd(&gsum[cur * HDIM + c], acc);
            if (c == 0) atomicAdd(&gcnt[cur], cnt);
            acc = 0.0f; cnt = 0; cur = g;
        }
        acc += h[(size_t)r * HDIM + c];
        cnt++;
    }
    atomicAdd(&gsum[cur * HDIM + c], acc);
    if (c == 0) atomicAdd(&gcnt[cur], cnt);
}

__global__ void k_finalize(const float* __restrict__ gsum, const int* __restrict__ gcnt,
                           float* __restrict__ out) {
    int i = blockIdx.x * blockDim.x + threadIdx.x;
    if (i >= NGRAPH * HDIM) return;
    float cnt = fmaxf((float)gcnt[i >> 7], 1.0f);
    out[i] = gsum[i] / cnt;
}

// ---------------- launch ----------------
extern "C" void kernel_launch(void* const* d_in, const int* in_sizes, int n_in,
                              void* d_out, int out_size) {
    const float* x     = (const float*)d_in[0];
    const int*   eidx  = (const int*)d_in[1];
    const int*   batch = (const int*)d_in[2];
    const float* W1 = (const float*)d_in[3];
    const float* b1 = (const float*)d_in[4];
    const float* g1 = (const float*)d_in[5];
    const float* be1 = (const float*)d_in[6];
    const float* W2 = (const float*)d_in[7];
    const float* b2 = (const float*)d_in[8];
    const float* g2 = (const float*)d_in[9];
    const float* be2 = (const float*)d_in[10];

    const int n = in_sizes[0] / FDIM;   // 100000
    const int e = in_sizes[1] / 2;      // 1600000
    const int* src = eidx;
    const int* dst = eidx + e;

    int*      ibuf;  cudaGetSymbolAddress((void**)&ibuf,  g_ibuf);
    int*      part;  cudaGetSymbolAddress((void**)&part,  g_partial);
    int*      bsum;  cudaGetSymbolAddress((void**)&bsum,  g_blocksum);
    int*      bpref; cudaGetSymbolAddress((void**)&bpref, g_blockpref);
    int2*     csr;   cudaGetSymbolAddress((void**)&csr,   g_csr);
    ushort_t* xbf;   cudaGetSymbolAddress((void**)&xbf,   g_xbf);
    float*    bufa;  cudaGetSymbolAddress((void**)&bufa,  g_bufa);
    float*    bufb;  cudaGetSymbolAddress((void**)&bufb,  g_bufb);
    float*    pool;  cudaGetSymbolAddress((void**)&pool,  g_pool);
    ushort_t *w1h, *w1l, *w2h, *w2l;
    cudaGetSymbolAddress((void**)&w1h, g_w1h);
    cudaGetSymbolAddress((void**)&w1l, g_w1l);
    cudaGetSymbolAddress((void**)&w2h, g_w2h);
    cudaGetSymbolAddress((void**)&w2l, g_w2l);

    int* deg  = ibuf;
    int* cnt2 = ibuf + NPARTIAL;
    float* gsum = pool;
    int*   gcnt = (int*)(pool + NGRAPH * HDIM);

    const int T = 256;
    auto cdiv = [](int a, int b) { return (a + b - 1) / b; };
    const int B   = cdiv(n + 1, SCANW);
    const int nb  = cdiv(e, T);
    const int nx4 = n * FDIM / 4;                 // float4s in x
    const int xb  = cdiv(nx4, T);

    cudaMemsetAsync(ibuf, 0, sizeof(int) * (NPARTIAL + NNODES));
    cudaMemsetAsync(pool, 0, sizeof(float) * (NGRAPH * HDIM) + sizeof(int) * NGRAPH);

    // CSR build + W split + x->bf16 (all in launch 1's grid)
    k_count_prep<<<nb + 2 + xb, T>>>(dst, deg, e, nb, W1, W2,
                                     w1h, w1l, w2h, w2l, x, xbf, nx4);             // 1
    k_scan_block<<<B, SCANW>>>(deg, part, bsum, n);                                // 2
    k_fill<<<cdiv(e, T), T>>>(src, dst, deg, part, bsum, B, bpref, cnt2, csr, e);  // 3

    // conv1: bf16 gather then tensor GEMM+LN+ReLU (h1 emitted as bf16)
    k_agg64<<<cdiv(n * 32, T), T>>>(xbf, deg, csr, part, bpref, bufa, n);          // 4 <- profiled
    k_mma_ln<FDIM, true, true><<<n / 32, T>>>(bufa, w1h, w1l, b1, g1, be1,
                                              (void*)bufb, n);                     // 5

    // conv2: bf16 gather (h1) then tensor GEMM+LN (fp32 out)
    k_agg128<<<cdiv(n * 32, T), T>>>((const ushort_t*)bufb, deg, csr, part, bpref,
                                     bufa, n);                                     // 6
    k_mma_ln<HDIM, false, false><<<n / 32, T>>>(bufa, w2h, w2l, b2, g2, be2,
                                                (void*)bufb, n);                   // 7

    // mean pool per graph (batch is sorted)
    const int rpb = 128;
    k_pool_sum<<<cdiv(n, rpb), HDIM>>>(bufb, batch, gsum, gcnt, n, rpb);           // 8
    k_finalize<<<cdiv(NGRAPH * HDIM, HDIM), HDIM>>>(gsum, gcnt, (float*)d_out);    // 9
}

// round 13
// speedup vs baseline: 1.2728x; 1.0399x over previous
#include <cuda_runtime.h>
#include <cuda_bf16.h>
#include <cstdint>

// Problem constants (shapes fixed by the dataset)
#define NNODES 100000
#define NEDGES 1600000
#define NGRAPH 128
#define HDIM   128
#define FDIM   64
#define LN_EPS 1e-5f

#define SCANW   1024
#define NSCANBLK ((NNODES + SCANW) / SCANW + 1)
#define NPARTIAL (NSCANBLK * SCANW)

typedef unsigned short ushort_t;

// ---------------- mma / ldmatrix (Ampere-path HMMA, legal on plain sm_100) --
#define LDSM4(r0, r1, r2, r3, addr) \
    asm volatile("ldmatrix.sync.aligned.m8n8.x4.shared.b16 {%0,%1,%2,%3}, [%4];" \
                 : "=r"(r0), "=r"(r1), "=r"(r2), "=r"(r3) : "r"(addr))

#define MMA_BF16(d, a0, a1, a2, a3, b0, b1) \
    asm volatile("mma.sync.aligned.m16n8k16.row.col.f32.bf16.bf16.f32 " \
                 "{%0,%1,%2,%3}, {%4,%5,%6,%7}, {%8,%9}, {%0,%1,%2,%3};" \
                 : "+f"(d[0]), "+f"(d[1]), "+f"(d[2]), "+f"(d[3]) \
                 : "r"(a0), "r"(a1), "r"(a2), "r"(a3), "r"(b0), "r"(b1))

__device__ __forceinline__ uint32_t smem_u32(const void* p) {
    uint32_t a;
    asm("{ .reg .u64 t; cvta.to.shared.u64 t, %1; cvt.u32.u64 %0, t; }" : "=r"(a) : "l"(p));
    return a;
}

// ---------------- scratch (device globals; no allocations allowed) ----------
__device__ int      g_ibuf[NPARTIAL + NNODES];      // deg + fill cursors (one memset)
__device__ int      g_partial[NPARTIAL];
__device__ int      g_blocksum[256];
__device__ int      g_blockpref[128];
__device__ int2     g_csr[NEDGES];                  // (src, bits(dinv[src]))
__device__ ushort_t g_xbf[(size_t)NNODES * FDIM];   // x in bf16 (gather operand)
__device__ float    g_bufa[(size_t)NNODES * HDIM];
__device__ float    g_bufb[(size_t)NNODES * HDIM];  // h1 as bf16 / h2 as fp32
__device__ float    g_pool[NGRAPH * HDIM + NGRAPH];
// W split images, chunk-major [chunk][n=128][40 k-slots] (k pad 32..39 zeroed)
__device__ ushort_t g_w1h[2 * 128 * 40], g_w1l[2 * 128 * 40];
__device__ ushort_t g_w2h[4 * 128 * 40], g_w2l[4 * 128 * 40];

// ---------------- degree count + W split + x->bf16 (fused) ----------------
__device__ __forceinline__ void prep_w(const float* __restrict__ W, int K,
                                       ushort_t* __restrict__ wh, ushort_t* __restrict__ wl) {
    for (int idx = threadIdx.x; idx < K * 128; idx += 256) {
        int k = idx >> 7, nn = idx & 127;
        float v = W[idx];
        __nv_bfloat16 h = __float2bfloat16(v);
        __nv_bfloat16 l = __float2bfloat16(v - __bfloat162float(h));
        int off = (((k >> 5) * 128 + nn) * 40) + (k & 31);
        wh[off] = __bfloat16_as_ushort(h);
        wl[off] = __bfloat16_as_ushort(l);
    }
    for (int idx = threadIdx.x; idx < (K / 32) * 128 * 8; idx += 256) {
        int cn = idx >> 3;
        int off = cn * 40 + 32 + (idx & 7);
        wh[off] = 0; wl[off] = 0;
    }
}

__global__ void __launch_bounds__(256)
k_count_prep(const int* __restrict__ dst, int* __restrict__ deg, int e, int nb,
             const float* __restrict__ W1, const float* __restrict__ W2,
             ushort_t* w1h, ushort_t* w1l, ushort_t* w2h, ushort_t* w2l,
             const float* __restrict__ x, ushort_t* __restrict__ xbf, int nx4) {
    if ((int)blockIdx.x < nb) {
        int i = blockIdx.x * 256 + threadIdx.x;
        if (i < e) atomicAdd(&deg[dst[i]], 1);
        return;
    }
    if (blockIdx.x == (unsigned)nb)       { prep_w(W1, FDIM, w1h, w1l); return; }
    if (blockIdx.x == (unsigned)(nb + 1)) { prep_w(W2, HDIM, w2h, w2l); return; }
    int idx = (blockIdx.x - nb - 2) * 256 + threadIdx.x;
    if (idx < nx4) {
        float4 v = reinterpret_cast<const float4*>(x)[idx];
        __nv_bfloat162 p0 = __floats2bfloat162_rn(v.x, v.y);
        __nv_bfloat162 p1 = __floats2bfloat162_rn(v.z, v.w);
        uint2 u = make_uint2(*reinterpret_cast<uint32_t*>(&p0),
                             *reinterpret_cast<uint32_t*>(&p1));
        reinterpret_cast<uint2*>(xbf)[idx] = u;
    }
}

// ---------------- per-block exclusive scan (level 1) ----------------
__global__ void k_scan_block(const int* __restrict__ deg, int* __restrict__ partial,
                             int* __restrict__ blocksum, int n) {
    __shared__ int sm[2][SCANW];
    int t = threadIdx.x;
    int g = blockIdx.x * SCANW + t;
    int v = (g < n) ? deg[g] : 0;
    sm[0][t] = v;
    __syncthreads();
    int cur = 0;
#pragma unroll
    for (int off = 1; off < SCANW; off <<= 1) {
        int x = sm[cur][t];
        if (t >= off) x += sm[cur][t - off];
        sm[cur ^ 1][t] = x;
        __syncthreads();
        cur ^= 1;
    }
    int inc = sm[cur][t];
    partial[g] = inc - v;
    if (t == SCANW - 1) blocksum[blockIdx.x] = inc;
}

// Level-2 prefix computed in-block (<=128 scan blocks). All threads call it.
__device__ __forceinline__ void block_prefix(const int* __restrict__ bsum, int B,
                                             int* __restrict__ sbp) {
    __shared__ int tmp[128];
    int t = threadIdx.x;
    int v = 0;
    if (t < 128) { v = (t < B) ? bsum[t] : 0; tmp[t] = v; }
    __syncthreads();
#pragma unroll
    for (int off = 1; off < 128; off <<= 1) {
        int x = 0;
        if (t < 128) { x = tmp[t]; if (t >= off) x += tmp[t - off]; }
        __syncthreads();
        if (t < 128) tmp[t] = x;
        __syncthreads();
    }
    if (t < 128) sbp[t] = tmp[t] - v;   // exclusive
    __syncthreads();
}

// ---------------- CSR fill (also publishes the level-2 prefix) --------------
__global__ void __launch_bounds__(256)
k_fill(const int* __restrict__ src, const int* __restrict__ dst,
       const int* __restrict__ deg, const int* __restrict__ partial,
       const int* __restrict__ bsum, int B, int* __restrict__ bpref_g,
       int* __restrict__ cnt2, int2* __restrict__ csr, int e) {
    __shared__ int sbp[128];
    block_prefix(bsum, B, sbp);
    if (blockIdx.x == 0 && threadIdx.x < 128) bpref_g[threadIdx.x] = sbp[threadIdx.x];
    int i = blockIdx.x * blockDim.x + threadIdx.x;
    if (i >= e) return;
    int s = src[i];
    int d = dst[i];
    float dvs = rsqrtf((float)(deg[s] + 1));
    int pos = partial[d] + sbp[d >> 10] + atomicAdd(&cnt2[d], 1);
    csr[pos] = make_int2(s, __float_as_int(dvs));
}

// ---------------- gather aggregation: warp per dst node, bf16 operands ------
// CSR read via int4 (2 edges per load; parity prologue keeps 16B alignment).
__global__ void __launch_bounds__(256)
k_agg64(const ushort_t* __restrict__ featbf, const int* __restrict__ deg,
        const int2* __restrict__ csr, const int* __restrict__ partial,
        const int* __restrict__ bpref, float* __restrict__ out, int n) {
    int w = (blockIdx.x * blockDim.x + threadIdx.x) >> 5;
    if (w >= n) return;
    int lane = threadIdx.x & 31;
    int r0 = partial[w] + bpref[w >> 10];
    int r1 = partial[w + 1] + bpref[(w + 1) >> 10];
    float dv = rsqrtf((float)(deg[w] + 1));

    const uint32_t* f32v = reinterpret_cast<const uint32_t*>(featbf);
    uint32_t su = f32v[(size_t)w * 32 + lane];
    float2 acc = __bfloat1622float2(*reinterpret_cast<__nv_bfloat162*>(&su));
    acc.x *= dv; acc.y *= dv;

    int r = r0;
    if ((r & 1) && r < r1) {
        int2 e0 = csr[r];
        uint32_t u0 = f32v[(size_t)e0.x * 32 + lane];
        float2 v0 = __bfloat1622float2(*reinterpret_cast<__nv_bfloat162*>(&u0));
        float w0 = __int_as_float(e0.y);
        acc.x = fmaf(w0, v0.x, acc.x); acc.y = fmaf(w0, v0.y, acc.y);
        r++;
    }
    for (; r + 4 <= r1; r += 4) {
        int4 p = *reinterpret_cast<const int4*>(csr + r);
        int4 q = *reinterpret_cast<const int4*>(csr + r + 2);
        uint32_t u0 = f32v[(size_t)p.x * 32 + lane];
        uint32_t u1 = f32v[(size_t)p.z * 32 + lane];
        uint32_t u2 = f32v[(size_t)q.x * 32 + lane];
        uint32_t u3 = f32v[(size_t)q.z * 32 + lane];
        float2 v0 = __bfloat1622float2(*reinterpret_cast<__nv_bfloat162*>(&u0));
        float2 v1 = __bfloat1622float2(*reinterpret_cast<__nv_bfloat162*>(&u1));
        float2 v2 = __bfloat1622float2(*reinterpret_cast<__nv_bfloat162*>(&u2));
        float2 v3 = __bfloat1622float2(*reinterpret_cast<__nv_bfloat162*>(&u3));
        float w0 = __int_as_float(p.y), w1 = __int_as_float(p.w);
        float w2 = __int_as_float(q.y), w3 = __int_as_float(q.w);
        acc.x = fmaf(w0, v0.x, acc.x); acc.y = fmaf(w0, v0.y, acc.y);
        acc.x = fmaf(w1, v1.x, acc.x); acc.y = fmaf(w1, v1.y, acc.y);
        acc.x = fmaf(w2, v2.x, acc.x); acc.y = fmaf(w2, v2.y, acc.y);
        acc.x = fmaf(w3, v3.x, acc.x); acc.y = fmaf(w3, v3.y, acc.y);
    }
    for (; r < r1; r++) {
        int2 e0 = csr[r];
        uint32_t u0 = f32v[(size_t)e0.x * 32 + lane];
        float2 v0 = __bfloat1622float2(*reinterpret_cast<__nv_bfloat162*>(&u0));
        float w0 = __int_as_float(e0.y);
        acc.x = fmaf(w0, v0.x, acc.x); acc.y = fmaf(w0, v0.y, acc.y);
    }
    acc.x *= dv; acc.y *= dv;
    reinterpret_cast<float2*>(out)[(size_t)w * 32 + lane] = acc;
}

__device__ __forceinline__ void bf4_unpack(uint2 u, float4& o) {
    float2 a = __bfloat1622float2(*reinterpret_cast<__nv_bfloat162*>(&u.x));
    float2 b = __bfloat1622float2(*reinterpret_cast<__nv_bfloat162*>(&u.y));
    o.x = a.x; o.y = a.y; o.z = b.x; o.w = b.y;
}

__global__ void __launch_bounds__(256)
k_agg128(const ushort_t* __restrict__ featbf, const int* __restrict__ deg,
         const int2* __restrict__ csr, const int* __restrict__ partial,
         const int* __restrict__ bpref, float* __restrict__ out, int n) {
    int w = (blockIdx.x * blockDim.x + threadIdx.x) >> 5;
    if (w >= n) return;
    int lane = threadIdx.x & 31;
    int r0 = partial[w] + bpref[w >> 10];
    int r1 = partial[w + 1] + bpref[(w + 1) >> 10];
    float dv = rsqrtf((float)(deg[w] + 1));

    const uint2* f64v = reinterpret_cast<const uint2*>(featbf);
    float4 acc;
    bf4_unpack(f64v[(size_t)w * 32 + lane], acc);
    acc.x *= dv; acc.y *= dv; acc.z *= dv; acc.w *= dv;

    int r = r0;
    if ((r & 1) && r < r1) {
        int2 e0 = csr[r];
        float4 v0;
        bf4_unpack(f64v[(size_t)e0.x * 32 + lane], v0);
        float w0 = __int_as_float(e0.y);
        acc.x = fmaf(w0, v0.x, acc.x); acc.y = fmaf(w0, v0.y, acc.y);
        acc.z = fmaf(w0, v0.z, acc.z); acc.w = fmaf(w0, v0.w, acc.w);
        r++;
    }
    for (; r + 4 <= r1; r += 4) {
        int4 p = *reinterpret_cast<const int4*>(csr + r);
        int4 q = *reinterpret_cast<const int4*>(csr + r + 2);
        uint2 u0 = f64v[(size_t)p.x * 32 + lane];
        uint2 u1 = f64v[(size_t)p.z * 32 + lane];
        uint2 u2 = f64v[(size_t)q.x * 32 + lane];
        uint2 u3 = f64v[(size_t)q.z * 32 + lane];
        float4 v0, v1, v2, v3;
        bf4_unpack(u0, v0); bf4_unpack(u1, v1); bf4_unpack(u2, v2); bf4_unpack(u3, v3);
        float w0 = __int_as_float(p.y), w1 = __int_as_float(p.w);
        float w2 = __int_as_float(q.y), w3 = __int_as_float(q.w);
        acc.x = fmaf(w0, v0.x, acc.x); acc.y = fmaf(w0, v0.y, acc.y);
        acc.z = fmaf(w0, v0.z, acc.z); acc.w = fmaf(w0, v0.w, acc.w);
        acc.x = fmaf(w1, v1.x, acc.x); acc.y = fmaf(w1, v1.y, acc.y);
        acc.z = fmaf(w1, v1.z, acc.z); acc.w = fmaf(w1, v1.w, acc.w);
        acc.x = fmaf(w2, v2.x, acc.x); acc.y = fmaf(w2, v2.y, acc.y);
        acc.z = fmaf(w2, v2.z, acc.z); acc.w = fmaf(w2, v2.w, acc.w);
        acc.x = fmaf(w3, v3.x, acc.x); acc.y = fmaf(w3, v3.y, acc.y);
        acc.z = fmaf(w3, v3.z, acc.z); acc.w = fmaf(w3, v3.w, acc.w);
    }
    for (; r < r1; r++) {
        int2 e0 = csr[r];
        float4 v0;
        bf4_unpack(f64v[(size_t)e0.x * 32 + lane], v0);
        float w0 = __int_as_float(e0.y);
        acc.x = fmaf(w0, v0.x, acc.x); acc.y = fmaf(w0, v0.y, acc.y);
        acc.z = fmaf(w0, v0.z, acc.z); acc.w = fmaf(w0, v0.w, acc.w);
    }
    acc.x *= dv; acc.y *= dv; acc.z *= dv; acc.w *= dv;
    reinterpret_cast<float4*>(out)[(size_t)w * 32 + lane] = acc;
}

// ---------------- tensor GEMM + bias + LN (+ReLU), 64 rows/block ------------
// Halves per-block W staging traffic vs 32-row blocks. Dynamic smem.
// warp w: row-tile rt = w&3 (16 rows), col half nbase = (w>>2)*64 (8 n-tiles).
template <int K, bool RELU, bool OUT_BF16>
__global__ void __launch_bounds__(256)
k_mma_ln(const float* __restrict__ in,
         const ushort_t* __restrict__ gWh, const ushort_t* __restrict__ gWl,
         const float* __restrict__ bias, const float* __restrict__ gamma,
         const float* __restrict__ beta, void* __restrict__ outv, int n) {
    constexpr int ROWS   = 64;
    constexpr int XSTR   = K + 8;                 // ushorts per X row (pad)
    constexpr int NCH    = K / 32;                // W chunks
    constexpr int XBYTES = ROWS * XSTR * 2;       // one X split
    constexpr int WBYTES = 128 * 40 * 2;          // one W chunk split

    extern __shared__ __align__(16) unsigned char sbuf[];
    ushort_t* sXh = (ushort_t*)sbuf;
    ushort_t* sXl = (ushort_t*)(sbuf + XBYTES);
    ushort_t* sWh = (ushort_t*)(sbuf + 2 * XBYTES);
    ushort_t* sWl = (ushort_t*)(sbuf + 2 * XBYTES + WBYTES);
    float (*sOut)[132] = (float (*)[132])sbuf;    // aliases everything after mma

    const int tid  = threadIdx.x;
    const int warp = tid >> 5;
    const int lane = tid & 31;
    const int row0 = blockIdx.x * ROWS;           // last block may be partial

    // ---------------- load X fp32, split to bf16 hi/lo tiles ----------------
    constexpr int NF4 = ROWS * K / 4;
#pragma unroll
    for (int idx = tid; idx < NF4; idx += 256) {
        int row = idx / (K / 4);
        int c4  = idx % (K / 4);
        float4 v = (row0 + row < n)
                 ? reinterpret_cast<const float4*>(in + (size_t)(row0 + row) * K)[c4]
                 : make_float4(0.f, 0.f, 0.f, 0.f);
        __nv_bfloat162 hp0 = __floats2bfloat162_rn(v.x, v.y);
        __nv_bfloat162 hp1 = __floats2bfloat162_rn(v.z, v.w);
        float2 hf0 = __bfloat1622float2(hp0);
        float2 hf1 = __bfloat1622float2(hp1);
        __nv_bfloat162 lp0 = __floats2bfloat162_rn(v.x - hf0.x, v.y - hf0.y);
        __nv_bfloat162 lp1 = __floats2bfloat162_rn(v.z - hf1.x, v.w - hf1.y);
        uint2 hu = make_uint2(*reinterpret_cast<uint32_t*>(&hp0),
                              *reinterpret_cast<uint32_t*>(&hp1));
        uint2 lu = make_uint2(*reinterpret_cast<uint32_t*>(&lp0),
                              *reinterpret_cast<uint32_t*>(&lp1));
        *reinterpret_cast<uint2*>(sXh + row * XSTR + c4 * 4) = hu;
        *reinterpret_cast<uint2*>(sXl + row * XSTR + c4 * 4) = lu;
    }

    // ---------------- bf16 3-split mma ----------------
    const int rt    = warp & 3;                    // row-tile (16 rows)
    const int nbase = (warp >> 2) * 64;            // 64-col half
    const int a_row = rt * 16 + (lane & 7) + ((lane >> 3) & 1) * 8;
    const int a_k   = (lane >> 4) * 8;
    const uint32_t aH = smem_u32(sXh) + (uint32_t)(a_row * XSTR + a_k) * 2;
    const uint32_t aL = smem_u32(sXl) + (uint32_t)(a_row * XSTR + a_k) * 2;
    const int b_n = (lane & 7) + ((lane >> 4) & 1) * 8;
    const int b_k = ((lane >> 3) & 1) * 8;
    const uint32_t bHb = smem_u32(sWh) + (uint32_t)((nbase + b_n) * 40 + b_k) * 2;
    const uint32_t bLb = smem_u32(sWl) + (uint32_t)((nbase + b_n) * 40 + b_k) * 2;

    float acc[8][4];
#pragma unroll
    for (int t = 0; t < 8; t++)
#pragma unroll
        for (int c = 0; c < 4; c++) acc[t][c] = 0.0f;

#pragma unroll
    for (int c = 0; c < NCH; c++) {
        {
            const uint4* srcH = reinterpret_cast<const uint4*>(gWh + c * 5120);
            const uint4* srcL = reinterpret_cast<const uint4*>(gWl + c * 5120);
            uint4* dH = reinterpret_cast<uint4*>(sWh);
            uint4* dL = reinterpret_cast<uint4*>(sWl);
#pragma unroll
            for (int i = tid; i < 640; i += 256) { dH[i] = srcH[i]; dL[i] = srcL[i]; }
        }
        __syncthreads();

#pragma unroll
        for (int ks = 0; ks < 2; ks++) {
            const uint32_t ko = (uint32_t)(c * 32 + ks * 16) * 2;
            const uint32_t kc = (uint32_t)(ks * 16) * 2;
            uint32_t ah0, ah1, ah2, ah3, al0, al1, al2, al3;
            LDSM4(ah0, ah1, ah2, ah3, aH + ko);
            LDSM4(al0, al1, al2, al3, aL + ko);
#pragma unroll
            for (int tp = 0; tp < 4; tp++) {
                const uint32_t off = (uint32_t)(tp * 16 * 40 * 2) + kc;
                uint32_t bh0, bh1, bh2, bh3, bl0, bl1, bl2, bl3;
                LDSM4(bh0, bh1, bh2, bh3, bHb + off);
                LDSM4(bl0, bl1, bl2, bl3, bLb + off);
                MMA_BF16(acc[2 * tp + 0], ah0, ah1, ah2, ah3, bh0, bh1);
                MMA_BF16(acc[2 * tp + 0], ah0, ah1, ah2, ah3, bl0, bl1);
                MMA_BF16(acc[2 * tp + 0], al0, al1, al2, al3, bh0, bh1);
                MMA_BF16(acc[2 * tp + 1], ah0, ah1, ah2, ah3, bh2, bh3);
                MMA_BF16(acc[2 * tp + 1], ah0, ah1, ah2, ah3, bl2, bl3);
                MMA_BF16(acc[2 * tp + 1], al0, al1, al2, al3, bh2, bh3);
            }
        }
        __syncthreads();
    }

    // scatter fragments to sOut (aliases tiles; safe after final sync)
    {
        const int g  = lane >> 2;
        const int cx = 2 * (lane & 3);
#pragma unroll
        for (int t = 0; t < 8; t++) {
            const int col = nbase + 8 * t + cx;
            *reinterpret_cast<float2*>(&sOut[rt * 16 + g][col]) =
                make_float2(acc[t][0], acc[t][1]);
            *reinterpret_cast<float2*>(&sOut[rt * 16 + g + 8][col]) =
                make_float2(acc[t][2], acc[t][3]);
        }
    }
    __syncthreads();

    // ---------------- LN epilogue (8 rows per warp) ----------------
    const float4 bv = reinterpret_cast<const float4*>(bias)[lane];
    const float4 gv = reinterpret_cast<const float4*>(gamma)[lane];
    const float4 be = reinterpret_cast<const float4*>(beta)[lane];

#pragma unroll
    for (int r = 0; r < 8; r++) {
        int rl = warp * 8 + r;
        float4 v = *reinterpret_cast<float4*>(&sOut[rl][lane * 4]);
        float hx = v.x + bv.x;
        float hy = v.y + bv.y;
        float hz = v.z + bv.z;
        float hw = v.w + bv.w;
        float s = hx + hy + hz + hw;
#pragma unroll
        for (int o = 16; o > 0; o >>= 1) s += __shfl_xor_sync(0xffffffffu, s, o);
        float mu = s * (1.0f / 128.0f);
        float dx = hx - mu, dy = hy - mu, dz = hz - mu, dw = hw - mu;
        float q = dx * dx + dy * dy + dz * dz + dw * dw;
#pragma unroll
        for (int o = 16; o > 0; o >>= 1) q += __shfl_xor_sync(0xffffffffu, q, o);
        float rstd = rsqrtf(q * (1.0f / 128.0f) + LN_EPS);

        float4 o4;
        o4.x = dx * rstd * gv.x + be.x;
        o4.y = dy * rstd * gv.y + be.y;
        o4.z = dz * rstd * gv.z + be.z;
        o4.w = dw * rstd * gv.w + be.w;
        if (RELU) {
            o4.x = fmaxf(o4.x, 0.0f);
            o4.y = fmaxf(o4.y, 0.0f);
            o4.z = fmaxf(o4.z, 0.0f);
            o4.w = fmaxf(o4.w, 0.0f);
        }
        int row = row0 + rl;
        if (row < n) {
            if (OUT_BF16) {
                __nv_bfloat162 p0 = __floats2bfloat162_rn(o4.x, o4.y);
                __nv_bfloat162 p1 = __floats2bfloat162_rn(o4.z, o4.w);
                uint2 u = make_uint2(*reinterpret_cast<uint32_t*>(&p0),
                                     *reinterpret_cast<uint32_t*>(&p1));
                reinterpret_cast<uint2*>((ushort_t*)outv + (size_t)row * 128)[lane] = u;
            } else {
                reinterpret_cast<float4*>((float*)outv + (size_t)row * 128)[lane] = o4;
            }
        }
    }
}

// ---------------- pooling (batch is sorted; count fused) ----------------
__global__ void k_pool_sum(const float* __restrict__ h, const int* __restrict__ batch,
                           float* __restrict__ gsum, int* __restrict__ gcnt, int n, int rpb) {
    int c  = threadIdx.x;
    int r0 = blockIdx.x * rpb;
    int r1 = min(r0 + rpb, n);
    if (r0 >= r1) return;
    float acc = 0.0f;
    int cnt = 0;
    int cur = batch[r0];
    for (int r = r0; r < r1; r++) {
        int g = batch[r];
        if (g != cur) {
            atomicAdd(&gsum[cur * HDIM + c], acc);
            if (c == 0) atomicAdd(&gcnt[cur], cnt);
            acc = 0.0f; cnt = 0; cur = g;
        }
        acc += h[(size_t)r * HDIM + c];
        cnt++;
    }
    atomicAdd(&gsum[cur * HDIM + c], acc);
    if (c == 0) atomicAdd(&gcnt[cur], cnt);
}

__global__ void k_finalize(const float* __restrict__ gsum, const int* __restrict__ gcnt,
                           float* __restrict__ out) {
    int i = blockIdx.x * blockDim.x + threadIdx.x;
    if (i >= NGRAPH * HDIM) return;
    float cnt = fmaxf((float)gcnt[i >> 7], 1.0f);
    out[i] = gsum[i] / cnt;
}

// ---------------- launch ----------------
extern "C" void kernel_launch(void* const* d_in, const int* in_sizes, int n_in,
                              void* d_out, int out_size) {
    const float* x     = (const float*)d_in[0];
    const int*   eidx  = (const int*)d_in[1];
    const int*   batch = (const int*)d_in[2];
    const float* W1 = (const float*)d_in[3];
    const float* b1 = (const float*)d_in[4];
    const float* g1 = (const float*)d_in[5];
    const float* be1 = (const float*)d_in[6];
    const float* W2 = (const float*)d_in[7];
    const float* b2 = (const float*)d_in[8];
    const float* g2 = (const float*)d_in[9];
    const float* be2 = (const float*)d_in[10];

    const int n = in_sizes[0] / FDIM;   // 100000
    const int e = in_sizes[1] / 2;      // 1600000
    const int* src = eidx;
    const int* dst = eidx + e;

    int*      ibuf;  cudaGetSymbolAddress((void**)&ibuf,  g_ibuf);
    int*      part;  cudaGetSymbolAddress((void**)&part,  g_partial);
    int*      bsum;  cudaGetSymbolAddress((void**)&bsum,  g_blocksum);
    int*      bpref; cudaGetSymbolAddress((void**)&bpref, g_blockpref);
    int2*     csr;   cudaGetSymbolAddress((void**)&csr,   g_csr);
    ushort_t* xbf;   cudaGetSymbolAddress((void**)&xbf,   g_xbf);
    float*    bufa;  cudaGetSymbolAddress((void**)&bufa,  g_bufa);
    float*    bufb;  cudaGetSymbolAddress((void**)&bufb,  g_bufb);
    float*    pool;  cudaGetSymbolAddress((void**)&pool,  g_pool);
    ushort_t *w1h, *w1l, *w2h, *w2l;
    cudaGetSymbolAddress((void**)&w1h, g_w1h);
    cudaGetSymbolAddress((void**)&w1l, g_w1l);
    cudaGetSymbolAddress((void**)&w2h, g_w2h);
    cudaGetSymbolAddress((void**)&w2l, g_w2l);

    int* deg  = ibuf;
    int* cnt2 = ibuf + NPARTIAL;
    float* gsum = pool;
    int*   gcnt = (int*)(pool + NGRAPH * HDIM);

    const int T = 256;
    auto cdiv = [](int a, int b) { return (a + b - 1) / b; };
    const int B   = cdiv(n + 1, SCANW);
    const int nb  = cdiv(e, T);
    const int nx4 = n * FDIM / 4;
    const int xb  = cdiv(nx4, T);
    const int gB  = cdiv(n, 64);                  // 64-row mma blocks

    // dynamic smem: 2 X splits + 2 W chunk splits
    constexpr int SMEM1 = 2 * (64 * (FDIM + 8) * 2) + 2 * (128 * 40 * 2);  // 38912
    constexpr int SMEM2 = 2 * (64 * (HDIM + 8) * 2) + 2 * (128 * 40 * 2);  // 55296
    cudaFuncSetAttribute(k_mma_ln<FDIM, true, true>,
                         cudaFuncAttributeMaxDynamicSharedMemorySize, SMEM1);
    cudaFuncSetAttribute(k_mma_ln<HDIM, false, false>,
                         cudaFuncAttributeMaxDynamicSharedMemorySize, SMEM2);

    cudaMemsetAsync(ibuf, 0, sizeof(int) * (NPARTIAL + NNODES));
    cudaMemsetAsync(pool, 0, sizeof(float) * (NGRAPH * HDIM) + sizeof(int) * NGRAPH);

    // CSR build + W split + x->bf16 (all in launch 1's grid)
    k_count_prep<<<nb + 2 + xb, T>>>(dst, deg, e, nb, W1, W2,
                                     w1h, w1l, w2h, w2l, x, xbf, nx4);             // 1
    k_scan_block<<<B, SCANW>>>(deg, part, bsum, n);                                // 2
    k_fill<<<cdiv(e, T), T>>>(src, dst, deg, part, bsum, B, bpref, cnt2, csr, e);  // 3

    // conv1: bf16 gather then tensor GEMM+LN+ReLU (h1 emitted as bf16)
    k_agg64<<<cdiv(n * 32, T), T>>>(xbf, deg, csr, part, bpref, bufa, n);          // 4 <- profiled
    k_mma_ln<FDIM, true, true><<<gB, T, SMEM1>>>(bufa, w1h, w1l, b1, g1, be1,
                                                 (void*)bufb, n);                  // 5

    // conv2: bf16 gather (h1) then tensor GEMM+LN (fp32 out)
    k_agg128<<<cdiv(n * 32, T), T>>>((const ushort_t*)bufb, deg, csr, part, bpref,
                                     bufa, n);                                     // 6
    k_mma_ln<HDIM, false, false><<<gB, T, SMEM2>>>(bufa, w2h, w2l, b2, g2, be2,
                                                   (void*)bufb, n);                // 7

    // mean pool per graph (batch is sorted)
    const int rpb = 128;
    k_pool_sum<<<cdiv(n, rpb), HDIM>>>(bufb, batch, gsum, gcnt, n, rpb);           // 8
    k_finalize<<<cdiv(NGRAPH * HDIM, HDIM), HDIM>>>(gsum, gcnt, (float*)d_out);    // 9
}

// round 14
// speedup vs baseline: 1.2864x; 1.0107x over previous
#include <cuda_runtime.h>
#include <cuda_bf16.h>
#include <cstdint>

// Problem constants (shapes fixed by the dataset)
#define NNODES 100000
#define NEDGES 1600000
#define NGRAPH 128
#define HDIM   128
#define FDIM   64
#define LN_EPS 1e-5f

#define SCANW   1024
#define NSCANBLK ((NNODES + SCANW) / SCANW + 1)
#define NPARTIAL (NSCANBLK * SCANW)

typedef unsigned short ushort_t;

// ---------------- mma / ldmatrix (Ampere-path HMMA, legal on plain sm_100) --
#define LDSM4(r0, r1, r2, r3, addr) \
    asm volatile("ldmatrix.sync.aligned.m8n8.x4.shared.b16 {%0,%1,%2,%3}, [%4];" \
                 : "=r"(r0), "=r"(r1), "=r"(r2), "=r"(r3) : "r"(addr))

#define MMA_BF16(d, a0, a1, a2, a3, b0, b1) \
    asm volatile("mma.sync.aligned.m16n8k16.row.col.f32.bf16.bf16.f32 " \
                 "{%0,%1,%2,%3}, {%4,%5,%6,%7}, {%8,%9}, {%0,%1,%2,%3};" \
                 : "+f"(d[0]), "+f"(d[1]), "+f"(d[2]), "+f"(d[3]) \
                 : "r"(a0), "r"(a1), "r"(a2), "r"(a3), "r"(b0), "r"(b1))

__device__ __forceinline__ uint32_t smem_u32(const void* p) {
    uint32_t a;
    asm("{ .reg .u64 t; cvta.to.shared.u64 t, %1; cvt.u32.u64 %0, t; }" : "=r"(a) : "l"(p));
    return a;
}

// ---------------- scratch (device globals; no allocations allowed) ----------
__device__ int      g_ibuf[NPARTIAL + NNODES];      // deg + fill cursors (one memset)
__device__ int      g_partial[NPARTIAL];
__device__ int      g_blocksum[256];
__device__ int      g_blockpref[128];
__device__ int      g_csr[NEDGES];                  // src index only (feat prescaled)
__device__ ushort_t g_xbf[(size_t)NNODES * FDIM];   // dinv*x in bf16
__device__ float    g_bufa[(size_t)NNODES * HDIM];
__device__ float    g_bufb[(size_t)NNODES * HDIM];  // dinv*h1 bf16 / h2 fp32
__device__ float    g_pool[NGRAPH * HDIM + NGRAPH];
// W split images, chunk-major [chunk][n=128][40 k-slots] (k pad 32..39 zeroed)
__device__ ushort_t g_w1h[2 * 128 * 40], g_w1l[2 * 128 * 40];
__device__ ushort_t g_w2h[4 * 128 * 40], g_w2l[4 * 128 * 40];

// ---------------- degree count + W split (fused, tail blocks) ----------------
__device__ __forceinline__ void prep_w(const float* __restrict__ W, int K,
                                       ushort_t* __restrict__ wh, ushort_t* __restrict__ wl) {
    for (int idx = threadIdx.x; idx < K * 128; idx += 256) {
        int k = idx >> 7, nn = idx & 127;
        float v = W[idx];
        __nv_bfloat16 h = __float2bfloat16(v);
        __nv_bfloat16 l = __float2bfloat16(v - __bfloat162float(h));
        int off = (((k >> 5) * 128 + nn) * 40) + (k & 31);
        wh[off] = __bfloat16_as_ushort(h);
        wl[off] = __bfloat16_as_ushort(l);
    }
    for (int idx = threadIdx.x; idx < (K / 32) * 128 * 8; idx += 256) {
        int cn = idx >> 3;
        int off = cn * 40 + 32 + (idx & 7);
        wh[off] = 0; wl[off] = 0;
    }
}

__global__ void __launch_bounds__(256)
k_count_prep(const int* __restrict__ dst, int* __restrict__ deg, int e, int nb,
             const float* __restrict__ W1, const float* __restrict__ W2,
             ushort_t* w1h, ushort_t* w1l, ushort_t* w2h, ushort_t* w2l) {
    if ((int)blockIdx.x < nb) {
        int i = blockIdx.x * 256 + threadIdx.x;
        if (i < e) atomicAdd(&deg[dst[i]], 1);
        return;
    }
    if (blockIdx.x == (unsigned)nb) prep_w(W1, FDIM, w1h, w1l);
    else                            prep_w(W2, HDIM, w2h, w2l);
}

// ---------------- per-block exclusive scan (level 1) ----------------
__global__ void k_scan_block(const int* __restrict__ deg, int* __restrict__ partial,
                             int* __restrict__ blocksum, int n) {
    __shared__ int sm[2][SCANW];
    int t = threadIdx.x;
    int g = blockIdx.x * SCANW + t;
    int v = (g < n) ? deg[g] : 0;
    sm[0][t] = v;
    __syncthreads();
    int cur = 0;
#pragma unroll
    for (int off = 1; off < SCANW; off <<= 1) {
        int x = sm[cur][t];
        if (t >= off) x += sm[cur][t - off];
        sm[cur ^ 1][t] = x;
        __syncthreads();
        cur ^= 1;
    }
    int inc = sm[cur][t];
    partial[g] = inc - v;
    if (t == SCANW - 1) blocksum[blockIdx.x] = inc;
}

// Level-2 prefix computed in-block (<=128 scan blocks). All threads call it.
__device__ __forceinline__ void block_prefix(const int* __restrict__ bsum, int B,
                                             int* __restrict__ sbp) {
    __shared__ int tmp[128];
    int t = threadIdx.x;
    int v = 0;
    if (t < 128) { v = (t < B) ? bsum[t] : 0; tmp[t] = v; }
    __syncthreads();
#pragma unroll
    for (int off = 1; off < 128; off <<= 1) {
        int x = 0;
        if (t < 128) { x = tmp[t]; if (t >= off) x += tmp[t - off]; }
        __syncthreads();
        if (t < 128) tmp[t] = x;
        __syncthreads();
    }
    if (t < 128) sbp[t] = tmp[t] - v;   // exclusive
    __syncthreads();
}

// ---------------- CSR fill + publish prefix + x->bf16*dinv (tail) -----------
__global__ void __launch_bounds__(256)
k_fill(const int* __restrict__ src, const int* __restrict__ dst,
       const int* __restrict__ deg, const int* __restrict__ partial,
       const int* __restrict__ bsum, int B, int* __restrict__ bpref_g,
       int* __restrict__ cnt2, int* __restrict__ csr, int e, int nbf,
       const float* __restrict__ x, ushort_t* __restrict__ xbf) {
    __shared__ int sbp[128];
    block_prefix(bsum, B, sbp);
    if ((int)blockIdx.x < nbf) {
        if (blockIdx.x == 0 && threadIdx.x < 128) bpref_g[threadIdx.x] = sbp[threadIdx.x];
        int i = blockIdx.x * blockDim.x + threadIdx.x;
        if (i >= e) return;
        int s = src[i];
        int d = dst[i];
        int pos = partial[d] + sbp[d >> 10] + atomicAdd(&cnt2[d], 1);
        csr[pos] = s;
        return;
    }
    // tail: xbf[row] = bf16( dinv[row] * x[row] )   (one float4 per thread)
    int idx = (blockIdx.x - nbf) * 256 + threadIdx.x;
    if (idx >= e) return;           // nx4 == e == 1.6M by coincidence of shapes
    int row = idx >> 4;             // FDIM/4 = 16 float4 per row
    float dv = rsqrtf((float)(deg[row] + 1));
    float4 v = reinterpret_cast<const float4*>(x)[idx];
    __nv_bfloat162 p0 = __floats2bfloat162_rn(v.x * dv, v.y * dv);
    __nv_bfloat162 p1 = __floats2bfloat162_rn(v.z * dv, v.w * dv);
    uint2 u = make_uint2(*reinterpret_cast<uint32_t*>(&p0),
                         *reinterpret_cast<uint32_t*>(&p1));
    reinterpret_cast<uint2*>(xbf)[idx] = u;
}

// ---------------- gather aggregation: warp per dst node, prescaled bf16 -----
// out[v] = dinv[v] * ( sum_{s in N(v)} fs[s] + fs[v] ),  fs = dinv*feat (bf16)
__global__ void __launch_bounds__(256)
k_agg64(const ushort_t* __restrict__ featbf, const int* __restrict__ deg,
        const int* __restrict__ csr, const int* __restrict__ partial,
        const int* __restrict__ bpref, float* __restrict__ out, int n) {
    int w = (blockIdx.x * blockDim.x + threadIdx.x) >> 5;
    if (w >= n) return;
    int lane = threadIdx.x & 31;
    int r0 = partial[w] + bpref[w >> 10];
    int r1 = partial[w + 1] + bpref[(w + 1) >> 10];
    float dv = rsqrtf((float)(deg[w] + 1));

    const uint32_t* f32v = reinterpret_cast<const uint32_t*>(featbf);
    uint32_t su = f32v[(size_t)w * 32 + lane];
    float2 acc = __bfloat1622float2(*reinterpret_cast<__nv_bfloat162*>(&su));

    int r = r0;
    int pre = (4 - (r0 & 3)) & 3;
    if (pre > r1 - r0) pre = r1 - r0;
    for (int i = 0; i < pre; i++, r++) {
        uint32_t u0 = f32v[(size_t)csr[r] * 32 + lane];
        float2 v0 = __bfloat1622float2(*reinterpret_cast<__nv_bfloat162*>(&u0));
        acc.x += v0.x; acc.y += v0.y;
    }
    for (; r + 4 <= r1; r += 4) {
        int4 p = *reinterpret_cast<const int4*>(csr + r);   // 4 edges, one load
        uint32_t u0 = f32v[(size_t)p.x * 32 + lane];
        uint32_t u1 = f32v[(size_t)p.y * 32 + lane];
        uint32_t u2 = f32v[(size_t)p.z * 32 + lane];
        uint32_t u3 = f32v[(size_t)p.w * 32 + lane];
        float2 v0 = __bfloat1622float2(*reinterpret_cast<__nv_bfloat162*>(&u0));
        float2 v1 = __bfloat1622float2(*reinterpret_cast<__nv_bfloat162*>(&u1));
        float2 v2 = __bfloat1622float2(*reinterpret_cast<__nv_bfloat162*>(&u2));
        float2 v3 = __bfloat1622float2(*reinterpret_cast<__nv_bfloat162*>(&u3));
        acc.x += v0.x; acc.y += v0.y;
        acc.x += v1.x; acc.y += v1.y;
        acc.x += v2.x; acc.y += v2.y;
        acc.x += v3.x; acc.y += v3.y;
    }
    for (; r < r1; r++) {
        uint32_t u0 = f32v[(size_t)csr[r] * 32 + lane];
        float2 v0 = __bfloat1622float2(*reinterpret_cast<__nv_bfloat162*>(&u0));
        acc.x += v0.x; acc.y += v0.y;
    }
    acc.x *= dv; acc.y *= dv;
    reinterpret_cast<float2*>(out)[(size_t)w * 32 + lane] = acc;
}

__device__ __forceinline__ void bf4_unpack(uint2 u, float4& o) {
    float2 a = __bfloat1622float2(*reinterpret_cast<__nv_bfloat162*>(&u.x));
    float2 b = __bfloat1622float2(*reinterpret_cast<__nv_bfloat162*>(&u.y));
    o.x = a.x; o.y = a.y; o.z = b.x; o.w = b.y;
}

__global__ void __launch_bounds__(256)
k_agg128(const ushort_t* __restrict__ featbf, const int* __restrict__ deg,
         const int* __restrict__ csr, const int* __restrict__ partial,
         const int* __restrict__ bpref, float* __restrict__ out, int n) {
    int w = (blockIdx.x * blockDim.x + threadIdx.x) >> 5;
    if (w >= n) return;
    int lane = threadIdx.x & 31;
    int r0 = partial[w] + bpref[w >> 10];
    int r1 = partial[w + 1] + bpref[(w + 1) >> 10];
    float dv = rsqrtf((float)(deg[w] + 1));

    const uint2* f64v = reinterpret_cast<const uint2*>(featbf);
    float4 acc;
    bf4_unpack(f64v[(size_t)w * 32 + lane], acc);

    int r = r0;
    int pre = (4 - (r0 & 3)) & 3;
    if (pre > r1 - r0) pre = r1 - r0;
    for (int i = 0; i < pre; i++, r++) {
        float4 v0;
        bf4_unpack(f64v[(size_t)csr[r] * 32 + lane], v0);
        acc.x += v0.x; acc.y += v0.y; acc.z += v0.z; acc.w += v0.w;
    }
    for (; r + 4 <= r1; r += 4) {
        int4 p = *reinterpret_cast<const int4*>(csr + r);
        uint2 u0 = f64v[(size_t)p.x * 32 + lane];
        uint2 u1 = f64v[(size_t)p.y * 32 + lane];
        uint2 u2 = f64v[(size_t)p.z * 32 + lane];
        uint2 u3 = f64v[(size_t)p.w * 32 + lane];
        float4 v0, v1, v2, v3;
        bf4_unpack(u0, v0); bf4_unpack(u1, v1); bf4_unpack(u2, v2); bf4_unpack(u3, v3);
        acc.x += v0.x; acc.y += v0.y; acc.z += v0.z; acc.w += v0.w;
        acc.x += v1.x; acc.y += v1.y; acc.z += v1.z; acc.w += v1.w;
        acc.x += v2.x; acc.y += v2.y; acc.z += v2.z; acc.w += v2.w;
        acc.x += v3.x; acc.y += v3.y; acc.z += v3.z; acc.w += v3.w;
    }
    for (; r < r1; r++) {
        float4 v0;
        bf4_unpack(f64v[(size_t)csr[r] * 32 + lane], v0);
        acc.x += v0.x; acc.y += v0.y; acc.z += v0.z; acc.w += v0.w;
    }
    acc.x *= dv; acc.y *= dv; acc.z *= dv; acc.w *= dv;
    reinterpret_cast<float4*>(out)[(size_t)w * 32 + lane] = acc;
}

// ---------------- tensor GEMM + bias + LN (+ReLU), 64 rows/block ------------
// OUT_BF16: store bf16 of dinv[row]*result (prescaled gather operand).
template <int K, bool RELU, bool OUT_BF16>
__global__ void __launch_bounds__(256)
k_mma_ln(const float* __restrict__ in,
         const ushort_t* __restrict__ gWh, const ushort_t* __restrict__ gWl,
         const float* __restrict__ bias, const float* __restrict__ gamma,
         const float* __restrict__ beta, const int* __restrict__ deg,
         void* __restrict__ outv, int n) {
    constexpr int ROWS   = 64;
    constexpr int XSTR   = K + 8;
    constexpr int NCH    = K / 32;
    constexpr int XBYTES = ROWS * XSTR * 2;
    constexpr int WBYTES = 128 * 40 * 2;

    extern __shared__ __align__(16) unsigned char sbuf[];
    ushort_t* sXh = (ushort_t*)sbuf;
    ushort_t* sXl = (ushort_t*)(sbuf + XBYTES);
    ushort_t* sWh = (ushort_t*)(sbuf + 2 * XBYTES);
    ushort_t* sWl = (ushort_t*)(sbuf + 2 * XBYTES + WBYTES);
    float (*sOut)[132] = (float (*)[132])sbuf;

    const int tid  = threadIdx.x;
    const int warp = tid >> 5;
    const int lane = tid & 31;
    const int row0 = blockIdx.x * ROWS;

    constexpr int NF4 = ROWS * K / 4;
#pragma unroll
    for (int idx = tid; idx < NF4; idx += 256) {
        int row = idx / (K / 4);
        int c4  = idx % (K / 4);
        float4 v = (row0 + row < n)
                 ? reinterpret_cast<const float4*>(in + (size_t)(row0 + row) * K)[c4]
                 : make_float4(0.f, 0.f, 0.f, 0.f);
        __nv_bfloat162 hp0 = __floats2bfloat162_rn(v.x, v.y);
        __nv_bfloat162 hp1 = __floats2bfloat162_rn(v.z, v.w);
        float2 hf0 = __bfloat1622float2(hp0);
        float2 hf1 = __bfloat1622float2(hp1);
        __nv_bfloat162 lp0 = __floats2bfloat162_rn(v.x - hf0.x, v.y - hf0.y);
        __nv_bfloat162 lp1 = __floats2bfloat162_rn(v.z - hf1.x, v.w - hf1.y);
        uint2 hu = make_uint2(*reinterpret_cast<uint32_t*>(&hp0),
                              *reinterpret_cast<uint32_t*>(&hp1));
        uint2 lu = make_uint2(*reinterpret_cast<uint32_t*>(&lp0),
                              *reinterpret_cast<uint32_t*>(&lp1));
        *reinterpret_cast<uint2*>(sXh + row * XSTR + c4 * 4) = hu;
        *reinterpret_cast<uint2*>(sXl + row * XSTR + c4 * 4) = lu;
    }

    const int rt    = warp & 3;
    const int nbase = (warp >> 2) * 64;
    const int a_row = rt * 16 + (lane & 7) + ((lane >> 3) & 1) * 8;
    const int a_k   = (lane >> 4) * 8;
    const uint32_t aH = smem_u32(sXh) + (uint32_t)(a_row * XSTR + a_k) * 2;
    const uint32_t aL = smem_u32(sXl) + (uint32_t)(a_row * XSTR + a_k) * 2;
    const int b_n = (lane & 7) + ((lane >> 4) & 1) * 8;
    const int b_k = ((lane >> 3) & 1) * 8;
    const uint32_t bHb = smem_u32(sWh) + (uint32_t)((nbase + b_n) * 40 + b_k) * 2;
    const uint32_t bLb = smem_u32(sWl) + (uint32_t)((nbase + b_n) * 40 + b_k) * 2;

    float acc[8][4];
#pragma unroll
    for (int t = 0; t < 8; t++)
#pragma unroll
        for (int c = 0; c < 4; c++) acc[t][c] = 0.0f;

#pragma unroll
    for (int c = 0; c < NCH; c++) {
        {
            const uint4* srcH = reinterpret_cast<const uint4*>(gWh + c * 5120);
            const uint4* srcL = reinterpret_cast<const uint4*>(gWl + c * 5120);
            uint4* dH = reinterpret_cast<uint4*>(sWh);
            uint4* dL = reinterpret_cast<uint4*>(sWl);
#pragma unroll
            for (int i = tid; i < 640; i += 256) { dH[i] = srcH[i]; dL[i] = srcL[i]; }
        }
        __syncthreads();

#pragma unroll
        for (int ks = 0; ks < 2; ks++) {
            const uint32_t ko = (uint32_t)(c * 32 + ks * 16) * 2;
            const uint32_t kc = (uint32_t)(ks * 16) * 2;
            uint32_t ah0, ah1, ah2, ah3, al0, al1, al2, al3;
            LDSM4(ah0, ah1, ah2, ah3, aH + ko);
            LDSM4(al0, al1, al2, al3, aL + ko);
#pragma unroll
            for (int tp = 0; tp < 4; tp++) {
                const uint32_t off = (uint32_t)(tp * 16 * 40 * 2) + kc;
                uint32_t bh0, bh1, bh2, bh3, bl0, bl1, bl2, bl3;
                LDSM4(bh0, bh1, bh2, bh3, bHb + off);
                LDSM4(bl0, bl1, bl2, bl3, bLb + off);
                MMA_BF16(acc[2 * tp + 0], ah0, ah1, ah2, ah3, bh0, bh1);
                MMA_BF16(acc[2 * tp + 0], ah0, ah1, ah2, ah3, bl0, bl1);
                MMA_BF16(acc[2 * tp + 0], al0, al1, al2, al3, bh0, bh1);
                MMA_BF16(acc[2 * tp + 1], ah0, ah1, ah2, ah3, bh2, bh3);
                MMA_BF16(acc[2 * tp + 1], ah0, ah1, ah2, ah3, bl2, bl3);
                MMA_BF16(acc[2 * tp + 1], al0, al1, al2, al3, bh2, bh3);
            }
        }
        __syncthreads();
    }

    {
        const int g  = lane >> 2;
        const int cx = 2 * (lane & 3);
#pragma unroll
        for (int t = 0; t < 8; t++) {
            const int col = nbase + 8 * t + cx;
            *reinterpret_cast<float2*>(&sOut[rt * 16 + g][col]) =
                make_float2(acc[t][0], acc[t][1]);
            *reinterpret_cast<float2*>(&sOut[rt * 16 + g + 8][col]) =
                make_float2(acc[t][2], acc[t][3]);
        }
    }
    __syncthreads();

    const float4 bv = reinterpret_cast<const float4*>(bias)[lane];
    const float4 gv = reinterpret_cast<const float4*>(gamma)[lane];
    const float4 be = reinterpret_cast<const float4*>(beta)[lane];

#pragma unroll
    for (int r = 0; r < 8; r++) {
        int rl = warp * 8 + r;
        float4 v = *reinterpret_cast<float4*>(&sOut[rl][lane * 4]);
        float hx = v.x + bv.x;
        float hy = v.y + bv.y;
        float hz = v.z + bv.z;
        float hw = v.w + bv.w;
        float s = hx + hy + hz + hw;
#pragma unroll
        for (int o = 16; o > 0; o >>= 1) s += __shfl_xor_sync(0xffffffffu, s, o);
        float mu = s * (1.0f / 128.0f);
        float dx = hx - mu, dy = hy - mu, dz = hz - mu, dw = hw - mu;
        float q = dx * dx + dy * dy + dz * dz + dw * dw;
#pragma unroll
        for (int o = 16; o > 0; o >>= 1) q += __shfl_xor_sync(0xffffffffu, q, o);
        float rstd = rsqrtf(q * (1.0f / 128.0f) + LN_EPS);

        float4 o4;
        o4.x = dx * rstd * gv.x + be.x;
        o4.y = dy * rstd * gv.y + be.y;
        o4.z = dz * rstd * gv.z + be.z;
        o4.w = dw * rstd * gv.w + be.w;
        if (RELU) {
            o4.x = fmaxf(o4.x, 0.0f);
            o4.y = fmaxf(o4.y, 0.0f);
            o4.z = fmaxf(o4.z, 0.0f);
            o4.w = fmaxf(o4.w, 0.0f);
        }
        int row = row0 + rl;
        if (row < n) {
            if (OUT_BF16) {
                float dvr = rsqrtf((float)(deg[row] + 1));
                __nv_bfloat162 p0 = __floats2bfloat162_rn(o4.x * dvr, o4.y * dvr);
                __nv_bfloat162 p1 = __floats2bfloat162_rn(o4.z * dvr, o4.w * dvr);
                uint2 u = make_uint2(*reinterpret_cast<uint32_t*>(&p0),
                                     *reinterpret_cast<uint32_t*>(&p1));
                reinterpret_cast<uint2*>((ushort_t*)outv + (size_t)row * 128)[lane] = u;
            } else {
                reinterpret_cast<float4*>((float*)outv + (size_t)row * 128)[lane] = o4;
            }
        }
    }
}

// ---------------- pooling (batch is sorted; count fused) ----------------
__global__ void k_pool_sum(const float* __restrict__ h, const int* __restrict__ batch,
                           float* __restrict__ gsum, int* __restrict__ gcnt, int n, int rpb) {
    int c  = threadIdx.x;
    int r0 = blockIdx.x * rpb;
    int r1 = min(r0 + rpb, n);
    if (r0 >= r1) return;
    float acc = 0.0f;
    int cnt = 0;
    int cur = batch[r0];
    for (int r = r0; r < r1; r++) {
        int g = batch[r];
        if (g != cur) {
            atomicAdd(&gsum[cur * HDIM + c], acc);
            if (c == 0) atomicAdd(&gcnt[cur], cnt);
            acc = 0.0f; cnt = 0; cur = g;
        }
        acc += h[(size_t)r * HDIM + c];
        cnt++;
    }
    atomicAdd(&gsum[cur * HDIM + c], acc);
    if (c == 0) atomicAdd(&gcnt[cur], cnt);
}

__global__ void k_finalize(const float* __restrict__ gsum, const int* __restrict__ gcnt,
                           float* __restrict__ out) {
    int i = blockIdx.x * blockDim.x + threadIdx.x;
    if (i >= NGRAPH * HDIM) return;
    float cnt = fmaxf((float)gcnt[i >> 7], 1.0f);
    out[i] = gsum[i] / cnt;
}

// ---------------- launch ----------------
extern "C" void kernel_launch(void* const* d_in, const int* in_sizes, int n_in,
                              void* d_out, int out_size) {
    const float* x     = (const float*)d_in[0];
    const int*   eidx  = (const int*)d_in[1];
    const int*   batch = (const int*)d_in[2];
    const float* W1 = (const float*)d_in[3];
    const float* b1 = (const float*)d_in[4];
    const float* g1 = (const float*)d_in[5];
    const float* be1 = (const float*)d_in[6];
    const float* W2 = (const float*)d_in[7];
    const float* b2 = (const float*)d_in[8];
    const float* g2 = (const float*)d_in[9];
    const float* be2 = (const float*)d_in[10];

    const int n = in_sizes[0] / FDIM;   // 100000
    const int e = in_sizes[1] / 2;      // 1600000
    const int* src = eidx;
    const int* dst = eidx + e;

    int*      ibuf;  cudaGetSymbolAddress((void**)&ibuf,  g_ibuf);
    int*      part;  cudaGetSymbolAddress((void**)&part,  g_partial);
    int*      bsum;  cudaGetSymbolAddress((void**)&bsum,  g_blocksum);
    int*      bpref; cudaGetSymbolAddress((void**)&bpref, g_blockpref);
    int*      csr;   cudaGetSymbolAddress((void**)&csr,   g_csr);
    ushort_t* xbf;   cudaGetSymbolAddress((void**)&xbf,   g_xbf);
    float*    bufa;  cudaGetSymbolAddress((void**)&bufa,  g_bufa);
    float*    bufb;  cudaGetSymbolAddress((void**)&bufb,  g_bufb);
    float*    pool;  cudaGetSymbolAddress((void**)&pool,  g_pool);
    ushort_t *w1h, *w1l, *w2h, *w2l;
    cudaGetSymbolAddress((void**)&w1h, g_w1h);
    cudaGetSymbolAddress((void**)&w1l, g_w1l);
    cudaGetSymbolAddress((void**)&w2h, g_w2h);
    cudaGetSymbolAddress((void**)&w2l, g_w2l);

    int* deg  = ibuf;
    int* cnt2 = ibuf + NPARTIAL;
    float* gsum = pool;
    int*   gcnt = (int*)(pool + NGRAPH * HDIM);

    const int T = 256;
    auto cdiv = [](int a, int b) { return (a + b - 1) / b; };
    const int B   = cdiv(n + 1, SCANW);
    const int nb  = cdiv(e, T);
    const int nx4 = n * FDIM / 4;                 // = 1.6M = e (shape coincidence)
    const int gB  = cdiv(n, 64);

    constexpr int SMEM1 = 2 * (64 * (FDIM + 8) * 2) + 2 * (128 * 40 * 2);  // 38912
    constexpr int SMEM2 = 2 * (64 * (HDIM + 8) * 2) + 2 * (128 * 40 * 2);  // 55296
    cudaFuncSetAttribute(k_mma_ln<FDIM, true, true>,
                         cudaFuncAttributeMaxDynamicSharedMemorySize, SMEM1);
    cudaFuncSetAttribute(k_mma_ln<HDIM, false, false>,
                         cudaFuncAttributeMaxDynamicSharedMemorySize, SMEM2);

    cudaMemsetAsync(ibuf, 0, sizeof(int) * (NPARTIAL + NNODES));
    cudaMemsetAsync(pool, 0, sizeof(float) * (NGRAPH * HDIM) + sizeof(int) * NGRAPH);

    // CSR build + W split; fill also prescales x into bf16 (tail blocks)
    k_count_prep<<<nb + 2, T>>>(dst, deg, e, nb, W1, W2, w1h, w1l, w2h, w2l);      // 1
    k_scan_block<<<B, SCANW>>>(deg, part, bsum, n);                                // 2
    k_fill<<<nb + cdiv(nx4, T), T>>>(src, dst, deg, part, bsum, B, bpref,
                                     cnt2, csr, e, nb, x, xbf);                    // 3

    // conv1: prescaled bf16 gather then tensor GEMM+LN+ReLU (dinv*h1 bf16 out)
    k_agg64<<<cdiv(n * 32, T), T>>>(xbf, deg, csr, part, bpref, bufa, n);          // 4 <- profiled
    k_mma_ln<FDIM, true, true><<<gB, T, SMEM1>>>(bufa, w1h, w1l, b1, g1, be1,
                                                 deg, (void*)bufb, n);             // 5

    // conv2: prescaled bf16 gather then tensor GEMM+LN (fp32 out)
    k_agg128<<<cdiv(n * 32, T), T>>>((const ushort_t*)bufb, deg, csr, part, bpref,
                                     bufa, n);                                     // 6
    k_mma_ln<HDIM, false, false><<<gB, T, SMEM2>>>(bufa, w2h, w2l, b2, g2, be2,
                                                   deg, (void*)bufb, n);           // 7

    // mean pool per graph (batch is sorted)
    const int rpb = 128;
    k_pool_sum<<<cdiv(n, rpb), HDIM>>>(bufb, batch, gsum, gcnt, n, rpb);           // 8
    k_finalize<<<cdiv(NGRAPH * HDIM, HDIM), HDIM>>>(gsum, gcnt, (float*)d_out);    // 9
}

// round 15
// speedup vs baseline: 1.4873x; 1.1561x over previous
#include <cuda_runtime.h>
#include <cuda_bf16.h>
#include <cstdint>

// Problem constants (shapes fixed by the dataset)
#define NNODES 100000
#define NEDGES 1600000
#define NGRAPH 128
#define HDIM   128
#define FDIM   64
#define LN_EPS 1e-5f

#define SCANW   1024
#define NSCANBLK ((NNODES + SCANW) / SCANW + 1)
#define NPARTIAL (NSCANBLK * SCANW)

typedef unsigned short ushort_t;

// ---------------- mma / ldmatrix (Ampere-path HMMA, legal on plain sm_100) --
#define LDSM4(r0, r1, r2, r3, addr) \
    asm volatile("ldmatrix.sync.aligned.m8n8.x4.shared.b16 {%0,%1,%2,%3}, [%4];" \
                 : "=r"(r0), "=r"(r1), "=r"(r2), "=r"(r3) : "r"(addr))

#define MMA_BF16(d, a0, a1, a2, a3, b0, b1) \
    asm volatile("mma.sync.aligned.m16n8k16.row.col.f32.bf16.bf16.f32 " \
                 "{%0,%1,%2,%3}, {%4,%5,%6,%7}, {%8,%9}, {%0,%1,%2,%3};" \
                 : "+f"(d[0]), "+f"(d[1]), "+f"(d[2]), "+f"(d[3]) \
                 : "r"(a0), "r"(a1), "r"(a2), "r"(a3), "r"(b0), "r"(b1))

__device__ __forceinline__ uint32_t smem_u32(const void* p) {
    uint32_t a;
    asm("{ .reg .u64 t; cvta.to.shared.u64 t, %1; cvt.u32.u64 %0, t; }" : "=r"(a) : "l"(p));
    return a;
}

__device__ __forceinline__ void red_add_v4(float* p, float4 v) {
    asm volatile("red.global.add.v4.f32 [%0], {%1,%2,%3,%4};"
                 :: "l"(p), "f"(v.x), "f"(v.y), "f"(v.z), "f"(v.w) : "memory");
}

// ---------------- scratch (device globals; no allocations allowed) ----------
__device__ int      g_ibuf[NPARTIAL + NNODES];      // deg + fill cursors (one memset)
__device__ int      g_partial[NPARTIAL];
__device__ int      g_blocksum[256];
__device__ int      g_blockpref[128];
__device__ int      g_csr[NEDGES];                  // src index only (feat prescaled)
__device__ ushort_t g_xbf[(size_t)NNODES * FDIM];   // dinv*x in bf16
__device__ float    g_bufa[(size_t)NNODES * HDIM];
__device__ float    g_bufb[(size_t)NNODES * HDIM];  // dinv*h1 bf16
__device__ float    g_pool[NGRAPH * HDIM + NGRAPH];
// W split images, chunk-major [chunk][n=128][40 k-slots] (k pad 32..39 zeroed)
__device__ ushort_t g_w1h[2 * 128 * 40], g_w1l[2 * 128 * 40];
__device__ ushort_t g_w2h[4 * 128 * 40], g_w2l[4 * 128 * 40];

// ---------------- degree count + W split (fused, tail blocks) ----------------
__device__ __forceinline__ void prep_w(const float* __restrict__ W, int K,
                                       ushort_t* __restrict__ wh, ushort_t* __restrict__ wl) {
    for (int idx = threadIdx.x; idx < K * 128; idx += 256) {
        int k = idx >> 7, nn = idx & 127;
        float v = W[idx];
        __nv_bfloat16 h = __float2bfloat16(v);
        __nv_bfloat16 l = __float2bfloat16(v - __bfloat162float(h));
        int off = (((k >> 5) * 128 + nn) * 40) + (k & 31);
        wh[off] = __bfloat16_as_ushort(h);
        wl[off] = __bfloat16_as_ushort(l);
    }
    for (int idx = threadIdx.x; idx < (K / 32) * 128 * 8; idx += 256) {
        int cn = idx >> 3;
        int off = cn * 40 + 32 + (idx & 7);
        wh[off] = 0; wl[off] = 0;
    }
}

__global__ void __launch_bounds__(256)
k_count_prep(const int* __restrict__ dst, int* __restrict__ deg, int e, int nb,
             const float* __restrict__ W1, const float* __restrict__ W2,
             ushort_t* w1h, ushort_t* w1l, ushort_t* w2h, ushort_t* w2l) {
    if ((int)blockIdx.x < nb) {
        int i = blockIdx.x * 256 + threadIdx.x;
        if (i < e) atomicAdd(&deg[dst[i]], 1);
        return;
    }
    if (blockIdx.x == (unsigned)nb) prep_w(W1, FDIM, w1h, w1l);
    else                            prep_w(W2, HDIM, w2h, w2l);
}

// ---------------- per-block exclusive scan (level 1) ----------------
__global__ void k_scan_block(const int* __restrict__ deg, int* __restrict__ partial,
                             int* __restrict__ blocksum, int n) {
    __shared__ int sm[2][SCANW];
    int t = threadIdx.x;
    int g = blockIdx.x * SCANW + t;
    int v = (g < n) ? deg[g] : 0;
    sm[0][t] = v;
    __syncthreads();
    int cur = 0;
#pragma unroll
    for (int off = 1; off < SCANW; off <<= 1) {
        int x = sm[cur][t];
        if (t >= off) x += sm[cur][t - off];
        sm[cur ^ 1][t] = x;
        __syncthreads();
        cur ^= 1;
    }
    int inc = sm[cur][t];
    partial[g] = inc - v;
    if (t == SCANW - 1) blocksum[blockIdx.x] = inc;
}

// Level-2 prefix computed in-block (<=128 scan blocks). All threads call it.
__device__ __forceinline__ void block_prefix(const int* __restrict__ bsum, int B,
                                             int* __restrict__ sbp) {
    __shared__ int tmp[128];
    int t = threadIdx.x;
    int v = 0;
    if (t < 128) { v = (t < B) ? bsum[t] : 0; tmp[t] = v; }
    __syncthreads();
#pragma unroll
    for (int off = 1; off < 128; off <<= 1) {
        int x = 0;
        if (t < 128) { x = tmp[t]; if (t >= off) x += tmp[t - off]; }
        __syncthreads();
        if (t < 128) tmp[t] = x;
        __syncthreads();
    }
    if (t < 128) sbp[t] = tmp[t] - v;   // exclusive
    __syncthreads();
}

// ---------------- CSR fill + publish prefix + x->bf16*dinv (tail) -----------
__global__ void __launch_bounds__(256)
k_fill(const int* __restrict__ src, const int* __restrict__ dst,
       const int* __restrict__ deg, const int* __restrict__ partial,
       const int* __restrict__ bsum, int B, int* __restrict__ bpref_g,
       int* __restrict__ cnt2, int* __restrict__ csr, int e, int nbf,
       const float* __restrict__ x, ushort_t* __restrict__ xbf, int nx4) {
    __shared__ int sbp[128];
    block_prefix(bsum, B, sbp);
    if ((int)blockIdx.x < nbf) {
        if (blockIdx.x == 0 && threadIdx.x < 128) bpref_g[threadIdx.x] = sbp[threadIdx.x];
        int i = blockIdx.x * blockDim.x + threadIdx.x;
        if (i >= e) return;
        int s = src[i];
        int d = dst[i];
        int pos = partial[d] + sbp[d >> 10] + atomicAdd(&cnt2[d], 1);
        csr[pos] = s;
        return;
    }
    // tail: xbf[row] = bf16( dinv[row] * x[row] )   (one float4 per thread)
    int idx = (blockIdx.x - nbf) * 256 + threadIdx.x;
    if (idx >= nx4) return;
    int row = idx >> 4;             // FDIM/4 = 16 float4 per row
    float dv = rsqrtf((float)(deg[row] + 1));
    float4 v = reinterpret_cast<const float4*>(x)[idx];
    __nv_bfloat162 p0 = __floats2bfloat162_rn(v.x * dv, v.y * dv);
    __nv_bfloat162 p1 = __floats2bfloat162_rn(v.z * dv, v.w * dv);
    uint2 u = make_uint2(*reinterpret_cast<uint32_t*>(&p0),
                         *reinterpret_cast<uint32_t*>(&p1));
    reinterpret_cast<uint2*>(xbf)[idx] = u;
}

// ---------------- gather aggregation: warp per dst node, prescaled bf16 -----
// out[v] = dinv[v] * ( sum_{s in N(v)} fs[s] + fs[v] ),  fs = dinv*feat (bf16)
__global__ void __launch_bounds__(256)
k_agg64(const ushort_t* __restrict__ featbf, const int* __restrict__ deg,
        const int* __restrict__ csr, const int* __restrict__ partial,
        const int* __restrict__ bpref, float* __restrict__ out, int n) {
    int w = (blockIdx.x * blockDim.x + threadIdx.x) >> 5;
    if (w >= n) return;
    int lane = threadIdx.x & 31;
    int r0 = partial[w] + bpref[w >> 10];
    int r1 = partial[w + 1] + bpref[(w + 1) >> 10];
    float dv = rsqrtf((float)(deg[w] + 1));

    const uint32_t* f32v = reinterpret_cast<const uint32_t*>(featbf);
    uint32_t su = f32v[(size_t)w * 32 + lane];
    float2 acc = __bfloat1622float2(*reinterpret_cast<__nv_bfloat162*>(&su));

    int r = r0;
    int pre = (4 - (r0 & 3)) & 3;
    if (pre > r1 - r0) pre = r1 - r0;
    for (int i = 0; i < pre; i++, r++) {
        uint32_t u0 = f32v[(size_t)csr[r] * 32 + lane];
        float2 v0 = __bfloat1622float2(*reinterpret_cast<__nv_bfloat162*>(&u0));
        acc.x += v0.x; acc.y += v0.y;
    }
    // 8-edge unrolled main loop (MLP 8)
    for (; r + 8 <= r1; r += 8) {
        int4 p = *reinterpret_cast<const int4*>(csr + r);
        int4 q = *reinterpret_cast<const int4*>(csr + r + 4);
        uint32_t u0 = f32v[(size_t)p.x * 32 + lane];
        uint32_t u1 = f32v[(size_t)p.y * 32 + lane];
        uint32_t u2 = f32v[(size_t)p.z * 32 + lane];
        uint32_t u3 = f32v[(size_t)p.w * 32 + lane];
        uint32_t u4 = f32v[(size_t)q.x * 32 + lane];
        uint32_t u5 = f32v[(size_t)q.y * 32 + lane];
        uint32_t u6 = f32v[(size_t)q.z * 32 + lane];
        uint32_t u7 = f32v[(size_t)q.w * 32 + lane];
        float2 v0 = __bfloat1622float2(*reinterpret_cast<__nv_bfloat162*>(&u0));
        float2 v1 = __bfloat1622float2(*reinterpret_cast<__nv_bfloat162*>(&u1));
        float2 v2 = __bfloat1622float2(*reinterpret_cast<__nv_bfloat162*>(&u2));
        float2 v3 = __bfloat1622float2(*reinterpret_cast<__nv_bfloat162*>(&u3));
        float2 v4 = __bfloat1622float2(*reinterpret_cast<__nv_bfloat162*>(&u4));
        float2 v5 = __bfloat1622float2(*reinterpret_cast<__nv_bfloat162*>(&u5));
        float2 v6 = __bfloat1622float2(*reinterpret_cast<__nv_bfloat162*>(&u6));
        float2 v7 = __bfloat1622float2(*reinterpret_cast<__nv_bfloat162*>(&u7));
        acc.x += v0.x; acc.y += v0.y;
        acc.x += v1.x; acc.y += v1.y;
        acc.x += v2.x; acc.y += v2.y;
        acc.x += v3.x; acc.y += v3.y;
        acc.x += v4.x; acc.y += v4.y;
        acc.x += v5.x; acc.y += v5.y;
        acc.x += v6.x; acc.y += v6.y;
        acc.x += v7.x; acc.y += v7.y;
    }
    if (r + 4 <= r1) {
        int4 p = *reinterpret_cast<const int4*>(csr + r);
        uint32_t u0 = f32v[(size_t)p.x * 32 + lane];
        uint32_t u1 = f32v[(size_t)p.y * 32 + lane];
        uint32_t u2 = f32v[(size_t)p.z * 32 + lane];
        uint32_t u3 = f32v[(size_t)p.w * 32 + lane];
        float2 v0 = __bfloat1622float2(*reinterpret_cast<__nv_bfloat162*>(&u0));
        float2 v1 = __bfloat1622float2(*reinterpret_cast<__nv_bfloat162*>(&u1));
        float2 v2 = __bfloat1622float2(*reinterpret_cast<__nv_bfloat162*>(&u2));
        float2 v3 = __bfloat1622float2(*reinterpret_cast<__nv_bfloat162*>(&u3));
        acc.x += v0.x; acc.y += v0.y;
        acc.x += v1.x; acc.y += v1.y;
        acc.x += v2.x; acc.y += v2.y;
        acc.x += v3.x; acc.y += v3.y;
        r += 4;
    }
    for (; r < r1; r++) {
        uint32_t u0 = f32v[(size_t)csr[r] * 32 + lane];
        float2 v0 = __bfloat1622float2(*reinterpret_cast<__nv_bfloat162*>(&u0));
        acc.x += v0.x; acc.y += v0.y;
    }
    acc.x *= dv; acc.y *= dv;
    reinterpret_cast<float2*>(out)[(size_t)w * 32 + lane] = acc;
}

__device__ __forceinline__ void bf4_unpack(uint2 u, float4& o) {
    float2 a = __bfloat1622float2(*reinterpret_cast<__nv_bfloat162*>(&u.x));
    float2 b = __bfloat1622float2(*reinterpret_cast<__nv_bfloat162*>(&u.y));
    o.x = a.x; o.y = a.y; o.z = b.x; o.w = b.y;
}
__device__ __forceinline__ void acc_add(float4& a, const float4& v) {
    a.x += v.x; a.y += v.y; a.z += v.z; a.w += v.w;
}

__global__ void __launch_bounds__(256)
k_agg128(const ushort_t* __restrict__ featbf, const int* __restrict__ deg,
         const int* __restrict__ csr, const int* __restrict__ partial,
         const int* __restrict__ bpref, float* __restrict__ out, int n) {
    int w = (blockIdx.x * blockDim.x + threadIdx.x) >> 5;
    if (w >= n) return;
    int lane = threadIdx.x & 31;
    int r0 = partial[w] + bpref[w >> 10];
    int r1 = partial[w + 1] + bpref[(w + 1) >> 10];
    float dv = rsqrtf((float)(deg[w] + 1));

    const uint2* f64v = reinterpret_cast<const uint2*>(featbf);
    float4 acc;
    bf4_unpack(f64v[(size_t)w * 32 + lane], acc);

    int r = r0;
    int pre = (4 - (r0 & 3)) & 3;
    if (pre > r1 - r0) pre = r1 - r0;
    for (int i = 0; i < pre; i++, r++) {
        float4 v0;
        bf4_unpack(f64v[(size_t)csr[r] * 32 + lane], v0);
        acc_add(acc, v0);
    }
    for (; r + 8 <= r1; r += 8) {
        int4 p = *reinterpret_cast<const int4*>(csr + r);
        int4 q = *reinterpret_cast<const int4*>(csr + r + 4);
        uint2 u0 = f64v[(size_t)p.x * 32 + lane];
        uint2 u1 = f64v[(size_t)p.y * 32 + lane];
        uint2 u2 = f64v[(size_t)p.z * 32 + lane];
        uint2 u3 = f64v[(size_t)p.w * 32 + lane];
        uint2 u4 = f64v[(size_t)q.x * 32 + lane];
        uint2 u5 = f64v[(size_t)q.y * 32 + lane];
        uint2 u6 = f64v[(size_t)q.z * 32 + lane];
        uint2 u7 = f64v[(size_t)q.w * 32 + lane];
        float4 v0, v1, v2, v3, v4, v5, v6, v7;
        bf4_unpack(u0, v0); bf4_unpack(u1, v1); bf4_unpack(u2, v2); bf4_unpack(u3, v3);
        bf4_unpack(u4, v4); bf4_unpack(u5, v5); bf4_unpack(u6, v6); bf4_unpack(u7, v7);
        acc_add(acc, v0); acc_add(acc, v1); acc_add(acc, v2); acc_add(acc, v3);
        acc_add(acc, v4); acc_add(acc, v5); acc_add(acc, v6); acc_add(acc, v7);
    }
    if (r + 4 <= r1) {
        int4 p = *reinterpret_cast<const int4*>(csr + r);
        uint2 u0 = f64v[(size_t)p.x * 32 + lane];
        uint2 u1 = f64v[(size_t)p.y * 32 + lane];
        uint2 u2 = f64v[(size_t)p.z * 32 + lane];
        uint2 u3 = f64v[(size_t)p.w * 32 + lane];
        float4 v0, v1, v2, v3;
        bf4_unpack(u0, v0); bf4_unpack(u1, v1); bf4_unpack(u2, v2); bf4_unpack(u3, v3);
        acc_add(acc, v0); acc_add(acc, v1); acc_add(acc, v2); acc_add(acc, v3);
        r += 4;
    }
    for (; r < r1; r++) {
        float4 v0;
        bf4_unpack(f64v[(size_t)csr[r] * 32 + lane], v0);
        acc_add(acc, v0);
    }
    acc.x *= dv; acc.y *= dv; acc.z *= dv; acc.w *= dv;
    reinterpret_cast<float4*>(out)[(size_t)w * 32 + lane] = acc;
}

// ---------------- tensor GEMM + bias + LN (+ReLU), 64 rows/block ------------
// OUT_BF16: store bf16 of dinv[row]*result (prescaled gather operand).
// POOL: mean-pool epilogue — accumulate rows into gsum/gcnt (batch sorted),
//       nothing written to outv.
template <int K, bool RELU, bool OUT_BF16, bool POOL>
__global__ void __launch_bounds__(256)
k_mma_ln(const float* __restrict__ in,
         const ushort_t* __restrict__ gWh, const ushort_t* __restrict__ gWl,
         const float* __restrict__ bias, const float* __restrict__ gamma,
         const float* __restrict__ beta, const int* __restrict__ deg,
         const int* __restrict__ batch, float* __restrict__ gsum,
         int* __restrict__ gcnt, void* __restrict__ outv, int n) {
    constexpr int ROWS   = 64;
    constexpr int XSTR   = K + 8;
    constexpr int NCH    = K / 32;
    constexpr int XBYTES = ROWS * XSTR * 2;
    constexpr int WBYTES = 128 * 40 * 2;

    extern __shared__ __align__(16) unsigned char sbuf[];
    ushort_t* sXh = (ushort_t*)sbuf;
    ushort_t* sXl = (ushort_t*)(sbuf + XBYTES);
    ushort_t* sWh = (ushort_t*)(sbuf + 2 * XBYTES);
    ushort_t* sWl = (ushort_t*)(sbuf + 2 * XBYTES + WBYTES);
    float (*sOut)[132] = (float (*)[132])sbuf;

    const int tid  = threadIdx.x;
    const int warp = tid >> 5;
    const int lane = tid & 31;
    const int row0 = blockIdx.x * ROWS;

    constexpr int NF4 = ROWS * K / 4;
#pragma unroll
    for (int idx = tid; idx < NF4; idx += 256) {
        int row = idx / (K / 4);
        int c4  = idx % (K / 4);
        float4 v = (row0 + row < n)
                 ? reinterpret_cast<const float4*>(in + (size_t)(row0 + row) * K)[c4]
                 : make_float4(0.f, 0.f, 0.f, 0.f);
        __nv_bfloat162 hp0 = __floats2bfloat162_rn(v.x, v.y);
        __nv_bfloat162 hp1 = __floats2bfloat162_rn(v.z, v.w);
        float2 hf0 = __bfloat1622float2(hp0);
        float2 hf1 = __bfloat1622float2(hp1);
        __nv_bfloat162 lp0 = __floats2bfloat162_rn(v.x - hf0.x, v.y - hf0.y);
        __nv_bfloat162 lp1 = __floats2bfloat162_rn(v.z - hf1.x, v.w - hf1.y);
        uint2 hu = make_uint2(*reinterpret_cast<uint32_t*>(&hp0),
                              *reinterpret_cast<uint32_t*>(&hp1));
        uint2 lu = make_uint2(*reinterpret_cast<uint32_t*>(&lp0),
                              *reinterpret_cast<uint32_t*>(&lp1));
        *reinterpret_cast<uint2*>(sXh + row * XSTR + c4 * 4) = hu;
        *reinterpret_cast<uint2*>(sXl + row * XSTR + c4 * 4) = lu;
    }

    const int rt    = warp & 3;
    const int nbase = (warp >> 2) * 64;
    const int a_row = rt * 16 + (lane & 7) + ((lane >> 3) & 1) * 8;
    const int a_k   = (lane >> 4) * 8;
    const uint32_t aH = smem_u32(sXh) + (uint32_t)(a_row * XSTR + a_k) * 2;
    const uint32_t aL = smem_u32(sXl) + (uint32_t)(a_row * XSTR + a_k) * 2;
    const int b_n = (lane & 7) + ((lane >> 4) & 1) * 8;
    const int b_k = ((lane >> 3) & 1) * 8;
    const uint32_t bHb = smem_u32(sWh) + (uint32_t)((nbase + b_n) * 40 + b_k) * 2;
    const uint32_t bLb = smem_u32(sWl) + (uint32_t)((nbase + b_n) * 40 + b_k) * 2;

    float acc[8][4];
#pragma unroll
    for (int t = 0; t < 8; t++)
#pragma unroll
        for (int c = 0; c < 4; c++) acc[t][c] = 0.0f;

#pragma unroll
    for (int c = 0; c < NCH; c++) {
        {
            const uint4* srcH = reinterpret_cast<const uint4*>(gWh + c * 5120);
            const uint4* srcL = reinterpret_cast<const uint4*>(gWl + c * 5120);
            uint4* dH = reinterpret_cast<uint4*>(sWh);
            uint4* dL = reinterpret_cast<uint4*>(sWl);
#pragma unroll
            for (int i = tid; i < 640; i += 256) { dH[i] = srcH[i]; dL[i] = srcL[i]; }
        }
        __syncthreads();

#pragma unroll
        for (int ks = 0; ks < 2; ks++) {
            const uint32_t ko = (uint32_t)(c * 32 + ks * 16) * 2;
            const uint32_t kc = (uint32_t)(ks * 16) * 2;
            uint32_t ah0, ah1, ah2, ah3, al0, al1, al2, al3;
            LDSM4(ah0, ah1, ah2, ah3, aH + ko);
            LDSM4(al0, al1, al2, al3, aL + ko);
#pragma unroll
            for (int tp = 0; tp < 4; tp++) {
                const uint32_t off = (uint32_t)(tp * 16 * 40 * 2) + kc;
                uint32_t bh0, bh1, bh2, bh3, bl0, bl1, bl2, bl3;
                LDSM4(bh0, bh1, bh2, bh3, bHb + off);
                LDSM4(bl0, bl1, bl2, bl3, bLb + off);
                MMA_BF16(acc[2 * tp + 0], ah0, ah1, ah2, ah3, bh0, bh1);
                MMA_BF16(acc[2 * tp + 0], ah0, ah1, ah2, ah3, bl0, bl1);
                MMA_BF16(acc[2 * tp + 0], al0, al1, al2, al3, bh0, bh1);
                MMA_BF16(acc[2 * tp + 1], ah0, ah1, ah2, ah3, bh2, bh3);
                MMA_BF16(acc[2 * tp + 1], ah0, ah1, ah2, ah3, bl2, bl3);
                MMA_BF16(acc[2 * tp + 1], al0, al1, al2, al3, bh2, bh3);
            }
        }
        __syncthreads();
    }

    {
        const int g  = lane >> 2;
        const int cx = 2 * (lane & 3);
#pragma unroll
        for (int t = 0; t < 8; t++) {
            const int col = nbase + 8 * t + cx;
            *reinterpret_cast<float2*>(&sOut[rt * 16 + g][col]) =
                make_float2(acc[t][0], acc[t][1]);
            *reinterpret_cast<float2*>(&sOut[rt * 16 + g + 8][col]) =
                make_float2(acc[t][2], acc[t][3]);
        }
    }
    __syncthreads();

    const float4 bv = reinterpret_cast<const float4*>(bias)[lane];
    const float4 gv = reinterpret_cast<const float4*>(gamma)[lane];
    const float4 be = reinterpret_cast<const float4*>(beta)[lane];

    // POOL state (batch sorted -> run accumulation per warp over its 8 rows)
    float4 psum = make_float4(0.f, 0.f, 0.f, 0.f);
    int pcnt = 0;
    int pcur = -1;

#pragma unroll
    for (int r = 0; r < 8; r++) {
        int rl = warp * 8 + r;
        int row = row0 + rl;
        float4 v = *reinterpret_cast<float4*>(&sOut[rl][lane * 4]);
        float hx = v.x + bv.x;
        float hy = v.y + bv.y;
        float hz = v.z + bv.z;
        float hw = v.w + bv.w;
        float s = hx + hy + hz + hw;
#pragma unroll
        for (int o = 16; o > 0; o >>= 1) s += __shfl_xor_sync(0xffffffffu, s, o);
        float mu = s * (1.0f / 128.0f);
        float dx = hx - mu, dy = hy - mu, dz = hz - mu, dw = hw - mu;
        float q = dx * dx + dy * dy + dz * dz + dw * dw;
#pragma unroll
        for (int o = 16; o > 0; o >>= 1) q += __shfl_xor_sync(0xffffffffu, q, o);
        float rstd = rsqrtf(q * (1.0f / 128.0f) + LN_EPS);

        float4 o4;
        o4.x = dx * rstd * gv.x + be.x;
        o4.y = dy * rstd * gv.y + be.y;
        o4.z = dz * rstd * gv.z + be.z;
        o4.w = dw * rstd * gv.w + be.w;
        if (RELU) {
            o4.x = fmaxf(o4.x, 0.0f);
            o4.y = fmaxf(o4.y, 0.0f);
            o4.z = fmaxf(o4.z, 0.0f);
            o4.w = fmaxf(o4.w, 0.0f);
        }
        if (row < n) {
            if (POOL) {
                int g = batch[row];
                if (g != pcur) {
                    if (pcnt > 0) {
                        red_add_v4(gsum + pcur * HDIM + lane * 4, psum);
                        if (lane == 0) atomicAdd(&gcnt[pcur], pcnt);
                    }
                    pcur = g;
                    psum = make_float4(0.f, 0.f, 0.f, 0.f);
                    pcnt = 0;
                }
                psum.x += o4.x; psum.y += o4.y; psum.z += o4.z; psum.w += o4.w;
                pcnt++;
            } else if (OUT_BF16) {
                float dvr = rsqrtf((float)(deg[row] + 1));
                __nv_bfloat162 p0 = __floats2bfloat162_rn(o4.x * dvr, o4.y * dvr);
                __nv_bfloat162 p1 = __floats2bfloat162_rn(o4.z * dvr, o4.w * dvr);
                uint2 u = make_uint2(*reinterpret_cast<uint32_t*>(&p0),
                                     *reinterpret_cast<uint32_t*>(&p1));
                reinterpret_cast<uint2*>((ushort_t*)outv + (size_t)row * 128)[lane] = u;
            } else {
                reinterpret_cast<float4*>((float*)outv + (size_t)row * 128)[lane] = o4;
            }
        }
    }
    if (POOL && pcnt > 0) {
        red_add_v4(gsum + pcur * HDIM + lane * 4, psum);
        if (lane == 0) atomicAdd(&gcnt[pcur], pcnt);
    }
}

__global__ void k_finalize(const float* __restrict__ gsum, const int* __restrict__ gcnt,
                           float* __restrict__ out) {
    int i = blockIdx.x * blockDim.x + threadIdx.x;
    if (i >= NGRAPH * HDIM) return;
    float cnt = fmaxf((float)gcnt[i >> 7], 1.0f);
    out[i] = gsum[i] / cnt;
}

// ---------------- launch ----------------
extern "C" void kernel_launch(void* const* d_in, const int* in_sizes, int n_in,
                              void* d_out, int out_size) {
    const float* x     = (const float*)d_in[0];
    const int*   eidx  = (const int*)d_in[1];
    const int*   batch = (const int*)d_in[2];
    const float* W1 = (const float*)d_in[3];
    const float* b1 = (const float*)d_in[4];
    const float* g1 = (const float*)d_in[5];
    const float* be1 = (const float*)d_in[6];
    const float* W2 = (const float*)d_in[7];
    const float* b2 = (const float*)d_in[8];
    const float* g2 = (const float*)d_in[9];
    const float* be2 = (const float*)d_in[10];

    const int n = in_sizes[0] / FDIM;   // 100000
    const int e = in_sizes[1] / 2;      // 1600000
    const int* src = eidx;
    const int* dst = eidx + e;

    int*      ibuf;  cudaGetSymbolAddress((void**)&ibuf,  g_ibuf);
    int*      part;  cudaGetSymbolAddress((void**)&part,  g_partial);
    int*      bsum;  cudaGetSymbolAddress((void**)&bsum,  g_blocksum);
    int*      bpref; cudaGetSymbolAddress((void**)&bpref, g_blockpref);
    int*      csr;   cudaGetSymbolAddress((void**)&csr,   g_csr);
    ushort_t* xbf;   cudaGetSymbolAddress((void**)&xbf,   g_xbf);
    float*    bufa;  cudaGetSymbolAddress((void**)&bufa,  g_bufa);
    float*    bufb;  cudaGetSymbolAddress((void**)&bufb,  g_bufb);
    float*    pool;  cudaGetSymbolAddress((void**)&pool,  g_pool);
    ushort_t *w1h, *w1l, *w2h, *w2l;
    cudaGetSymbolAddress((void**)&w1h, g_w1h);
    cudaGetSymbolAddress((void**)&w1l, g_w1l);
    cudaGetSymbolAddress((void**)&w2h, g_w2h);
    cudaGetSymbolAddress((void**)&w2l, g_w2l);

    int* deg  = ibuf;
    int* cnt2 = ibuf + NPARTIAL;
    float* gsum = pool;
    int*   gcnt = (int*)(pool + NGRAPH * HDIM);

    const int T = 256;
    auto cdiv = [](int a, int b) { return (a + b - 1) / b; };
    const int B   = cdiv(n + 1, SCANW);
    const int nb  = cdiv(e, T);
    const int nx4 = n * FDIM / 4;
    const int gB  = cdiv(n, 64);

    constexpr int SMEM1 = 2 * (64 * (FDIM + 8) * 2) + 2 * (128 * 40 * 2);  // 38912
    constexpr int SMEM2 = 2 * (64 * (HDIM + 8) * 2) + 2 * (128 * 40 * 2);  // 55296
    cudaFuncSetAttribute(k_mma_ln<FDIM, true, true, false>,
                         cudaFuncAttributeMaxDynamicSharedMemorySize, SMEM1);
    cudaFuncSetAttribute(k_mma_ln<HDIM, false, false, true>,
                         cudaFuncAttributeMaxDynamicSharedMemorySize, SMEM2);

    cudaMemsetAsync(ibuf, 0, sizeof(int) * (NPARTIAL + NNODES));
    cudaMemsetAsync(pool, 0, sizeof(float) * (NGRAPH * HDIM) + sizeof(int) * NGRAPH);

    // CSR build + W split; fill also prescales x into bf16 (tail blocks)
    k_count_prep<<<nb + 2, T>>>(dst, deg, e, nb, W1, W2, w1h, w1l, w2h, w2l);      // 1
    k_scan_block<<<B, SCANW>>>(deg, part, bsum, n);                                // 2
    k_fill<<<nb + cdiv(nx4, T), T>>>(src, dst, deg, part, bsum, B, bpref,
                                     cnt2, csr, e, nb, x, xbf, nx4);               // 3

    // conv1: prescaled bf16 gather then tensor GEMM+LN+ReLU (dinv*h1 bf16 out)
    k_agg64<<<cdiv(n * 32, T), T>>>(xbf, deg, csr, part, bpref, bufa, n);          // 4 <- profiled
    k_mma_ln<FDIM, true, true, false><<<gB, T, SMEM1>>>(bufa, w1h, w1l, b1, g1, be1,
                                                        deg, nullptr, nullptr,
                                                        nullptr, (void*)bufb, n);  // 5

    // conv2: prescaled bf16 gather then tensor GEMM+LN with FUSED mean-pool
    k_agg128<<<cdiv(n * 32, T), T>>>((const ushort_t*)bufb, deg, csr, part, bpref,
                                     bufa, n);                                     // 6
    k_mma_ln<HDIM, false, false, true><<<gB, T, SMEM2>>>(bufa, w2h, w2l, b2, g2, be2,
                                                         deg, batch, gsum, gcnt,
                                                         nullptr, n);              // 7

    k_finalize<<<cdiv(NGRAPH * HDIM, HDIM), HDIM>>>(gsum, gcnt, (float*)d_out);    // 8
}

// round 16
// speedup vs baseline: 1.6711x; 1.1236x over previous
#include <cuda_runtime.h>
#include <cuda_bf16.h>
#include <cstdint>

// Problem constants (shapes fixed by the dataset)
#define NNODES 100000
#define NEDGES 1600000
#define NGRAPH 128
#define HDIM   128
#define FDIM   64
#define LN_EPS 1e-5f

#define SCANW   1024
#define NSCANBLK ((NNODES + SCANW) / SCANW + 1)
#define NPARTIAL (NSCANBLK * SCANW)

typedef unsigned short ushort_t;

// ---------------- mma / ldmatrix (Ampere-path HMMA, legal on plain sm_100) --
#define LDSM4(r0, r1, r2, r3, addr) \
    asm volatile("ldmatrix.sync.aligned.m8n8.x4.shared.b16 {%0,%1,%2,%3}, [%4];" \
                 : "=r"(r0), "=r"(r1), "=r"(r2), "=r"(r3) : "r"(addr))

#define MMA_BF16(d, a0, a1, a2, a3, b0, b1) \
    asm volatile("mma.sync.aligned.m16n8k16.row.col.f32.bf16.bf16.f32 " \
                 "{%0,%1,%2,%3}, {%4,%5,%6,%7}, {%8,%9}, {%0,%1,%2,%3};" \
                 : "+f"(d[0]), "+f"(d[1]), "+f"(d[2]), "+f"(d[3]) \
                 : "r"(a0), "r"(a1), "r"(a2), "r"(a3), "r"(b0), "r"(b1))

__device__ __forceinline__ uint32_t smem_u32(const void* p) {
    uint32_t a;
    asm("{ .reg .u64 t; cvta.to.shared.u64 t, %1; cvt.u32.u64 %0, t; }" : "=r"(a) : "l"(p));
    return a;
}

__device__ __forceinline__ void red_add_v4(float* p, float4 v) {
    asm volatile("red.global.add.v4.f32 [%0], {%1,%2,%3,%4};"
                 :: "l"(p), "f"(v.x), "f"(v.y), "f"(v.z), "f"(v.w) : "memory");
}

// ---------------- scratch (device globals; no allocations allowed) ----------
__device__ int      g_ibuf[NPARTIAL + NNODES];      // deg + fill cursors (one memset)
__device__ int      g_partial[NPARTIAL];
__device__ int      g_blocksum[256];
__device__ int      g_blockpref[128];
__device__ int      g_csr[NEDGES];                  // src*32 (prescaled word offset)
__device__ ushort_t g_xbf[(size_t)NNODES * FDIM];   // dinv*x in bf16
__device__ float    g_bufa[(size_t)NNODES * HDIM];
__device__ float    g_bufb[(size_t)NNODES * HDIM];  // dinv*h1 bf16
__device__ float    g_pool[NGRAPH * HDIM + NGRAPH];
// W split images, chunk-major [chunk][n=128][40 k-slots] (k pad 32..39 zeroed)
__device__ ushort_t g_w1h[2 * 128 * 40], g_w1l[2 * 128 * 40];
__device__ ushort_t g_w2h[4 * 128 * 40], g_w2l[4 * 128 * 40];

// ---------------- degree count + W split (striped over 8 blocks each) -------
#define WPREP_BLKS 8
__device__ __forceinline__ void prep_w(const float* __restrict__ W, int K,
                                       ushort_t* __restrict__ wh, ushort_t* __restrict__ wl,
                                       int part) {
    for (int idx = part * 256 + threadIdx.x; idx < K * 128; idx += 256 * WPREP_BLKS) {
        int k = idx >> 7, nn = idx & 127;
        float v = W[idx];
        __nv_bfloat16 h = __float2bfloat16(v);
        __nv_bfloat16 l = __float2bfloat16(v - __bfloat162float(h));
        int off = (((k >> 5) * 128 + nn) * 40) + (k & 31);
        wh[off] = __bfloat16_as_ushort(h);
        wl[off] = __bfloat16_as_ushort(l);
    }
    for (int idx = part * 256 + threadIdx.x; idx < (K / 32) * 128 * 8; idx += 256 * WPREP_BLKS) {
        int cn = idx >> 3;
        int off = cn * 40 + 32 + (idx & 7);
        wh[off] = 0; wl[off] = 0;
    }
}

__global__ void __launch_bounds__(256)
k_count_prep(const int* __restrict__ dst, int* __restrict__ deg, int e, int nb,
             const float* __restrict__ W1, const float* __restrict__ W2,
             ushort_t* w1h, ushort_t* w1l, ushort_t* w2h, ushort_t* w2l) {
    if ((int)blockIdx.x < nb) {
        int i = blockIdx.x * 256 + threadIdx.x;
        if (i < e) atomicAdd(&deg[dst[i]], 1);
        return;
    }
    int t = blockIdx.x - nb;
    if (t < WPREP_BLKS) prep_w(W1, FDIM, w1h, w1l, t);
    else                prep_w(W2, HDIM, w2h, w2l, t - WPREP_BLKS);
}

// ---------------- per-block exclusive scan (level 1) ----------------
__global__ void k_scan_block(const int* __restrict__ deg, int* __restrict__ partial,
                             int* __restrict__ blocksum, int n) {
    __shared__ int sm[2][SCANW];
    int t = threadIdx.x;
    int g = blockIdx.x * SCANW + t;
    int v = (g < n) ? deg[g] : 0;
    sm[0][t] = v;
    __syncthreads();
    int cur = 0;
#pragma unroll
    for (int off = 1; off < SCANW; off <<= 1) {
        int x = sm[cur][t];
        if (t >= off) x += sm[cur][t - off];
        sm[cur ^ 1][t] = x;
        __syncthreads();
        cur ^= 1;
    }
    int inc = sm[cur][t];
    partial[g] = inc - v;
    if (t == SCANW - 1) blocksum[blockIdx.x] = inc;
}

// Level-2 prefix computed in-block (<=128 scan blocks). All threads call it.
__device__ __forceinline__ void block_prefix(const int* __restrict__ bsum, int B,
                                             int* __restrict__ sbp) {
    __shared__ int tmp[128];
    int t = threadIdx.x;
    int v = 0;
    if (t < 128) { v = (t < B) ? bsum[t] : 0; tmp[t] = v; }
    __syncthreads();
#pragma unroll
    for (int off = 1; off < 128; off <<= 1) {
        int x = 0;
        if (t < 128) { x = tmp[t]; if (t >= off) x += tmp[t - off]; }
        __syncthreads();
        if (t < 128) tmp[t] = x;
        __syncthreads();
    }
    if (t < 128) sbp[t] = tmp[t] - v;   // exclusive
    __syncthreads();
}

// ---------------- CSR fill + publish prefix + x->bf16*dinv (tail) -----------
__global__ void __launch_bounds__(256)
k_fill(const int* __restrict__ src, const int* __restrict__ dst,
       const int* __restrict__ deg, const int* __restrict__ partial,
       const int* __restrict__ bsum, int B, int* __restrict__ bpref_g,
       int* __restrict__ cnt2, int* __restrict__ csr, int e, int nbf,
       const float* __restrict__ x, ushort_t* __restrict__ xbf, int nx4) {
    __shared__ int sbp[128];
    block_prefix(bsum, B, sbp);
    if ((int)blockIdx.x < nbf) {
        if (blockIdx.x == 0 && threadIdx.x < 128) bpref_g[threadIdx.x] = sbp[threadIdx.x];
        int i = blockIdx.x * blockDim.x + threadIdx.x;
        if (i >= e) return;
        int s = src[i];
        int d = dst[i];
        int pos = partial[d] + sbp[d >> 10] + atomicAdd(&cnt2[d], 1);
        csr[pos] = s << 5;            // prescaled word offset (row stride 32)
        return;
    }
    // tail: xbf[row] = bf16( dinv[row] * x[row] )   (one float4 per thread)
    int idx = (blockIdx.x - nbf) * 256 + threadIdx.x;
    if (idx >= nx4) return;
    int row = idx >> 4;             // FDIM/4 = 16 float4 per row
    float dv = rsqrtf((float)(deg[row] + 1));
    float4 v = reinterpret_cast<const float4*>(x)[idx];
    __nv_bfloat162 p0 = __floats2bfloat162_rn(v.x * dv, v.y * dv);
    __nv_bfloat162 p1 = __floats2bfloat162_rn(v.z * dv, v.w * dv);
    uint2 u = make_uint2(*reinterpret_cast<uint32_t*>(&p0),
                         *reinterpret_cast<uint32_t*>(&p1));
    reinterpret_cast<uint2*>(xbf)[idx] = u;
}

// ---------------- gather aggregation: warp per dst node, prescaled bf16 -----
// out[v] = dinv[v] * ( sum_{s in N(v)} fs[s] + fs[v] ),  fs = dinv*feat (bf16)
// csr holds src*32 -> per-edge address = single IADD with lane.
__global__ void __launch_bounds__(256)
k_agg64(const ushort_t* __restrict__ featbf, const int* __restrict__ deg,
        const int* __restrict__ csr, const int* __restrict__ partial,
        const int* __restrict__ bpref, float* __restrict__ out, int n) {
    int w = (blockIdx.x * blockDim.x + threadIdx.x) >> 5;
    if (w >= n) return;
    int lane = threadIdx.x & 31;
    int r0 = partial[w] + bpref[w >> 10];
    int r1 = partial[w + 1] + bpref[(w + 1) >> 10];
    float dv = rsqrtf((float)(deg[w] + 1));

    const uint32_t* f32v = reinterpret_cast<const uint32_t*>(featbf) + lane;
    uint32_t su = f32v[(unsigned)w * 32u];
    float2 acc = __bfloat1622float2(*reinterpret_cast<__nv_bfloat162*>(&su));

    int r = r0;
    int pre = (4 - (r0 & 3)) & 3;
    if (pre > r1 - r0) pre = r1 - r0;
    for (int i = 0; i < pre; i++, r++) {
        uint32_t u0 = f32v[(unsigned)csr[r]];
        float2 v0 = __bfloat1622float2(*reinterpret_cast<__nv_bfloat162*>(&u0));
        acc.x += v0.x; acc.y += v0.y;
    }
    // 8-edge unrolled main loop (MLP 8)
    for (; r + 8 <= r1; r += 8) {
        int4 p = *reinterpret_cast<const int4*>(csr + r);
        int4 q = *reinterpret_cast<const int4*>(csr + r + 4);
        uint32_t u0 = f32v[(unsigned)p.x];
        uint32_t u1 = f32v[(unsigned)p.y];
        uint32_t u2 = f32v[(unsigned)p.z];
        uint32_t u3 = f32v[(unsigned)p.w];
        uint32_t u4 = f32v[(unsigned)q.x];
        uint32_t u5 = f32v[(unsigned)q.y];
        uint32_t u6 = f32v[(unsigned)q.z];
        uint32_t u7 = f32v[(unsigned)q.w];
        float2 v0 = __bfloat1622float2(*reinterpret_cast<__nv_bfloat162*>(&u0));
        float2 v1 = __bfloat1622float2(*reinterpret_cast<__nv_bfloat162*>(&u1));
        float2 v2 = __bfloat1622float2(*reinterpret_cast<__nv_bfloat162*>(&u2));
        float2 v3 = __bfloat1622float2(*reinterpret_cast<__nv_bfloat162*>(&u3));
        float2 v4 = __bfloat1622float2(*reinterpret_cast<__nv_bfloat162*>(&u4));
        float2 v5 = __bfloat1622float2(*reinterpret_cast<__nv_bfloat162*>(&u5));
        float2 v6 = __bfloat1622float2(*reinterpret_cast<__nv_bfloat162*>(&u6));
        float2 v7 = __bfloat1622float2(*reinterpret_cast<__nv_bfloat162*>(&u7));
        acc.x += v0.x; acc.y += v0.y;
        acc.x += v1.x; acc.y += v1.y;
        acc.x += v2.x; acc.y += v2.y;
        acc.x += v3.x; acc.y += v3.y;
        acc.x += v4.x; acc.y += v4.y;
        acc.x += v5.x; acc.y += v5.y;
        acc.x += v6.x; acc.y += v6.y;
        acc.x += v7.x; acc.y += v7.y;
    }
    if (r + 4 <= r1) {
        int4 p = *reinterpret_cast<const int4*>(csr + r);
        uint32_t u0 = f32v[(unsigned)p.x];
        uint32_t u1 = f32v[(unsigned)p.y];
        uint32_t u2 = f32v[(unsigned)p.z];
        uint32_t u3 = f32v[(unsigned)p.w];
        float2 v0 = __bfloat1622float2(*reinterpret_cast<__nv_bfloat162*>(&u0));
        float2 v1 = __bfloat1622float2(*reinterpret_cast<__nv_bfloat162*>(&u1));
        float2 v2 = __bfloat1622float2(*reinterpret_cast<__nv_bfloat162*>(&u2));
        float2 v3 = __bfloat1622float2(*reinterpret_cast<__nv_bfloat162*>(&u3));
        acc.x += v0.x; acc.y += v0.y;
        acc.x += v1.x; acc.y += v1.y;
        acc.x += v2.x; acc.y += v2.y;
        acc.x += v3.x; acc.y += v3.y;
        r += 4;
    }
    for (; r < r1; r++) {
        uint32_t u0 = f32v[(unsigned)csr[r]];
        float2 v0 = __bfloat1622float2(*reinterpret_cast<__nv_bfloat162*>(&u0));
        acc.x += v0.x; acc.y += v0.y;
    }
    acc.x *= dv; acc.y *= dv;
    reinterpret_cast<float2*>(out)[(size_t)w * 32 + lane] = acc;
}

__device__ __forceinline__ void bf4_unpack(uint2 u, float4& o) {
    float2 a = __bfloat1622float2(*reinterpret_cast<__nv_bfloat162*>(&u.x));
    float2 b = __bfloat1622float2(*reinterpret_cast<__nv_bfloat162*>(&u.y));
    o.x = a.x; o.y = a.y; o.z = b.x; o.w = b.y;
}
__device__ __forceinline__ void acc_add(float4& a, const float4& v) {
    a.x += v.x; a.y += v.y; a.z += v.z; a.w += v.w;
}

__global__ void __launch_bounds__(256)
k_agg128(const ushort_t* __restrict__ featbf, const int* __restrict__ deg,
         const int* __restrict__ csr, const int* __restrict__ partial,
         const int* __restrict__ bpref, float* __restrict__ out, int n) {
    int w = (blockIdx.x * blockDim.x + threadIdx.x) >> 5;
    if (w >= n) return;
    int lane = threadIdx.x & 31;
    int r0 = partial[w] + bpref[w >> 10];
    int r1 = partial[w + 1] + bpref[(w + 1) >> 10];
    float dv = rsqrtf((float)(deg[w] + 1));

    const uint2* f64v = reinterpret_cast<const uint2*>(featbf) + lane;
    float4 acc;
    bf4_unpack(f64v[(unsigned)w * 32u], acc);

    int r = r0;
    int pre = (4 - (r0 & 3)) & 3;
    if (pre > r1 - r0) pre = r1 - r0;
    for (int i = 0; i < pre; i++, r++) {
        float4 v0;
        bf4_unpack(f64v[(unsigned)csr[r]], v0);
        acc_add(acc, v0);
    }
    for (; r + 8 <= r1; r += 8) {
        int4 p = *reinterpret_cast<const int4*>(csr + r);
        int4 q = *reinterpret_cast<const int4*>(csr + r + 4);
        uint2 u0 = f64v[(unsigned)p.x];
        uint2 u1 = f64v[(unsigned)p.y];
        uint2 u2 = f64v[(unsigned)p.z];
        uint2 u3 = f64v[(unsigned)p.w];
        uint2 u4 = f64v[(unsigned)q.x];
        uint2 u5 = f64v[(unsigned)q.y];
        uint2 u6 = f64v[(unsigned)q.z];
        uint2 u7 = f64v[(unsigned)q.w];
        float4 v0, v1, v2, v3, v4, v5, v6, v7;
        bf4_unpack(u0, v0); bf4_unpack(u1, v1); bf4_unpack(u2, v2); bf4_unpack(u3, v3);
        bf4_unpack(u4, v4); bf4_unpack(u5, v5); bf4_unpack(u6, v6); bf4_unpack(u7, v7);
        acc_add(acc, v0); acc_add(acc, v1); acc_add(acc, v2); acc_add(acc, v3);
        acc_add(acc, v4); acc_add(acc, v5); acc_add(acc, v6); acc_add(acc, v7);
    }
    if (r + 4 <= r1) {
        int4 p = *reinterpret_cast<const int4*>(csr + r);
        uint2 u0 = f64v[(unsigned)p.x];
        uint2 u1 = f64v[(unsigned)p.y];
        uint2 u2 = f64v[(unsigned)p.z];
        uint2 u3 = f64v[(unsigned)p.w];
        float4 v0, v1, v2, v3;
        bf4_unpack(u0, v0); bf4_unpack(u1, v1); bf4_unpack(u2, v2); bf4_unpack(u3, v3);
        acc_add(acc, v0); acc_add(acc, v1); acc_add(acc, v2); acc_add(acc, v3);
        r += 4;
    }
    for (; r < r1; r++) {
        float4 v0;
        bf4_unpack(f64v[(unsigned)csr[r]], v0);
        acc_add(acc, v0);
    }
    acc.x *= dv; acc.y *= dv; acc.z *= dv; acc.w *= dv;
    reinterpret_cast<float4*>(out)[(size_t)w * 32 + lane] = acc;
}

// ---------------- tensor GEMM + bias + LN (+ReLU), 64 rows/block ------------
// OUT_BF16: store bf16 of dinv[row]*result (prescaled gather operand).
// POOL: mean-pool epilogue — accumulate rows into gsum/gcnt (batch sorted).
template <int K, bool RELU, bool OUT_BF16, bool POOL>
__global__ void __launch_bounds__(256)
k_mma_ln(const float* __restrict__ in,
         const ushort_t* __restrict__ gWh, const ushort_t* __restrict__ gWl,
         const float* __restrict__ bias, const float* __restrict__ gamma,
         const float* __restrict__ beta, const int* __restrict__ deg,
         const int* __restrict__ batch, float* __restrict__ gsum,
         int* __restrict__ gcnt, void* __restrict__ outv, int n) {
    constexpr int ROWS   = 64;
    constexpr int XSTR   = K + 8;
    constexpr int NCH    = K / 32;
    constexpr int XBYTES = ROWS * XSTR * 2;
    constexpr int WBYTES = 128 * 40 * 2;

    extern __shared__ __align__(16) unsigned char sbuf[];
    ushort_t* sXh = (ushort_t*)sbuf;
    ushort_t* sXl = (ushort_t*)(sbuf + XBYTES);
    ushort_t* sWh = (ushort_t*)(sbuf + 2 * XBYTES);
    ushort_t* sWl = (ushort_t*)(sbuf + 2 * XBYTES + WBYTES);
    float (*sOut)[132] = (float (*)[132])sbuf;

    const int tid  = threadIdx.x;
    const int warp = tid >> 5;
    const int lane = tid & 31;
    const int row0 = blockIdx.x * ROWS;

    constexpr int NF4 = ROWS * K / 4;
#pragma unroll
    for (int idx = tid; idx < NF4; idx += 256) {
        int row = idx / (K / 4);
        int c4  = idx % (K / 4);
        float4 v = (row0 + row < n)
                 ? reinterpret_cast<const float4*>(in + (size_t)(row0 + row) * K)[c4]
                 : make_float4(0.f, 0.f, 0.f, 0.f);
        __nv_bfloat162 hp0 = __floats2bfloat162_rn(v.x, v.y);
        __nv_bfloat162 hp1 = __floats2bfloat162_rn(v.z, v.w);
        float2 hf0 = __bfloat1622float2(hp0);
        float2 hf1 = __bfloat1622float2(hp1);
        __nv_bfloat162 lp0 = __floats2bfloat162_rn(v.x - hf0.x, v.y - hf0.y);
        __nv_bfloat162 lp1 = __floats2bfloat162_rn(v.z - hf1.x, v.w - hf1.y);
        uint2 hu = make_uint2(*reinterpret_cast<uint32_t*>(&hp0),
                              *reinterpret_cast<uint32_t*>(&hp1));
        uint2 lu = make_uint2(*reinterpret_cast<uint32_t*>(&lp0),
                              *reinterpret_cast<uint32_t*>(&lp1));
        *reinterpret_cast<uint2*>(sXh + row * XSTR + c4 * 4) = hu;
        *reinterpret_cast<uint2*>(sXl + row * XSTR + c4 * 4) = lu;
    }

    const int rt    = warp & 3;
    const int nbase = (warp >> 2) * 64;
    const int a_row = rt * 16 + (lane & 7) + ((lane >> 3) & 1) * 8;
    const int a_k   = (lane >> 4) * 8;
    const uint32_t aH = smem_u32(sXh) + (uint32_t)(a_row * XSTR + a_k) * 2;
    const uint32_t aL = smem_u32(sXl) + (uint32_t)(a_row * XSTR + a_k) * 2;
    const int b_n = (lane & 7) + ((lane >> 4) & 1) * 8;
    const int b_k = ((lane >> 3) & 1) * 8;
    const uint32_t bHb = smem_u32(sWh) + (uint32_t)((nbase + b_n) * 40 + b_k) * 2;
    const uint32_t bLb = smem_u32(sWl) + (uint32_t)((nbase + b_n) * 40 + b_k) * 2;

    float acc[8][4];
#pragma unroll
    for (int t = 0; t < 8; t++)
#pragma unroll
        for (int c = 0; c < 4; c++) acc[t][c] = 0.0f;

#pragma unroll
    for (int c = 0; c < NCH; c++) {
        {
            const uint4* srcH = reinterpret_cast<const uint4*>(gWh + c * 5120);
            const uint4* srcL = reinterpret_cast<const uint4*>(gWl + c * 5120);
            uint4* dH = reinterpret_cast<uint4*>(sWh);
            uint4* dL = reinterpret_cast<uint4*>(sWl);
#pragma unroll
            for (int i = tid; i < 640; i += 256) { dH[i] = srcH[i]; dL[i] = srcL[i]; }
        }
        __syncthreads();

#pragma unroll
        for (int ks = 0; ks < 2; ks++) {
            const uint32_t ko = (uint32_t)(c * 32 + ks * 16) * 2;
            const uint32_t kc = (uint32_t)(ks * 16) * 2;
            uint32_t ah0, ah1, ah2, ah3, al0, al1, al2, al3;
            LDSM4(ah0, ah1, ah2, ah3, aH + ko);
            LDSM4(al0, al1, al2, al3, aL + ko);
#pragma unroll
            for (int tp = 0; tp < 4; tp++) {
                const uint32_t off = (uint32_t)(tp * 16 * 40 * 2) + kc;
                uint32_t bh0, bh1, bh2, bh3, bl0, bl1, bl2, bl3;
                LDSM4(bh0, bh1, bh2, bh3, bHb + off);
                LDSM4(bl0, bl1, bl2, bl3, bLb + off);
                MMA_BF16(acc[2 * tp + 0], ah0, ah1, ah2, ah3, bh0, bh1);
                MMA_BF16(acc[2 * tp + 0], ah0, ah1, ah2, ah3, bl0, bl1);
                MMA_BF16(acc[2 * tp + 0], al0, al1, al2, al3, bh0, bh1);
                MMA_BF16(acc[2 * tp + 1], ah0, ah1, ah2, ah3, bh2, bh3);
                MMA_BF16(acc[2 * tp + 1], ah0, ah1, ah2, ah3, bl2, bl3);
                MMA_BF16(acc[2 * tp + 1], al0, al1, al2, al3, bh2, bh3);
            }
        }
        __syncthreads();
    }

    {
        const int g  = lane >> 2;
        const int cx = 2 * (lane & 3);
#pragma unroll
        for (int t = 0; t < 8; t++) {
            const int col = nbase + 8 * t + cx;
            *reinterpret_cast<float2*>(&sOut[rt * 16 + g][col]) =
                make_float2(acc[t][0], acc[t][1]);
            *reinterpret_cast<float2*>(&sOut[rt * 16 + g + 8][col]) =
                make_float2(acc[t][2], acc[t][3]);
        }
    }
    __syncthreads();

    const float4 bv = reinterpret_cast<const float4*>(bias)[lane];
    const float4 gv = reinterpret_cast<const float4*>(gamma)[lane];
    const float4 be = reinterpret_cast<const float4*>(beta)[lane];

    float4 psum = make_float4(0.f, 0.f, 0.f, 0.f);
    int pcnt = 0;
    int pcur = -1;

#pragma unroll
    for (int r = 0; r < 8; r++) {
        int rl = warp * 8 + r;
        int row = row0 + rl;
        float4 v = *reinterpret_cast<float4*>(&sOut[rl][lane * 4]);
        float hx = v.x + bv.x;
        float hy = v.y + bv.y;
        float hz = v.z + bv.z;
        float hw = v.w + bv.w;
        float s = hx + hy + hz + hw;
#pragma unroll
        for (int o = 16; o > 0; o >>= 1) s += __shfl_xor_sync(0xffffffffu, s, o);
        float mu = s * (1.0f / 128.0f);
        float dx = hx - mu, dy = hy - mu, dz = hz - mu, dw = hw - mu;
        float q = dx * dx + dy * dy + dz * dz + dw * dw;
#pragma unroll
        for (int o = 16; o > 0; o >>= 1) q += __shfl_xor_sync(0xffffffffu, q, o);
        float rstd = rsqrtf(q * (1.0f / 128.0f) + LN_EPS);

        float4 o4;
        o4.x = dx * rstd * gv.x + be.x;
        o4.y = dy * rstd * gv.y + be.y;
        o4.z = dz * rstd * gv.z + be.z;
        o4.w = dw * rstd * gv.w + be.w;
        if (RELU) {
            o4.x = fmaxf(o4.x, 0.0f);
            o4.y = fmaxf(o4.y, 0.0f);
            o4.z = fmaxf(o4.z, 0.0f);
            o4.w = fmaxf(o4.w, 0.0f);
        }
        if (row < n) {
            if (POOL) {
                int g = batch[row];
                if (g != pcur) {
                    if (pcnt > 0) {
                        red_add_v4(gsum + pcur * HDIM + lane * 4, psum);
                        if (lane == 0) atomicAdd(&gcnt[pcur], pcnt);
                    }
                    pcur = g;
                    psum = make_float4(0.f, 0.f, 0.f, 0.f);
                    pcnt = 0;
                }
                psum.x += o4.x; psum.y += o4.y; psum.z += o4.z; psum.w += o4.w;
                pcnt++;
            } else if (OUT_BF16) {
                float dvr = rsqrtf((float)(deg[row] + 1));
                __nv_bfloat162 p0 = __floats2bfloat162_rn(o4.x * dvr, o4.y * dvr);
                __nv_bfloat162 p1 = __floats2bfloat162_rn(o4.z * dvr, o4.w * dvr);
                uint2 u = make_uint2(*reinterpret_cast<uint32_t*>(&p0),
                                     *reinterpret_cast<uint32_t*>(&p1));
                reinterpret_cast<uint2*>((ushort_t*)outv + (size_t)row * 128)[lane] = u;
            } else {
                reinterpret_cast<float4*>((float*)outv + (size_t)row * 128)[lane] = o4;
            }
        }
    }
    if (POOL && pcnt > 0) {
        red_add_v4(gsum + pcur * HDIM + lane * 4, psum);
        if (lane == 0) atomicAdd(&gcnt[pcur], pcnt);
    }
}

__global__ void k_finalize(const float* __restrict__ gsum, const int* __restrict__ gcnt,
                           float* __restrict__ out) {
    int i = blockIdx.x * blockDim.x + threadIdx.x;
    if (i >= NGRAPH * HDIM) return;
    float cnt = fmaxf((float)gcnt[i >> 7], 1.0f);
    out[i] = gsum[i] / cnt;
}

// ---------------- launch ----------------
extern "C" void kernel_launch(void* const* d_in, const int* in_sizes, int n_in,
                              void* d_out, int out_size) {
    const float* x     = (const float*)d_in[0];
    const int*   eidx  = (const int*)d_in[1];
    const int*   batch = (const int*)d_in[2];
    const float* W1 = (const float*)d_in[3];
    const float* b1 = (const float*)d_in[4];
    const float* g1 = (const float*)d_in[5];
    const float* be1 = (const float*)d_in[6];
    const float* W2 = (const float*)d_in[7];
    const float* b2 = (const float*)d_in[8];
    const float* g2 = (const float*)d_in[9];
    const float* be2 = (const float*)d_in[10];

    const int n = in_sizes[0] / FDIM;   // 100000
    const int e = in_sizes[1] / 2;      // 1600000
    const int* src = eidx;
    const int* dst = eidx + e;

    int*      ibuf;  cudaGetSymbolAddress((void**)&ibuf,  g_ibuf);
    int*      part;  cudaGetSymbolAddress((void**)&part,  g_partial);
    int*      bsum;  cudaGetSymbolAddress((void**)&bsum,  g_blocksum);
    int*      bpref; cudaGetSymbolAddress((void**)&bpref, g_blockpref);
    int*      csr;   cudaGetSymbolAddress((void**)&csr,   g_csr);
    ushort_t* xbf;   cudaGetSymbolAddress((void**)&xbf,   g_xbf);
    float*    bufa;  cudaGetSymbolAddress((void**)&bufa,  g_bufa);
    float*    bufb;  cudaGetSymbolAddress((void**)&bufb,  g_bufb);
    float*    pool;  cudaGetSymbolAddress((void**)&pool,  g_pool);
    ushort_t *w1h, *w1l, *w2h, *w2l;
    cudaGetSymbolAddress((void**)&w1h, g_w1h);
    cudaGetSymbolAddress((void**)&w1l, g_w1l);
    cudaGetSymbolAddress((void**)&w2h, g_w2h);
    cudaGetSymbolAddress((void**)&w2l, g_w2l);

    int* deg  = ibuf;
    int* cnt2 = ibuf + NPARTIAL;
    float* gsum = pool;
    int*   gcnt = (int*)(pool + NGRAPH * HDIM);

    const int T = 256;
    auto cdiv = [](int a, int b) { return (a + b - 1) / b; };
    const int B   = cdiv(n + 1, SCANW);
    const int nb  = cdiv(e, T);
    const int nx4 = n * FDIM / 4;
    const int gB  = cdiv(n, 64);

    constexpr int SMEM1 = 2 * (64 * (FDIM + 8) * 2) + 2 * (128 * 40 * 2);  // 38912
    constexpr int SMEM2 = 2 * (64 * (HDIM + 8) * 2) + 2 * (128 * 40 * 2);  // 55296
    cudaFuncSetAttribute(k_mma_ln<FDIM, true, true, false>,
                         cudaFuncAttributeMaxDynamicSharedMemorySize, SMEM1);
    cudaFuncSetAttribute(k_mma_ln<HDIM, false, false, true>,
                         cudaFuncAttributeMaxDynamicSharedMemorySize, SMEM2);

    cudaMemsetAsync(ibuf, 0, sizeof(int) * (NPARTIAL + NNODES));
    cudaMemsetAsync(pool, 0, sizeof(float) * (NGRAPH * HDIM) + sizeof(int) * NGRAPH);

    // CSR build + W split (striped); fill also prescales x into bf16 (tail)
    k_count_prep<<<nb + 2 * WPREP_BLKS, T>>>(dst, deg, e, nb, W1, W2,
                                             w1h, w1l, w2h, w2l);                  // 1
    k_scan_block<<<B, SCANW>>>(deg, part, bsum, n);                                // 2
    k_fill<<<nb + cdiv(nx4, T), T>>>(src, dst, deg, part, bsum, B, bpref,
                                     cnt2, csr, e, nb, x, xbf, nx4);               // 3

    // conv1: prescaled bf16 gather then tensor GEMM+LN+ReLU (dinv*h1 bf16 out)
    k_agg64<<<cdiv(n * 32, T), T>>>(xbf, deg, csr, part, bpref, bufa, n);          // 4 <- profiled
    k_mma_ln<FDIM, true, true, false><<<gB, T, SMEM1>>>(bufa, w1h, w1l, b1, g1, be1,
                                                        deg, nullptr, nullptr,
                                                        nullptr, (void*)bufb, n);  // 5

    // conv2: prescaled bf16 gather then tensor GEMM+LN with FUSED mean-pool
    k_agg128<<<cdiv(n * 32, T), T>>>((const ushort_t*)bufb, deg, csr, part, bpref,
                                     bufa, n);                                     // 6
    k_mma_ln<HDIM, false, false, true><<<gB, T, SMEM2>>>(bufa, w2h, w2l, b2, g2, be2,
                                                         deg, batch, gsum, gcnt,
                                                         nullptr, n);              // 7

    k_finalize<<<cdiv(NGRAPH * HDIM, HDIM), HDIM>>>(gsum, gcnt, (float*)d_out);    // 8
}